// round 3
// baseline (speedup 1.0000x reference)
#include <cuda_runtime.h>
#include <math.h>

#define BB 512
#define DD 128
#define NLAT 16
#define NH 4
#define HDIM 32
#define ND 25600
#define NE 153600
#define NPAIR 64
#define LAYERS 4

// scratch (static device globals: allowed)
__device__ float g_lat[BB * NLAT * DD];
__device__ float g_qt[2][BB * NPAIR * DD];
__device__ float g_ctx[2][BB * NPAIR * DD];
__device__ int   g_starts[2][BB + 1];

__device__ __forceinline__ int lb_dev(const int* __restrict__ a, int n, int key) {
    int lo = 0, hi = n;
    while (lo < hi) { int mid = (lo + hi) >> 1; if (a[mid] < key) lo = mid + 1; else hi = mid; }
    return lo;
}

__global__ void offsets_kernel(const int* __restrict__ db, const int* __restrict__ eb) {
    int i = blockIdx.x * blockDim.x + threadIdx.x;
    if (i <= BB) { g_starts[0][i] = lb_dev(db, ND, i); g_starts[1][i] = lb_dev(eb, NE, i); }
}

__global__ void init_lat_kernel(const float* __restrict__ latents) {
    int i = blockIdx.x * blockDim.x + threadIdx.x;
    if (i < BB * NLAT * DD) g_lat[i] = latents[i & (NLAT * DD - 1)];
}

// LayerNorm 16 rows of 128 (src global/smem) -> dst smem
__device__ __forceinline__ void layernorm_rows(const float* __restrict__ src,
                                               const float* __restrict__ g,
                                               const float* __restrict__ bta,
                                               float (*dst)[DD], int t, int nthr) {
    int warp = t >> 5, lane = t & 31, nw = nthr >> 5;
    for (int r = warp; r < NLAT; r += nw) {
        float4 v = ((const float4*)(src + r * DD))[lane];
        float s = v.x + v.y + v.z + v.w;
        #pragma unroll
        for (int o = 16; o; o >>= 1) s += __shfl_xor_sync(0xffffffffu, s, o);
        float mean = s * (1.0f / DD);
        float dx = v.x - mean, dy = v.y - mean, dz = v.z - mean, dw = v.w - mean;
        float q = dx * dx + dy * dy + dz * dz + dw * dw;
        #pragma unroll
        for (int o = 16; o; o >>= 1) q += __shfl_xor_sync(0xffffffffu, q, o);
        float rstd = rsqrtf(q * (1.0f / DD) + 1e-5f);
        int c = lane * 4;
        dst[r][c + 0] = dx * rstd * g[c + 0] + bta[c + 0];
        dst[r][c + 1] = dy * rstd * g[c + 1] + bta[c + 1];
        dst[r][c + 2] = dz * rstd * g[c + 2] + bta[c + 2];
        dst[r][c + 3] = dw * rstd * g[c + 3] + bta[c + 3];
    }
}

// dst[i][t] = sum_j src[i][j]*W[t*DD+j] + bias[t] ; safe if dst aliases src
__device__ __forceinline__ void proj128(const float (*src)[DD], float (*dst)[DD],
                                        const float* __restrict__ W,
                                        const float* __restrict__ bias, int t) {
    float acc[NLAT];
    float bv = bias[t];
    #pragma unroll
    for (int i = 0; i < NLAT; i++) acc[i] = bv;
    const float4* w4p = (const float4*)(W + t * DD);
    #pragma unroll 4
    for (int j4 = 0; j4 < DD / 4; j4++) {
        float4 w4 = w4p[j4];
        #pragma unroll
        for (int i = 0; i < NLAT; i++) {
            float4 n4 = *(const float4*)(&src[i][j4 * 4]);
            acc[i] = fmaf(n4.x, w4.x, fmaf(n4.y, w4.y, fmaf(n4.z, w4.z, fmaf(n4.w, w4.w, acc[i]))));
        }
    }
    __syncthreads();
    #pragma unroll
    for (int i = 0; i < NLAT; i++) dst[i][t] = acc[i];
}

// qt[b][q*NH+h][t] = scale * sum_j qh[q][h*32+j] * W[(DD+h*32+j)*DD + t]
__device__ __forceinline__ void qt_proj(const float (*qh)[DD], const float* __restrict__ W,
                                        float* __restrict__ qtg, int t) {
    const float scale = 0.17677669529663688f; // 1/sqrt(32)
    #pragma unroll
    for (int h = 0; h < NH; h++) {
        float acc[NLAT];
        #pragma unroll
        for (int i = 0; i < NLAT; i++) acc[i] = 0.0f;
        for (int j = 0; j < HDIM; j++) {
            float wv = W[(DD + h * HDIM + j) * DD + t];
            float qv[NLAT];
            #pragma unroll
            for (int i = 0; i < NLAT; i++) acc[i] = fmaf(qh[i][h * HDIM + j], wv, acc[i]);
            (void)qv;
        }
        #pragma unroll
        for (int i = 0; i < NLAT; i++) qtg[(i * NH + h) * DD + t] = acc[i] * scale;
    }
}

// LN1 + latent q-proj + mha q-proj + wk fold, both modalities. 512 blocks x 128 thr
__global__ void __launch_bounds__(128) prep_q_kernel(
    const float* __restrict__ lng, const float* __restrict__ lnb,
    const float* __restrict__ wqd, const float* __restrict__ bqd,
    const float* __restrict__ mwd, const float* __restrict__ mbd,
    const float* __restrict__ wqe, const float* __restrict__ bqe,
    const float* __restrict__ mwe, const float* __restrict__ mbe) {
    __shared__ float nl[NLAT][DD];
    __shared__ float qb[NLAT][DD];
    __shared__ float qh[NLAT][DD];
    int b = blockIdx.x, t = threadIdx.x;
    layernorm_rows(g_lat + (size_t)b * NLAT * DD, lng, lnb, nl, t, 128);
    __syncthreads();

    proj128(nl, qb, wqd, bqd, t); __syncthreads();
    proj128(qb, qh, mwd, mbd, t); __syncthreads();
    qt_proj(qh, mwd, g_qt[0] + (size_t)b * NPAIR * DD, t);
    __syncthreads();

    proj128(nl, qb, wqe, bqe, t); __syncthreads();
    proj128(qb, qh, mwe, mbe, t); __syncthreads();
    qt_proj(qh, mwe, g_qt[1] + (size_t)b * NPAIR * DD, t);
}

// ragged flash attention, fp32, chunk=32 tokens. 512 blocks x 256 thr, dyn smem
#define ATT_SMEM_FLOATS (64 * 132 + 32 * 128 + 32 * 128 + 32 * 64 + 192)
#define ATT_SMEM_BYTES (ATT_SMEM_FLOATS * 4)

__global__ void __launch_bounds__(256, 2) attn_kernel(int mod,
    const float* __restrict__ Kg, const float* __restrict__ Vg) {
    extern __shared__ float sm[];
    float* qts = sm;                 // 64 pairs x 33 float4 (padded)
    float* ks  = qts + 64 * 132;     // 32 x 128
    float* vs  = ks + 32 * 128;      // 32 x 128
    float* ss  = vs + 32 * 128;      // ss[k][p] 32 x 64
    float* m_s = ss + 32 * 64;
    float* l_s = m_s + 64;
    float* sc_s = l_s + 64;

    int b = blockIdx.x, t = threadIdx.x;
    int s0 = g_starts[mod][b];
    int cnt = g_starts[mod][b + 1] - s0;

    const float4* qtg = (const float4*)(g_qt[mod] + (size_t)b * NPAIR * DD);
    float4* qts4 = (float4*)qts;
    float4* ks4 = (float4*)ks;
    float4* vs4 = (float4*)vs;

    for (int i = t; i < NPAIR * 32; i += 256) {
        int r = i >> 5, c = i & 31;
        qts4[r * 33 + c] = qtg[i];
    }
    if (t < NPAIR) { m_s[t] = -1e30f; l_s[t] = 0.0f; }

    int g = t & 7, pp = t >> 3;   // ctx phase
    int p2 = t & 31, kt = t >> 5; // score phase

    float4 cA[4], cB[4];
    #pragma unroll
    for (int j = 0; j < 4; j++) { cA[j] = make_float4(0,0,0,0); cB[j] = make_float4(0,0,0,0); }

    for (int base = 0; base < cnt; base += 32) {
        int nk = min(32, cnt - base);
        __syncthreads();
        {
            const float4* Kr = (const float4*)(Kg + (size_t)(s0 + base) * DD);
            const float4* Vr = (const float4*)(Vg + (size_t)(s0 + base) * DD);
            float4 z = make_float4(0, 0, 0, 0);
            for (int i = t; i < 32 * 32; i += 256) {
                int r = i >> 5;
                ks4[i] = (r < nk) ? Kr[i] : z;
                vs4[i] = (r < nk) ? Vr[i] : z;
            }
        }
        __syncthreads();
        // scores: pairs {p2, p2+32}, tokens kt*4..kt*4+3
        {
            float sA0=0,sA1=0,sA2=0,sA3=0,sB0=0,sB1=0,sB2=0,sB3=0;
            const float4* qa = qts4 + p2 * 33;
            const float4* qbp = qts4 + (p2 + 32) * 33;
            const float4* kb = ks4 + (kt * 4) * 32;
            #pragma unroll 4
            for (int d4 = 0; d4 < 32; d4++) {
                float4 A = qa[d4], Bq = qbp[d4];
                float4 K0 = kb[d4], K1 = kb[32 + d4], K2 = kb[64 + d4], K3 = kb[96 + d4];
                sA0 += A.x*K0.x + A.y*K0.y + A.z*K0.z + A.w*K0.w;
                sA1 += A.x*K1.x + A.y*K1.y + A.z*K1.z + A.w*K1.w;
                sA2 += A.x*K2.x + A.y*K2.y + A.z*K2.z + A.w*K2.w;
                sA3 += A.x*K3.x + A.y*K3.y + A.z*K3.z + A.w*K3.w;
                sB0 += Bq.x*K0.x + Bq.y*K0.y + Bq.z*K0.z + Bq.w*K0.w;
                sB1 += Bq.x*K1.x + Bq.y*K1.y + Bq.z*K1.z + Bq.w*K1.w;
                sB2 += Bq.x*K2.x + Bq.y*K2.y + Bq.z*K2.z + Bq.w*K2.w;
                sB3 += Bq.x*K3.x + Bq.y*K3.y + Bq.z*K3.z + Bq.w*K3.w;
            }
            int k0 = kt * 4;
            ss[(k0+0)*64 + p2] = (k0+0 < nk) ? sA0 : -1e30f;
            ss[(k0+1)*64 + p2] = (k0+1 < nk) ? sA1 : -1e30f;
            ss[(k0+2)*64 + p2] = (k0+2 < nk) ? sA2 : -1e30f;
            ss[(k0+3)*64 + p2] = (k0+3 < nk) ? sA3 : -1e30f;
            ss[(k0+0)*64 + p2+32] = (k0+0 < nk) ? sB0 : -1e30f;
            ss[(k0+1)*64 + p2+32] = (k0+1 < nk) ? sB1 : -1e30f;
            ss[(k0+2)*64 + p2+32] = (k0+2 < nk) ? sB2 : -1e30f;
            ss[(k0+3)*64 + p2+32] = (k0+3 < nk) ? sB3 : -1e30f;
        }
        __syncthreads();
        if (t < NPAIR) {
            float mo = m_s[t];
            float cm = mo;
            #pragma unroll 4
            for (int k = 0; k < 32; k++) cm = fmaxf(cm, ss[k * 64 + t]);
            float scl = __expf(mo - cm);
            float l = l_s[t] * scl;
            float ssum = 0.0f;
            #pragma unroll 4
            for (int k = 0; k < 32; k++) {
                float e = __expf(ss[k * 64 + t] - cm);
                ss[k * 64 + t] = e;
                ssum += e;
            }
            l_s[t] = l + ssum; m_s[t] = cm; sc_s[t] = scl;
        }
        __syncthreads();
        {
            float sc0 = sc_s[pp], sc1 = sc_s[pp + 32];
            #pragma unroll
            for (int j = 0; j < 4; j++) {
                cA[j].x*=sc0; cA[j].y*=sc0; cA[j].z*=sc0; cA[j].w*=sc0;
                cB[j].x*=sc1; cB[j].y*=sc1; cB[j].z*=sc1; cB[j].w*=sc1;
            }
            #pragma unroll 2
            for (int k = 0; k < 32; k++) {
                float e0 = ss[k * 64 + pp];
                float e1 = ss[k * 64 + pp + 32];
                const float4* vr = vs4 + k * 32;
                #pragma unroll
                for (int j = 0; j < 4; j++) {
                    float4 v = vr[g + 8 * j];
                    cA[j].x += e0*v.x; cA[j].y += e0*v.y; cA[j].z += e0*v.z; cA[j].w += e0*v.w;
                    cB[j].x += e1*v.x; cB[j].y += e1*v.y; cB[j].z += e1*v.z; cB[j].w += e1*v.w;
                }
            }
        }
    }
    __syncthreads();
    float l0 = l_s[pp], l1 = l_s[pp + 32];
    float i0 = (l0 > 0.0f) ? 1.0f / l0 : 0.0f;
    float i1 = (l1 > 0.0f) ? 1.0f / l1 : 0.0f;
    float4* cb = (float4*)(g_ctx[mod] + (size_t)b * NPAIR * DD);
    #pragma unroll
    for (int j = 0; j < 4; j++) {
        cb[pp * 32 + g + 8 * j] = make_float4(cA[j].x*i0, cA[j].y*i0, cA[j].z*i0, cA[j].w*i0);
        cb[(pp + 32) * 32 + g + 8 * j] = make_float4(cB[j].x*i1, cB[j].y*i1, cB[j].z*i1, cB[j].w*i1);
    }
}

// lat += (ctx@wv^T+bv)@ow^T + ob for both modalities. 512 blocks x 128 thr
__global__ void __launch_bounds__(128) proj_add_kernel(
    const float* __restrict__ mwd, const float* __restrict__ mbd,
    const float* __restrict__ owd, const float* __restrict__ obd,
    const float* __restrict__ mwe, const float* __restrict__ mbe,
    const float* __restrict__ owe, const float* __restrict__ obe) {
    __shared__ float t1[NLAT][DD];
    int b = blockIdx.x, t = threadIdx.x;
    float acc2[NLAT];
    float ob2 = obd[t] + obe[t];
    #pragma unroll
    for (int i = 0; i < NLAT; i++) acc2[i] = ob2;

    for (int mod = 0; mod < 2; mod++) {
        const float* mw = mod ? mwe : mwd;
        const float* mb = mod ? mbe : mbd;
        const float* ow = mod ? owe : owd;
        const float* ctxb = g_ctx[mod] + (size_t)b * NPAIR * DD;
        int h = t >> 5;
        float a1[NLAT];
        float bv = mb[2 * DD + t];
        #pragma unroll
        for (int i = 0; i < NLAT; i++) a1[i] = bv;
        const float4* wvp = (const float4*)(mw + (size_t)(2 * DD + t) * DD);
        #pragma unroll 2
        for (int d4 = 0; d4 < DD / 4; d4++) {
            float4 w4 = wvp[d4];
            #pragma unroll
            for (int i = 0; i < NLAT; i++) {
                float4 c4 = *(const float4*)(ctxb + ((i * NH + h) * DD + d4 * 4));
                a1[i] = fmaf(c4.x, w4.x, fmaf(c4.y, w4.y, fmaf(c4.z, w4.z, fmaf(c4.w, w4.w, a1[i]))));
            }
        }
        __syncthreads();
        #pragma unroll
        for (int i = 0; i < NLAT; i++) t1[i][t] = a1[i];
        __syncthreads();
        const float4* owp = (const float4*)(ow + (size_t)t * DD);
        #pragma unroll 2
        for (int u4 = 0; u4 < DD / 4; u4++) {
            float4 w4 = owp[u4];
            #pragma unroll
            for (int i = 0; i < NLAT; i++) {
                float4 h4 = *(const float4*)(&t1[i][u4 * 4]);
                acc2[i] = fmaf(h4.x, w4.x, fmaf(h4.y, w4.y, fmaf(h4.z, w4.z, fmaf(h4.w, w4.w, acc2[i]))));
            }
        }
        __syncthreads();
    }
    float* latb = g_lat + (size_t)b * NLAT * DD;
    #pragma unroll
    for (int i = 0; i < NLAT; i++) latb[i * DD + t] += acc2[i];
}

// lat += relu(LN2(lat)@w1^T+b1)@w2^T + b2. 512 blocks x 256 thr
__global__ void __launch_bounds__(256) ffn_kernel(
    const float* __restrict__ lng, const float* __restrict__ lnb,
    const float* __restrict__ w1, const float* __restrict__ b1,
    const float* __restrict__ w2, const float* __restrict__ b2) {
    __shared__ float nl[NLAT][DD];
    __shared__ float hid[NLAT][2 * DD];
    int b = blockIdx.x, t = threadIdx.x;
    float* latb = g_lat + (size_t)b * NLAT * DD;
    layernorm_rows(latb, lng, lnb, nl, t, 256);
    __syncthreads();
    {
        float acc[NLAT];
        float bv = b1[t];
        #pragma unroll
        for (int i = 0; i < NLAT; i++) acc[i] = bv;
        const float4* wp = (const float4*)(w1 + (size_t)t * DD);
        #pragma unroll 2
        for (int d4 = 0; d4 < DD / 4; d4++) {
            float4 w4 = wp[d4];
            #pragma unroll
            for (int i = 0; i < NLAT; i++) {
                float4 n4 = *(const float4*)(&nl[i][d4 * 4]);
                acc[i] = fmaf(n4.x, w4.x, fmaf(n4.y, w4.y, fmaf(n4.z, w4.z, fmaf(n4.w, w4.w, acc[i]))));
            }
        }
        #pragma unroll
        for (int i = 0; i < NLAT; i++) hid[i][t] = fmaxf(acc[i], 0.0f);
    }
    __syncthreads();
    if (t < DD) {
        float acc[NLAT];
        float bv = b2[t];
        #pragma unroll
        for (int i = 0; i < NLAT; i++) acc[i] = bv;
        const float4* wp = (const float4*)(w2 + (size_t)t * 2 * DD);
        #pragma unroll 2
        for (int u4 = 0; u4 < 2 * DD / 4; u4++) {
            float4 w4 = wp[u4];
            #pragma unroll
            for (int i = 0; i < NLAT; i++) {
                float4 h4 = *(const float4*)(&hid[i][u4 * 4]);
                acc[i] = fmaf(h4.x, w4.x, fmaf(h4.y, w4.y, fmaf(h4.z, w4.z, fmaf(h4.w, w4.w, acc[i]))));
            }
        }
        #pragma unroll
        for (int i = 0; i < NLAT; i++) latb[i * DD + t] += acc[i];
    }
}

// out[b] = softplus(relu(flat@w1^T+b1)@w2^T+b2). 512 blocks x 128 thr
__global__ void __launch_bounds__(128) head_kernel(
    const float* __restrict__ w1, const float* __restrict__ b1,
    const float* __restrict__ w2, const float* __restrict__ b2,
    float* __restrict__ out) {
    __shared__ float part[4];
    int b = blockIdx.x, t = threadIdx.x;
    const float4* flat = (const float4*)(g_lat + (size_t)b * NLAT * DD);
    const float4* wp = (const float4*)(w1 + (size_t)t * NLAT * DD);
    float acc = b1[t];
    #pragma unroll 4
    for (int u4 = 0; u4 < NLAT * DD / 4; u4++) {
        float4 f4 = flat[u4];
        float4 w4 = wp[u4];
        acc = fmaf(f4.x, w4.x, fmaf(f4.y, w4.y, fmaf(f4.z, w4.z, fmaf(f4.w, w4.w, acc))));
    }
    float v = fmaxf(acc, 0.0f) * w2[t];
    #pragma unroll
    for (int o = 16; o; o >>= 1) v += __shfl_xor_sync(0xffffffffu, v, o);
    if ((t & 31) == 0) part[t >> 5] = v;
    __syncthreads();
    if (t == 0) {
        float x = part[0] + part[1] + part[2] + part[3] + b2[0];
        out[b] = (x > 20.0f) ? x : log1pf(__expf(x));
    }
}

extern "C" void kernel_launch(void* const* d_in, const int* in_sizes, int n_in,
                              void* d_out, int out_size) {
    const float* drug_k   = (const float*)d_in[0];
    const float* drug_v   = (const float*)d_in[1];
    const float* enz_k    = (const float*)d_in[2];
    const float* enz_v    = (const float*)d_in[3];
    const int*   drug_b   = (const int*)d_in[4];
    const int*   enz_b    = (const int*)d_in[5];
    const float* latents  = (const float*)d_in[6];
    const float* wq_d     = (const float*)d_in[7];
    const float* bq_d     = (const float*)d_in[8];
    const float* wq_e     = (const float*)d_in[9];
    const float* bq_e     = (const float*)d_in[10];
    const float* mha_d_w  = (const float*)d_in[11];
    const float* mha_d_b  = (const float*)d_in[12];
    const float* mha_d_ow = (const float*)d_in[13];
    const float* mha_d_ob = (const float*)d_in[14];
    const float* mha_e_w  = (const float*)d_in[15];
    const float* mha_e_b  = (const float*)d_in[16];
    const float* mha_e_ow = (const float*)d_in[17];
    const float* mha_e_ob = (const float*)d_in[18];
    const float* ln1_g    = (const float*)d_in[19];
    const float* ln1_b    = (const float*)d_in[20];
    const float* ln2_g    = (const float*)d_in[21];
    const float* ln2_b    = (const float*)d_in[22];
    const float* ffn_w1   = (const float*)d_in[23];
    const float* ffn_b1   = (const float*)d_in[24];
    const float* ffn_w2   = (const float*)d_in[25];
    const float* ffn_b2   = (const float*)d_in[26];
    const float* head_w1  = (const float*)d_in[27];
    const float* head_b1  = (const float*)d_in[28];
    const float* head_w2  = (const float*)d_in[29];
    const float* head_b2  = (const float*)d_in[30];
    float* out = (float*)d_out;

    cudaFuncSetAttribute(attn_kernel, cudaFuncAttributeMaxDynamicSharedMemorySize, ATT_SMEM_BYTES);

    offsets_kernel<<<3, 256>>>(drug_b, enz_b);
    init_lat_kernel<<<(BB * NLAT * DD + 255) / 256, 256>>>(latents);

    for (int l = 0; l < LAYERS; l++) {
        size_t oD = (size_t)l * DD * DD;     // [D,D] weights
        size_t o3D = (size_t)l * 3 * DD * DD;
        size_t o3b = (size_t)l * 3 * DD;
        size_t oV = (size_t)l * DD;          // [D] vectors
        size_t oF1 = (size_t)l * 2 * DD * DD;
        size_t oF1b = (size_t)l * 2 * DD;

        prep_q_kernel<<<BB, 128>>>(
            ln1_g + oV, ln1_b + oV,
            wq_d + oD, bq_d + oV, mha_d_w + o3D, mha_d_b + o3b,
            wq_e + oD, bq_e + oV, mha_e_w + o3D, mha_e_b + o3b);

        attn_kernel<<<BB, 256, ATT_SMEM_BYTES>>>(0, drug_k, drug_v);
        attn_kernel<<<BB, 256, ATT_SMEM_BYTES>>>(1, enz_k, enz_v);

        proj_add_kernel<<<BB, 128>>>(
            mha_d_w + o3D, mha_d_b + o3b, mha_d_ow + oD, mha_d_ob + oV,
            mha_e_w + o3D, mha_e_b + o3b, mha_e_ow + oD, mha_e_ob + oV);

        ffn_kernel<<<BB, 256>>>(
            ln2_g + oV, ln2_b + oV,
            ffn_w1 + oF1, ffn_b1 + oF1b, ffn_w2 + oF1, ffn_b2 + oV);
    }

    head_kernel<<<BB, 128>>>(head_w1, head_b1, head_w2, head_b2, out);
}

// round 6
// speedup vs baseline: 1.4442x; 1.4442x over previous
#include <cuda_runtime.h>
#include <cuda_bf16.h>
#include <stdint.h>
#include <math.h>

#define BB 512
#define DD 128
#define NLAT 16
#define NH 4
#define HDIM 32
#define ND 25600
#define NE 153600
#define NPAIR 64
#define LAYERS 4

// scratch (static device globals: allowed)
__device__ float g_lat[BB * NLAT * DD];
__device__ float g_qt[2][BB * NPAIR * DD];
__device__ float g_ctx[2][BB * NPAIR * DD];
__device__ int   g_starts[2][BB + 1];

__device__ __forceinline__ int lb_dev(const int* __restrict__ a, int n, int key) {
    int lo = 0, hi = n;
    while (lo < hi) { int mid = (lo + hi) >> 1; if (a[mid] < key) lo = mid + 1; else hi = mid; }
    return lo;
}

__global__ void offsets_kernel(const int* __restrict__ db, const int* __restrict__ eb) {
    int i = blockIdx.x * blockDim.x + threadIdx.x;
    if (i <= BB) { g_starts[0][i] = lb_dev(db, ND, i); g_starts[1][i] = lb_dev(eb, NE, i); }
}

__global__ void init_lat_kernel(const float* __restrict__ latents) {
    int i = blockIdx.x * blockDim.x + threadIdx.x;
    if (i < BB * NLAT * DD) g_lat[i] = latents[i & (NLAT * DD - 1)];
}

// ---------------- shared small-GEMM helpers (fp32) ----------------
__device__ __forceinline__ void layernorm_rows(const float* __restrict__ src,
                                               const float* __restrict__ g,
                                               const float* __restrict__ bta,
                                               float (*dst)[DD], int t, int nthr) {
    int warp = t >> 5, lane = t & 31, nw = nthr >> 5;
    for (int r = warp; r < NLAT; r += nw) {
        float4 v = ((const float4*)(src + r * DD))[lane];
        float s = v.x + v.y + v.z + v.w;
        #pragma unroll
        for (int o = 16; o; o >>= 1) s += __shfl_xor_sync(0xffffffffu, s, o);
        float mean = s * (1.0f / DD);
        float dx = v.x - mean, dy = v.y - mean, dz = v.z - mean, dw = v.w - mean;
        float q = dx * dx + dy * dy + dz * dz + dw * dw;
        #pragma unroll
        for (int o = 16; o; o >>= 1) q += __shfl_xor_sync(0xffffffffu, q, o);
        float rstd = rsqrtf(q * (1.0f / DD) + 1e-5f);
        int c = lane * 4;
        dst[r][c + 0] = dx * rstd * g[c + 0] + bta[c + 0];
        dst[r][c + 1] = dy * rstd * g[c + 1] + bta[c + 1];
        dst[r][c + 2] = dz * rstd * g[c + 2] + bta[c + 2];
        dst[r][c + 3] = dw * rstd * g[c + 3] + bta[c + 3];
    }
}

__device__ __forceinline__ void proj128(const float (*src)[DD], float (*dst)[DD],
                                        const float* __restrict__ W,
                                        const float* __restrict__ bias, int t) {
    float acc[NLAT];
    float bv = bias[t];
    #pragma unroll
    for (int i = 0; i < NLAT; i++) acc[i] = bv;
    const float4* w4p = (const float4*)(W + t * DD);
    #pragma unroll 4
    for (int j4 = 0; j4 < DD / 4; j4++) {
        float4 w4 = w4p[j4];
        #pragma unroll
        for (int i = 0; i < NLAT; i++) {
            float4 n4 = *(const float4*)(&src[i][j4 * 4]);
            acc[i] = fmaf(n4.x, w4.x, fmaf(n4.y, w4.y, fmaf(n4.z, w4.z, fmaf(n4.w, w4.w, acc[i]))));
        }
    }
    __syncthreads();
    #pragma unroll
    for (int i = 0; i < NLAT; i++) dst[i][t] = acc[i];
}

__device__ __forceinline__ void qt_proj(const float (*qh)[DD], const float* __restrict__ W,
                                        float* __restrict__ qtg, int t) {
    const float scale = 0.17677669529663688f; // 1/sqrt(32)
    #pragma unroll
    for (int h = 0; h < NH; h++) {
        float acc[NLAT];
        #pragma unroll
        for (int i = 0; i < NLAT; i++) acc[i] = 0.0f;
        for (int j = 0; j < HDIM; j++) {
            float wv = W[(DD + h * HDIM + j) * DD + t];
            #pragma unroll
            for (int i = 0; i < NLAT; i++) acc[i] = fmaf(qh[i][h * HDIM + j], wv, acc[i]);
        }
        #pragma unroll
        for (int i = 0; i < NLAT; i++) qtg[(i * NH + h) * DD + t] = acc[i] * scale;
    }
}

__global__ void __launch_bounds__(128) prep_q_kernel(
    const float* __restrict__ lng, const float* __restrict__ lnb,
    const float* __restrict__ wqd, const float* __restrict__ bqd,
    const float* __restrict__ mwd, const float* __restrict__ mbd,
    const float* __restrict__ wqe, const float* __restrict__ bqe,
    const float* __restrict__ mwe, const float* __restrict__ mbe) {
    __shared__ float nl[NLAT][DD];
    __shared__ float qb[NLAT][DD];
    __shared__ float qh[NLAT][DD];
    int b = blockIdx.x, t = threadIdx.x;
    layernorm_rows(g_lat + (size_t)b * NLAT * DD, lng, lnb, nl, t, 128);
    __syncthreads();

    proj128(nl, qb, wqd, bqd, t); __syncthreads();
    proj128(qb, qh, mwd, mbd, t); __syncthreads();
    qt_proj(qh, mwd, g_qt[0] + (size_t)b * NPAIR * DD, t);
    __syncthreads();

    proj128(nl, qb, wqe, bqe, t); __syncthreads();
    proj128(qb, qh, mwe, mbe, t); __syncthreads();
    qt_proj(qh, mwe, g_qt[1] + (size_t)b * NPAIR * DD, t);
}

// ---------------- tensor-core attention ----------------
__device__ __forceinline__ uint32_t s2u(const void* p) {
    return (uint32_t)__cvta_generic_to_shared(p);
}
__device__ __forceinline__ uint32_t f2bf2(float x, float y) {
    __nv_bfloat162 h = __floats2bfloat162_rn(x, y);
    return *reinterpret_cast<uint32_t*>(&h);
}

#define LDSM4(R, addr) asm volatile( \
    "ldmatrix.sync.aligned.m8n8.x4.shared.b16 {%0,%1,%2,%3},[%4];" \
    : "=r"((R)[0]), "=r"((R)[1]), "=r"((R)[2]), "=r"((R)[3]) : "r"(addr))
#define LDSM4T(R, addr) asm volatile( \
    "ldmatrix.sync.aligned.m8n8.x4.trans.shared.b16 {%0,%1,%2,%3},[%4];" \
    : "=r"((R)[0]), "=r"((R)[1]), "=r"((R)[2]), "=r"((R)[3]) : "r"(addr))
#define MMA16816(D, A, B0, B1) asm volatile( \
    "mma.sync.aligned.m16n8k16.row.col.f32.bf16.bf16.f32 " \
    "{%0,%1,%2,%3},{%4,%5,%6,%7},{%8,%9},{%0,%1,%2,%3};" \
    : "+f"((D)[0]), "+f"((D)[1]), "+f"((D)[2]), "+f"((D)[3]) \
    : "r"((A)[0]), "r"((A)[1]), "r"((A)[2]), "r"((A)[3]), "r"(B0), "r"(B1))

// 512 blocks x 256 threads. Qt A-frags live in registers all kernel.
__global__ void __launch_bounds__(256) attn_kernel(int mod,
    const float* __restrict__ Kg, const float* __restrict__ Vg) {
    __shared__ __nv_bfloat16 Ks[32][136];
    __shared__ __nv_bfloat16 Vs[32][136];
    __shared__ float ss[64][34];
    __shared__ __nv_bfloat16 Ps[64][40];
    __shared__ float m_s[64], l_s[64], sc_s[64];

    int b = blockIdx.x, t = threadIdx.x;
    int w = t >> 5, lane = t & 31;
    int g = lane >> 2, tc = lane & 3;
    int s0 = g_starts[mod][b];
    int cnt = g_starts[mod][b + 1] - s0;

    int pb = (w & 3) * 16;        // pair-row base for this warp
    int th = w >> 2;              // token half (scores) / dim half (ctx)
    int tbase = th * 16;
    int dimbase = th * 64;

    // Load Qt A-fragments (bf16) directly from global fp32; persistent in regs.
    uint32_t qa[8][4];
    {
        const float* qtb = g_qt[mod] + (size_t)b * NPAIR * DD;
        int r0 = pb + g, r1 = pb + g + 8;
        #pragma unroll
        for (int ks = 0; ks < 8; ks++) {
            int c0 = ks * 16 + tc * 2;
            float2 v00 = *(const float2*)(qtb + r0 * DD + c0);
            float2 v10 = *(const float2*)(qtb + r1 * DD + c0);
            float2 v01 = *(const float2*)(qtb + r0 * DD + c0 + 8);
            float2 v11 = *(const float2*)(qtb + r1 * DD + c0 + 8);
            qa[ks][0] = f2bf2(v00.x, v00.y);
            qa[ks][1] = f2bf2(v10.x, v10.y);
            qa[ks][2] = f2bf2(v01.x, v01.y);
            qa[ks][3] = f2bf2(v11.x, v11.y);
        }
    }
    if (t < 64) { m_s[t] = -1e30f; l_s[t] = 0.0f; }

    float cx[8][4];
    #pragma unroll
    for (int i = 0; i < 8; i++)
        #pragma unroll
        for (int j = 0; j < 4; j++) cx[i][j] = 0.0f;

    // ldmatrix base addresses (byte offsets added per kstep/tile)
    uint32_t addrK = s2u(&Ks[tbase + ((lane >> 4) << 3) + (lane & 7)][((lane >> 3) & 1) * 8]);
    uint32_t addrP = s2u(&Ps[pb + (lane & 15)][(lane >> 4) * 8]);
    uint32_t addrV = s2u(&Vs[(lane & 15)][dimbase + (lane >> 4) * 8]);

    for (int base = 0; base < cnt; base += 32) {
        int nk = min(32, cnt - base);
        __syncthreads();
        // Load K/V chunk -> bf16 smem (zero-fill padded rows)
        {
            const float4* Kr = (const float4*)(Kg + (size_t)(s0 + base) * DD);
            const float4* Vr = (const float4*)(Vg + (size_t)(s0 + base) * DD);
            #pragma unroll
            for (int i = t; i < 1024; i += 256) {
                int r = i >> 5, c = (i & 31) * 4;
                float4 kv = make_float4(0, 0, 0, 0), vv = make_float4(0, 0, 0, 0);
                if (r < nk) { kv = Kr[i]; vv = Vr[i]; }
                *(uint2*)&Ks[r][c] = make_uint2(f2bf2(kv.x, kv.y), f2bf2(kv.z, kv.w));
                *(uint2*)&Vs[r][c] = make_uint2(f2bf2(vv.x, vv.y), f2bf2(vv.z, vv.w));
            }
        }
        __syncthreads();
        // Scores: S[pb:pb+16][tbase:tbase+16] via 8 ksteps x 2 n-tiles
        {
            float s0a[4] = {0, 0, 0, 0}, s1a[4] = {0, 0, 0, 0};
            #pragma unroll
            for (int ks = 0; ks < 8; ks++) {
                uint32_t kb[4];
                LDSM4(kb, addrK + ks * 32);
                MMA16816(s0a, qa[ks], kb[0], kb[1]);
                MMA16816(s1a, qa[ks], kb[2], kb[3]);
            }
            int r0 = pb + g, r1 = pb + g + 8;
            int c0 = tbase + tc * 2, c1 = tbase + 8 + tc * 2;
            *(float2*)&ss[r0][c0] = make_float2(s0a[0], s0a[1]);
            *(float2*)&ss[r1][c0] = make_float2(s0a[2], s0a[3]);
            *(float2*)&ss[r0][c1] = make_float2(s1a[0], s1a[1]);
            *(float2*)&ss[r1][c1] = make_float2(s1a[2], s1a[3]);
        }
        __syncthreads();
        // Online softmax per pair (64 threads)
        if (t < 64) {
            float mo = m_s[t], cm = mo;
            for (int k = 0; k < nk; k++) cm = fmaxf(cm, ss[t][k]);
            float scl = __expf(mo - cm);
            float l = l_s[t] * scl;
            float sum = 0.0f;
            #pragma unroll 4
            for (int k = 0; k < 32; k++) {
                float e = (k < nk) ? __expf(ss[t][k] - cm) : 0.0f;
                Ps[t][k] = __float2bfloat16(e);
                sum += e;
            }
            l_s[t] = l + sum; m_s[t] = cm; sc_s[t] = scl;
        }
        __syncthreads();
        // Ctx accumulate: rescale then += P @ V
        {
            float sc0 = sc_s[pb + g], sc1 = sc_s[pb + g + 8];
            #pragma unroll
            for (int nt = 0; nt < 8; nt++) {
                cx[nt][0] *= sc0; cx[nt][1] *= sc0;
                cx[nt][2] *= sc1; cx[nt][3] *= sc1;
            }
            #pragma unroll
            for (int ks = 0; ks < 2; ks++) {
                uint32_t pa[4];
                LDSM4(pa, addrP + ks * 32);
                #pragma unroll
                for (int ntp = 0; ntp < 4; ntp++) {
                    uint32_t vb[4];
                    LDSM4T(vb, addrV + ks * 4352 + ntp * 32);
                    MMA16816(cx[ntp * 2 + 0], pa, vb[0], vb[1]);
                    MMA16816(cx[ntp * 2 + 1], pa, vb[2], vb[3]);
                }
            }
        }
    }
    // normalize + store ctx
    int r0 = pb + g, r1 = pb + g + 8;
    float l0 = l_s[r0], l1 = l_s[r1];
    float i0 = (l0 > 0.0f) ? 1.0f / l0 : 0.0f;
    float i1 = (l1 > 0.0f) ? 1.0f / l1 : 0.0f;
    float* cbp = g_ctx[mod] + (size_t)b * NPAIR * DD;
    #pragma unroll
    for (int nt = 0; nt < 8; nt++) {
        int d0 = dimbase + nt * 8 + tc * 2;
        *(float2*)(cbp + r0 * DD + d0) = make_float2(cx[nt][0] * i0, cx[nt][1] * i0);
        *(float2*)(cbp + r1 * DD + d0) = make_float2(cx[nt][2] * i1, cx[nt][3] * i1);
    }
}

// ---------------- ctx -> wv -> ow + residual ----------------
__global__ void __launch_bounds__(128) proj_add_kernel(
    const float* __restrict__ mwd, const float* __restrict__ mbd,
    const float* __restrict__ owd, const float* __restrict__ obd,
    const float* __restrict__ mwe, const float* __restrict__ mbe,
    const float* __restrict__ owe, const float* __restrict__ obe) {
    __shared__ float t1[NLAT][DD];
    int b = blockIdx.x, t = threadIdx.x;
    float acc2[NLAT];
    float ob2 = obd[t] + obe[t];
    #pragma unroll
    for (int i = 0; i < NLAT; i++) acc2[i] = ob2;

    for (int mod = 0; mod < 2; mod++) {
        const float* mw = mod ? mwe : mwd;
        const float* mb = mod ? mbe : mbd;
        const float* ow = mod ? owe : owd;
        const float* ctxb = g_ctx[mod] + (size_t)b * NPAIR * DD;
        int h = t >> 5;
        float a1[NLAT];
        float bv = mb[2 * DD + t];
        #pragma unroll
        for (int i = 0; i < NLAT; i++) a1[i] = bv;
        const float4* wvp = (const float4*)(mw + (size_t)(2 * DD + t) * DD);
        #pragma unroll 2
        for (int d4 = 0; d4 < DD / 4; d4++) {
            float4 w4 = wvp[d4];
            #pragma unroll
            for (int i = 0; i < NLAT; i++) {
                float4 c4 = *(const float4*)(ctxb + ((i * NH + h) * DD + d4 * 4));
                a1[i] = fmaf(c4.x, w4.x, fmaf(c4.y, w4.y, fmaf(c4.z, w4.z, fmaf(c4.w, w4.w, a1[i]))));
            }
        }
        __syncthreads();
        #pragma unroll
        for (int i = 0; i < NLAT; i++) t1[i][t] = a1[i];
        __syncthreads();
        const float4* owp = (const float4*)(ow + (size_t)t * DD);
        #pragma unroll 2
        for (int u4 = 0; u4 < DD / 4; u4++) {
            float4 w4 = owp[u4];
            #pragma unroll
            for (int i = 0; i < NLAT; i++) {
                float4 h4 = *(const float4*)(&t1[i][u4 * 4]);
                acc2[i] = fmaf(h4.x, w4.x, fmaf(h4.y, w4.y, fmaf(h4.z, w4.z, fmaf(h4.w, w4.w, acc2[i]))));
            }
        }
        __syncthreads();
    }
    float* latb = g_lat + (size_t)b * NLAT * DD;
    #pragma unroll
    for (int i = 0; i < NLAT; i++) latb[i * DD + t] += acc2[i];
}

// ---------------- FFN ----------------
__global__ void __launch_bounds__(256) ffn_kernel(
    const float* __restrict__ lng, const float* __restrict__ lnb,
    const float* __restrict__ w1, const float* __restrict__ b1,
    const float* __restrict__ w2, const float* __restrict__ b2) {
    __shared__ float nl[NLAT][DD];
    __shared__ float hid[NLAT][2 * DD];
    int b = blockIdx.x, t = threadIdx.x;
    float* latb = g_lat + (size_t)b * NLAT * DD;
    layernorm_rows(latb, lng, lnb, nl, t, 256);
    __syncthreads();
    {
        float acc[NLAT];
        float bv = b1[t];
        #pragma unroll
        for (int i = 0; i < NLAT; i++) acc[i] = bv;
        const float4* wp = (const float4*)(w1 + (size_t)t * DD);
        #pragma unroll 2
        for (int d4 = 0; d4 < DD / 4; d4++) {
            float4 w4 = wp[d4];
            #pragma unroll
            for (int i = 0; i < NLAT; i++) {
                float4 n4 = *(const float4*)(&nl[i][d4 * 4]);
                acc[i] = fmaf(n4.x, w4.x, fmaf(n4.y, w4.y, fmaf(n4.z, w4.z, fmaf(n4.w, w4.w, acc[i]))));
            }
        }
        #pragma unroll
        for (int i = 0; i < NLAT; i++) hid[i][t] = fmaxf(acc[i], 0.0f);
    }
    __syncthreads();
    if (t < DD) {
        float acc[NLAT];
        float bv = b2[t];
        #pragma unroll
        for (int i = 0; i < NLAT; i++) acc[i] = bv;
        const float4* wp = (const float4*)(w2 + (size_t)t * 2 * DD);
        #pragma unroll 2
        for (int u4 = 0; u4 < 2 * DD / 4; u4++) {
            float4 w4 = wp[u4];
            #pragma unroll
            for (int i = 0; i < NLAT; i++) {
                float4 h4 = *(const float4*)(&hid[i][u4 * 4]);
                acc[i] = fmaf(h4.x, w4.x, fmaf(h4.y, w4.y, fmaf(h4.z, w4.z, fmaf(h4.w, w4.w, acc[i]))));
            }
        }
        #pragma unroll
        for (int i = 0; i < NLAT; i++) latb[i * DD + t] += acc[i];
    }
}

// ---------------- head ----------------
__global__ void __launch_bounds__(128) head_kernel(
    const float* __restrict__ w1, const float* __restrict__ b1,
    const float* __restrict__ w2, const float* __restrict__ b2,
    float* __restrict__ out) {
    __shared__ float part[4];
    int b = blockIdx.x, t = threadIdx.x;
    const float4* flat = (const float4*)(g_lat + (size_t)b * NLAT * DD);
    const float4* wp = (const float4*)(w1 + (size_t)t * NLAT * DD);
    float acc = b1[t];
    #pragma unroll 4
    for (int u4 = 0; u4 < NLAT * DD / 4; u4++) {
        float4 f4 = flat[u4];
        float4 w4 = wp[u4];
        acc = fmaf(f4.x, w4.x, fmaf(f4.y, w4.y, fmaf(f4.z, w4.z, fmaf(f4.w, w4.w, acc))));
    }
    float v = fmaxf(acc, 0.0f) * w2[t];
    #pragma unroll
    for (int o = 16; o; o >>= 1) v += __shfl_xor_sync(0xffffffffu, v, o);
    if ((t & 31) == 0) part[t >> 5] = v;
    __syncthreads();
    if (t == 0) {
        float x = part[0] + part[1] + part[2] + part[3] + b2[0];
        out[b] = (x > 20.0f) ? x : log1pf(__expf(x));
    }
}

extern "C" void kernel_launch(void* const* d_in, const int* in_sizes, int n_in,
                              void* d_out, int out_size) {
    const float* drug_k   = (const float*)d_in[0];
    const float* drug_v   = (const float*)d_in[1];
    const float* enz_k    = (const float*)d_in[2];
    const float* enz_v    = (const float*)d_in[3];
    const int*   drug_b   = (const int*)d_in[4];
    const int*   enz_b    = (const int*)d_in[5];
    const float* latents  = (const float*)d_in[6];
    const float* wq_d     = (const float*)d_in[7];
    const float* bq_d     = (const float*)d_in[8];
    const float* wq_e     = (const float*)d_in[9];
    const float* bq_e     = (const float*)d_in[10];
    const float* mha_d_w  = (const float*)d_in[11];
    const float* mha_d_b  = (const float*)d_in[12];
    const float* mha_d_ow = (const float*)d_in[13];
    const float* mha_d_ob = (const float*)d_in[14];
    const float* mha_e_w  = (const float*)d_in[15];
    const float* mha_e_b  = (const float*)d_in[16];
    const float* mha_e_ow = (const float*)d_in[17];
    const float* mha_e_ob = (const float*)d_in[18];
    const float* ln1_g    = (const float*)d_in[19];
    const float* ln1_b    = (const float*)d_in[20];
    const float* ln2_g    = (const float*)d_in[21];
    const float* ln2_b    = (const float*)d_in[22];
    const float* ffn_w1   = (const float*)d_in[23];
    const float* ffn_b1   = (const float*)d_in[24];
    const float* ffn_w2   = (const float*)d_in[25];
    const float* ffn_b2   = (const float*)d_in[26];
    const float* head_w1  = (const float*)d_in[27];
    const float* head_b1  = (const float*)d_in[28];
    const float* head_w2  = (const float*)d_in[29];
    const float* head_b2  = (const float*)d_in[30];
    float* out = (float*)d_out;

    offsets_kernel<<<3, 256>>>(drug_b, enz_b);
    init_lat_kernel<<<(BB * NLAT * DD + 255) / 256, 256>>>(latents);

    for (int l = 0; l < LAYERS; l++) {
        size_t oD = (size_t)l * DD * DD;
        size_t o3D = (size_t)l * 3 * DD * DD;
        size_t o3b = (size_t)l * 3 * DD;
        size_t oV = (size_t)l * DD;
        size_t oF1 = (size_t)l * 2 * DD * DD;
        size_t oF1b = (size_t)l * 2 * DD;

        prep_q_kernel<<<BB, 128>>>(
            ln1_g + oV, ln1_b + oV,
            wq_d + oD, bq_d + oV, mha_d_w + o3D, mha_d_b + o3b,
            wq_e + oD, bq_e + oV, mha_e_w + o3D, mha_e_b + o3b);

        attn_kernel<<<BB, 256>>>(0, drug_k, drug_v);
        attn_kernel<<<BB, 256>>>(1, enz_k, enz_v);

        proj_add_kernel<<<BB, 128>>>(
            mha_d_w + o3D, mha_d_b + o3b, mha_d_ow + oD, mha_d_ob + oV,
            mha_e_w + o3D, mha_e_b + o3b, mha_e_ow + oD, mha_e_ob + oV);

        ffn_kernel<<<BB, 256>>>(
            ln2_g + oV, ln2_b + oV,
            ffn_w1 + oF1, ffn_b1 + oF1b, ffn_w2 + oF1, ffn_b2 + oV);
    }

    head_kernel<<<BB, 128>>>(head_w1, head_b1, head_w2, head_b2, out);
}

// round 7
// speedup vs baseline: 1.4582x; 1.0097x over previous
#include <cuda_runtime.h>
#include <cuda_bf16.h>
#include <stdint.h>
#include <math.h>

#define BB 512
#define DD 128
#define NLAT 16
#define NH 4
#define HDIM 32
#define ND 25600
#define NE 153600
#define NPAIR 64
#define LAYERS 4

// scratch (static device globals: allowed)
__device__ float g_lat[BB * NLAT * DD];
__device__ float g_qt[2][BB * NPAIR * DD];
__device__ float g_ctx[2][BB * NPAIR * DD];
__device__ int   g_starts[2][BB + 1];

__device__ __forceinline__ int lb_dev(const int* __restrict__ a, int n, int key) {
    int lo = 0, hi = n;
    while (lo < hi) { int mid = (lo + hi) >> 1; if (a[mid] < key) lo = mid + 1; else hi = mid; }
    return lo;
}

__global__ void offsets_kernel(const int* __restrict__ db, const int* __restrict__ eb) {
    int i = blockIdx.x * blockDim.x + threadIdx.x;
    if (i <= BB) { g_starts[0][i] = lb_dev(db, ND, i); g_starts[1][i] = lb_dev(eb, NE, i); }
}

__global__ void init_lat_kernel(const float* __restrict__ latents) {
    int i = blockIdx.x * blockDim.x + threadIdx.x;
    if (i < BB * NLAT * DD) g_lat[i] = latents[i & (NLAT * DD - 1)];
}

// ---------------- shared small-GEMM helpers (fp32) ----------------
__device__ __forceinline__ void layernorm_rows(const float* __restrict__ src,
                                               const float* __restrict__ g,
                                               const float* __restrict__ bta,
                                               float (*dst)[DD], int t, int nthr) {
    int warp = t >> 5, lane = t & 31, nw = nthr >> 5;
    for (int r = warp; r < NLAT; r += nw) {
        float4 v = ((const float4*)(src + r * DD))[lane];
        float s = v.x + v.y + v.z + v.w;
        #pragma unroll
        for (int o = 16; o; o >>= 1) s += __shfl_xor_sync(0xffffffffu, s, o);
        float mean = s * (1.0f / DD);
        float dx = v.x - mean, dy = v.y - mean, dz = v.z - mean, dw = v.w - mean;
        float q = dx * dx + dy * dy + dz * dz + dw * dw;
        #pragma unroll
        for (int o = 16; o; o >>= 1) q += __shfl_xor_sync(0xffffffffu, q, o);
        float rstd = rsqrtf(q * (1.0f / DD) + 1e-5f);
        int c = lane * 4;
        dst[r][c + 0] = dx * rstd * g[c + 0] + bta[c + 0];
        dst[r][c + 1] = dy * rstd * g[c + 1] + bta[c + 1];
        dst[r][c + 2] = dz * rstd * g[c + 2] + bta[c + 2];
        dst[r][c + 3] = dw * rstd * g[c + 3] + bta[c + 3];
    }
}

__device__ __forceinline__ void proj128(const float (*src)[DD], float (*dst)[DD],
                                        const float* __restrict__ W,
                                        const float* __restrict__ bias, int t) {
    float acc[NLAT];
    float bv = bias[t];
    #pragma unroll
    for (int i = 0; i < NLAT; i++) acc[i] = bv;
    const float4* w4p = (const float4*)(W + t * DD);
    #pragma unroll 4
    for (int j4 = 0; j4 < DD / 4; j4++) {
        float4 w4 = w4p[j4];
        #pragma unroll
        for (int i = 0; i < NLAT; i++) {
            float4 n4 = *(const float4*)(&src[i][j4 * 4]);
            acc[i] = fmaf(n4.x, w4.x, fmaf(n4.y, w4.y, fmaf(n4.z, w4.z, fmaf(n4.w, w4.w, acc[i]))));
        }
    }
    __syncthreads();
    #pragma unroll
    for (int i = 0; i < NLAT; i++) dst[i][t] = acc[i];
}

__device__ __forceinline__ void qt_proj(const float (*qh)[DD], const float* __restrict__ W,
                                        float* __restrict__ qtg, int t) {
    const float scale = 0.17677669529663688f; // 1/sqrt(32)
    #pragma unroll
    for (int h = 0; h < NH; h++) {
        float acc[NLAT];
        #pragma unroll
        for (int i = 0; i < NLAT; i++) acc[i] = 0.0f;
        for (int j = 0; j < HDIM; j++) {
            float wv = W[(DD + h * HDIM + j) * DD + t];
            #pragma unroll
            for (int i = 0; i < NLAT; i++) acc[i] = fmaf(qh[i][h * HDIM + j], wv, acc[i]);
        }
        #pragma unroll
        for (int i = 0; i < NLAT; i++) qtg[(i * NH + h) * DD + t] = acc[i] * scale;
    }
}

// grid (BB, 2): blockIdx.y = modality. LN1 + q-proj + mha-q-proj + wk fold.
__global__ void __launch_bounds__(128) prep_q_kernel(
    const float* __restrict__ lng, const float* __restrict__ lnb,
    const float* __restrict__ wqd, const float* __restrict__ bqd,
    const float* __restrict__ mwd, const float* __restrict__ mbd,
    const float* __restrict__ wqe, const float* __restrict__ bqe,
    const float* __restrict__ mwe, const float* __restrict__ mbe) {
    __shared__ float nl[NLAT][DD];
    __shared__ float qb[NLAT][DD];
    __shared__ float qh[NLAT][DD];
    int b = blockIdx.x, t = threadIdx.x, mod = blockIdx.y;
    const float* wq = mod ? wqe : wqd;
    const float* bq = mod ? bqe : bqd;
    const float* mw = mod ? mwe : mwd;
    const float* mb = mod ? mbe : mbd;

    layernorm_rows(g_lat + (size_t)b * NLAT * DD, lng, lnb, nl, t, 128);
    __syncthreads();
    proj128(nl, qb, wq, bq, t); __syncthreads();
    proj128(qb, qh, mw, mb, t); __syncthreads();
    qt_proj(qh, mw, g_qt[mod] + (size_t)b * NPAIR * DD, t);
}

// ---------------- tensor-core attention ----------------
__device__ __forceinline__ uint32_t s2u(const void* p) {
    return (uint32_t)__cvta_generic_to_shared(p);
}
__device__ __forceinline__ uint32_t f2bf2(float x, float y) {
    __nv_bfloat162 h = __floats2bfloat162_rn(x, y);
    return *reinterpret_cast<uint32_t*>(&h);
}

#define LDSM4(R, addr) asm volatile( \
    "ldmatrix.sync.aligned.m8n8.x4.shared.b16 {%0,%1,%2,%3},[%4];" \
    : "=r"((R)[0]), "=r"((R)[1]), "=r"((R)[2]), "=r"((R)[3]) : "r"(addr))
#define LDSM4T(R, addr) asm volatile( \
    "ldmatrix.sync.aligned.m8n8.x4.trans.shared.b16 {%0,%1,%2,%3},[%4];" \
    : "=r"((R)[0]), "=r"((R)[1]), "=r"((R)[2]), "=r"((R)[3]) : "r"(addr))
#define MMA16816(D, A, B0, B1) asm volatile( \
    "mma.sync.aligned.m16n8k16.row.col.f32.bf16.bf16.f32 " \
    "{%0,%1,%2,%3},{%4,%5,%6,%7},{%8,%9},{%0,%1,%2,%3};" \
    : "+f"((D)[0]), "+f"((D)[1]), "+f"((D)[2]), "+f"((D)[3]) \
    : "r"((A)[0]), "r"((A)[1]), "r"((A)[2]), "r"((A)[3]), "r"(B0), "r"(B1))

// chunk = 64 tokens. dyn smem layout (halves/floats):
//  Ks[64][136] bf16, Vs[64][136] bf16, Ps[64][72] bf16, ss[64][68] f32, m/l/sc[64] f32
#define KS_HALF (64 * 136)
#define PS_HALF (64 * 72)
#define SS_FLT  (64 * 68)
#define ATT_BYTES (KS_HALF * 2 * 2 + PS_HALF * 2 + SS_FLT * 4 + 3 * 64 * 4)

// grid (BB, 2): blockIdx.y = modality. 256 threads.
__global__ void __launch_bounds__(256, 2) attn_kernel(
    const float* __restrict__ dKg, const float* __restrict__ dVg,
    const float* __restrict__ eKg, const float* __restrict__ eVg) {
    extern __shared__ char smraw[];
    __nv_bfloat16* Ks = (__nv_bfloat16*)smraw;                  // [64][136]
    __nv_bfloat16* Vs = Ks + KS_HALF;                           // [64][136]
    __nv_bfloat16* Ps = Vs + KS_HALF;                           // [64][72]
    float* ss  = (float*)(Ps + PS_HALF);                        // [64][68]
    float* m_s = ss + SS_FLT;
    float* l_s = m_s + 64;
    float* sc_s = l_s + 64;

    int b = blockIdx.x, t = threadIdx.x, mod = blockIdx.y;
    const float* Kg = mod ? eKg : dKg;
    const float* Vg = mod ? eVg : dVg;
    int w = t >> 5, lane = t & 31;
    int g = lane >> 2, tc = lane & 3;
    int s0 = g_starts[mod][b];
    int cnt = g_starts[mod][b + 1] - s0;

    int pb = (w & 3) * 16;        // pair-row base for this warp
    int th = w >> 2;              // token half (scores) / dim half (ctx)

    // Load Qt A-fragments (bf16) from global fp32; persistent in regs.
    uint32_t qa[8][4];
    {
        const float* qtb = g_qt[mod] + (size_t)b * NPAIR * DD;
        int r0 = pb + g, r1 = pb + g + 8;
        #pragma unroll
        for (int ks = 0; ks < 8; ks++) {
            int c0 = ks * 16 + tc * 2;
            float2 v00 = *(const float2*)(qtb + r0 * DD + c0);
            float2 v10 = *(const float2*)(qtb + r1 * DD + c0);
            float2 v01 = *(const float2*)(qtb + r0 * DD + c0 + 8);
            float2 v11 = *(const float2*)(qtb + r1 * DD + c0 + 8);
            qa[ks][0] = f2bf2(v00.x, v00.y);
            qa[ks][1] = f2bf2(v10.x, v10.y);
            qa[ks][2] = f2bf2(v01.x, v01.y);
            qa[ks][3] = f2bf2(v11.x, v11.y);
        }
    }
    if (t < 64) { m_s[t] = -1e30f; l_s[t] = 0.0f; }

    float cx[8][4];
    #pragma unroll
    for (int i = 0; i < 8; i++)
        #pragma unroll
        for (int j = 0; j < 4; j++) cx[i][j] = 0.0f;

    // ldmatrix base addresses
    // scores: warp covers tokens [th*32, th*32+32) as two 16-token tiles
    uint32_t addrK1 = s2u(Ks + (th * 32 + ((lane >> 4) << 3) + (lane & 7)) * 136 + ((lane >> 3) & 1) * 8);
    uint32_t addrK2 = addrK1 + 16 * 136 * 2;
    uint32_t addrP = s2u(Ps + (pb + (lane & 15)) * 72 + (lane >> 4) * 8);
    uint32_t addrV = s2u(Vs + (lane & 15) * 136 + th * 64 + (lane >> 4) * 8);

    for (int base = 0; base < cnt; base += 64) {
        int nk = min(64, cnt - base);
        __syncthreads();
        // Load K/V chunk -> bf16 smem (zero-fill padded rows)
        {
            const float4* Kr = (const float4*)(Kg + (size_t)(s0 + base) * DD);
            const float4* Vr = (const float4*)(Vg + (size_t)(s0 + base) * DD);
            #pragma unroll
            for (int i = t; i < 2048; i += 256) {
                int r = i >> 5, c = (i & 31) * 4;
                float4 kv = make_float4(0, 0, 0, 0), vv = make_float4(0, 0, 0, 0);
                if (r < nk) { kv = Kr[i]; vv = Vr[i]; }
                *(uint2*)(Ks + r * 136 + c) = make_uint2(f2bf2(kv.x, kv.y), f2bf2(kv.z, kv.w));
                *(uint2*)(Vs + r * 136 + c) = make_uint2(f2bf2(vv.x, vv.y), f2bf2(vv.z, vv.w));
            }
        }
        __syncthreads();
        // Scores: 16 pairs x 32 tokens per warp (two 16-token tiles)
        {
            float sa[4][4];
            #pragma unroll
            for (int j = 0; j < 4; j++)
                #pragma unroll
                for (int q = 0; q < 4; q++) sa[j][q] = 0.0f;
            #pragma unroll
            for (int ks = 0; ks < 8; ks++) {
                uint32_t kb1[4], kb2[4];
                LDSM4(kb1, addrK1 + ks * 32);
                LDSM4(kb2, addrK2 + ks * 32);
                MMA16816(sa[0], qa[ks], kb1[0], kb1[1]);
                MMA16816(sa[1], qa[ks], kb1[2], kb1[3]);
                MMA16816(sa[2], qa[ks], kb2[0], kb2[1]);
                MMA16816(sa[3], qa[ks], kb2[2], kb2[3]);
            }
            int r0 = pb + g, r1 = pb + g + 8;
            #pragma unroll
            for (int j = 0; j < 4; j++) {
                int c0 = th * 32 + j * 8 + tc * 2;
                *(float2*)&ss[r0 * 68 + c0] = make_float2(sa[j][0], sa[j][1]);
                *(float2*)&ss[r1 * 68 + c0] = make_float2(sa[j][2], sa[j][3]);
            }
        }
        __syncthreads();
        // Online softmax per pair (64 threads)
        if (t < 64) {
            float mo = m_s[t], cm = mo;
            for (int k = 0; k < nk; k++) cm = fmaxf(cm, ss[t * 68 + k]);
            float scl = __expf(mo - cm);
            float l = l_s[t] * scl;
            float sum = 0.0f;
            #pragma unroll 4
            for (int k = 0; k < 64; k++) {
                float e = (k < nk) ? __expf(ss[t * 68 + k] - cm) : 0.0f;
                Ps[t * 72 + k] = __float2bfloat16(e);
                sum += e;
            }
            l_s[t] = l + sum; m_s[t] = cm; sc_s[t] = scl;
        }
        __syncthreads();
        // Ctx accumulate: rescale then += P @ V (4 ksteps of 16)
        {
            float sc0 = sc_s[pb + g], sc1 = sc_s[pb + g + 8];
            #pragma unroll
            for (int nt = 0; nt < 8; nt++) {
                cx[nt][0] *= sc0; cx[nt][1] *= sc0;
                cx[nt][2] *= sc1; cx[nt][3] *= sc1;
            }
            #pragma unroll
            for (int ks = 0; ks < 4; ks++) {
                uint32_t pa[4];
                LDSM4(pa, addrP + ks * 32);
                #pragma unroll
                for (int ntp = 0; ntp < 4; ntp++) {
                    uint32_t vb[4];
                    LDSM4T(vb, addrV + ks * 4352 + ntp * 32);
                    MMA16816(cx[ntp * 2 + 0], pa, vb[0], vb[1]);
                    MMA16816(cx[ntp * 2 + 1], pa, vb[2], vb[3]);
                }
            }
        }
    }
    // normalize + store ctx
    int r0 = pb + g, r1 = pb + g + 8;
    float l0 = l_s[r0], l1 = l_s[r1];
    float i0 = (l0 > 0.0f) ? 1.0f / l0 : 0.0f;
    float i1 = (l1 > 0.0f) ? 1.0f / l1 : 0.0f;
    float* cbp = g_ctx[mod] + (size_t)b * NPAIR * DD;
    #pragma unroll
    for (int nt = 0; nt < 8; nt++) {
        int d0 = th * 64 + nt * 8 + tc * 2;
        *(float2*)(cbp + r0 * DD + d0) = make_float2(cx[nt][0] * i0, cx[nt][1] * i0);
        *(float2*)(cbp + r1 * DD + d0) = make_float2(cx[nt][2] * i1, cx[nt][3] * i1);
    }
}

// ---------------- ctx -> wv -> ow + residual ----------------
__global__ void __launch_bounds__(128) proj_add_kernel(
    const float* __restrict__ mwd, const float* __restrict__ mbd,
    const float* __restrict__ owd, const float* __restrict__ obd,
    const float* __restrict__ mwe, const float* __restrict__ mbe,
    const float* __restrict__ owe, const float* __restrict__ obe) {
    __shared__ float t1[NLAT][DD];
    int b = blockIdx.x, t = threadIdx.x;
    float acc2[NLAT];
    float ob2 = obd[t] + obe[t];
    #pragma unroll
    for (int i = 0; i < NLAT; i++) acc2[i] = ob2;

    for (int mod = 0; mod < 2; mod++) {
        const float* mw = mod ? mwe : mwd;
        const float* mb = mod ? mbe : mbd;
        const float* ow = mod ? owe : owd;
        const float* ctxb = g_ctx[mod] + (size_t)b * NPAIR * DD;
        int h = t >> 5;
        float a1[NLAT];
        float bv = mb[2 * DD + t];
        #pragma unroll
        for (int i = 0; i < NLAT; i++) a1[i] = bv;
        const float4* wvp = (const float4*)(mw + (size_t)(2 * DD + t) * DD);
        #pragma unroll 2
        for (int d4 = 0; d4 < DD / 4; d4++) {
            float4 w4 = wvp[d4];
            #pragma unroll
            for (int i = 0; i < NLAT; i++) {
                float4 c4 = *(const float4*)(ctxb + ((i * NH + h) * DD + d4 * 4));
                a1[i] = fmaf(c4.x, w4.x, fmaf(c4.y, w4.y, fmaf(c4.z, w4.z, fmaf(c4.w, w4.w, a1[i]))));
            }
        }
        __syncthreads();
        #pragma unroll
        for (int i = 0; i < NLAT; i++) t1[i][t] = a1[i];
        __syncthreads();
        const float4* owp = (const float4*)(ow + (size_t)t * DD);
        #pragma unroll 2
        for (int u4 = 0; u4 < DD / 4; u4++) {
            float4 w4 = owp[u4];
            #pragma unroll
            for (int i = 0; i < NLAT; i++) {
                float4 h4 = *(const float4*)(&t1[i][u4 * 4]);
                acc2[i] = fmaf(h4.x, w4.x, fmaf(h4.y, w4.y, fmaf(h4.z, w4.z, fmaf(h4.w, w4.w, acc2[i]))));
            }
        }
        __syncthreads();
    }
    float* latb = g_lat + (size_t)b * NLAT * DD;
    #pragma unroll
    for (int i = 0; i < NLAT; i++) latb[i * DD + t] += acc2[i];
}

// ---------------- FFN ----------------
__global__ void __launch_bounds__(256) ffn_kernel(
    const float* __restrict__ lng, const float* __restrict__ lnb,
    const float* __restrict__ w1, const float* __restrict__ b1,
    const float* __restrict__ w2, const float* __restrict__ b2) {
    __shared__ float nl[NLAT][DD];
    __shared__ float hid[NLAT][2 * DD];
    int b = blockIdx.x, t = threadIdx.x;
    float* latb = g_lat + (size_t)b * NLAT * DD;
    layernorm_rows(latb, lng, lnb, nl, t, 256);
    __syncthreads();
    {
        float acc[NLAT];
        float bv = b1[t];
        #pragma unroll
        for (int i = 0; i < NLAT; i++) acc[i] = bv;
        const float4* wp = (const float4*)(w1 + (size_t)t * DD);
        #pragma unroll 2
        for (int d4 = 0; d4 < DD / 4; d4++) {
            float4 w4 = wp[d4];
            #pragma unroll
            for (int i = 0; i < NLAT; i++) {
                float4 n4 = *(const float4*)(&nl[i][d4 * 4]);
                acc[i] = fmaf(n4.x, w4.x, fmaf(n4.y, w4.y, fmaf(n4.z, w4.z, fmaf(n4.w, w4.w, acc[i]))));
            }
        }
        #pragma unroll
        for (int i = 0; i < NLAT; i++) hid[i][t] = fmaxf(acc[i], 0.0f);
    }
    __syncthreads();
    if (t < DD) {
        float acc[NLAT];
        float bv = b2[t];
        #pragma unroll
        for (int i = 0; i < NLAT; i++) acc[i] = bv;
        const float4* wp = (const float4*)(w2 + (size_t)t * 2 * DD);
        #pragma unroll 2
        for (int u4 = 0; u4 < 2 * DD / 4; u4++) {
            float4 w4 = wp[u4];
            #pragma unroll
            for (int i = 0; i < NLAT; i++) {
                float4 h4 = *(const float4*)(&hid[i][u4 * 4]);
                acc[i] = fmaf(h4.x, w4.x, fmaf(h4.y, w4.y, fmaf(h4.z, w4.z, fmaf(h4.w, w4.w, acc[i]))));
            }
        }
        #pragma unroll
        for (int i = 0; i < NLAT; i++) latb[i * DD + t] += acc[i];
    }
}

// ---------------- head ----------------
__global__ void __launch_bounds__(128) head_kernel(
    const float* __restrict__ w1, const float* __restrict__ b1,
    const float* __restrict__ w2, const float* __restrict__ b2,
    float* __restrict__ out) {
    __shared__ float part[4];
    int b = blockIdx.x, t = threadIdx.x;
    const float4* flat = (const float4*)(g_lat + (size_t)b * NLAT * DD);
    const float4* wp = (const float4*)(w1 + (size_t)t * NLAT * DD);
    float acc = b1[t];
    #pragma unroll 4
    for (int u4 = 0; u4 < NLAT * DD / 4; u4++) {
        float4 f4 = flat[u4];
        float4 w4 = wp[u4];
        acc = fmaf(f4.x, w4.x, fmaf(f4.y, w4.y, fmaf(f4.z, w4.z, fmaf(f4.w, w4.w, acc))));
    }
    float v = fmaxf(acc, 0.0f) * w2[t];
    #pragma unroll
    for (int o = 16; o; o >>= 1) v += __shfl_xor_sync(0xffffffffu, v, o);
    if ((t & 31) == 0) part[t >> 5] = v;
    __syncthreads();
    if (t == 0) {
        float x = part[0] + part[1] + part[2] + part[3] + b2[0];
        out[b] = (x > 20.0f) ? x : log1pf(__expf(x));
    }
}

extern "C" void kernel_launch(void* const* d_in, const int* in_sizes, int n_in,
                              void* d_out, int out_size) {
    const float* drug_k   = (const float*)d_in[0];
    const float* drug_v   = (const float*)d_in[1];
    const float* enz_k    = (const float*)d_in[2];
    const float* enz_v    = (const float*)d_in[3];
    const int*   drug_b   = (const int*)d_in[4];
    const int*   enz_b    = (const int*)d_in[5];
    const float* latents  = (const float*)d_in[6];
    const float* wq_d     = (const float*)d_in[7];
    const float* bq_d     = (const float*)d_in[8];
    const float* wq_e     = (const float*)d_in[9];
    const float* bq_e     = (const float*)d_in[10];
    const float* mha_d_w  = (const float*)d_in[11];
    const float* mha_d_b  = (const float*)d_in[12];
    const float* mha_d_ow = (const float*)d_in[13];
    const float* mha_d_ob = (const float*)d_in[14];
    const float* mha_e_w  = (const float*)d_in[15];
    const float* mha_e_b  = (const float*)d_in[16];
    const float* mha_e_ow = (const float*)d_in[17];
    const float* mha_e_ob = (const float*)d_in[18];
    const float* ln1_g    = (const float*)d_in[19];
    const float* ln1_b    = (const float*)d_in[20];
    const float* ln2_g    = (const float*)d_in[21];
    const float* ln2_b    = (const float*)d_in[22];
    const float* ffn_w1   = (const float*)d_in[23];
    const float* ffn_b1   = (const float*)d_in[24];
    const float* ffn_w2   = (const float*)d_in[25];
    const float* ffn_b2   = (const float*)d_in[26];
    const float* head_w1  = (const float*)d_in[27];
    const float* head_b1  = (const float*)d_in[28];
    const float* head_w2  = (const float*)d_in[29];
    const float* head_b2  = (const float*)d_in[30];
    float* out = (float*)d_out;

    static int s_attr_set = 0;
    if (!s_attr_set) {
        cudaFuncSetAttribute(attn_kernel, cudaFuncAttributeMaxDynamicSharedMemorySize, ATT_BYTES);
        s_attr_set = 1;
    }

    offsets_kernel<<<3, 256>>>(drug_b, enz_b);
    init_lat_kernel<<<(BB * NLAT * DD + 255) / 256, 256>>>(latents);

    dim3 grid2(BB, 2);
    for (int l = 0; l < LAYERS; l++) {
        size_t oD = (size_t)l * DD * DD;
        size_t o3D = (size_t)l * 3 * DD * DD;
        size_t o3b = (size_t)l * 3 * DD;
        size_t oV = (size_t)l * DD;
        size_t oF1 = (size_t)l * 2 * DD * DD;
        size_t oF1b = (size_t)l * 2 * DD;

        prep_q_kernel<<<grid2, 128>>>(
            ln1_g + oV, ln1_b + oV,
            wq_d + oD, bq_d + oV, mha_d_w + o3D, mha_d_b + o3b,
            wq_e + oD, bq_e + oV, mha_e_w + o3D, mha_e_b + o3b);

        attn_kernel<<<grid2, 256, ATT_BYTES>>>(drug_k, drug_v, enz_k, enz_v);

        proj_add_kernel<<<BB, 128>>>(
            mha_d_w + o3D, mha_d_b + o3b, mha_d_ow + oD, mha_d_ob + oV,
            mha_e_w + o3D, mha_e_b + o3b, mha_e_ow + oD, mha_e_ob + oV);

        ffn_kernel<<<BB, 256>>>(
            ln2_g + oV, ln2_b + oV,
            ffn_w1 + oF1, ffn_b1 + oF1b, ffn_w2 + oF1, ffn_b2 + oV);
    }

    head_kernel<<<BB, 128>>>(head_w1, head_b1, head_w2, head_b2, out);
}

// round 8
// speedup vs baseline: 1.5520x; 1.0643x over previous
#include <cuda_runtime.h>
#include <cuda_bf16.h>
#include <stdint.h>
#include <math.h>

#define BB 512
#define DD 128
#define NLAT 16
#define NH 4
#define HDIM 32
#define ND 25600
#define NE 153600
#define NPAIR 64
#define LAYERS 4

// scratch (static device globals: allowed)
__device__ float g_lat[BB * NLAT * DD];
__device__ float g_qt[2][BB * NPAIR * DD];
__device__ float g_ctx[2][BB * NPAIR * DD];
__device__ int   g_starts[2][BB + 1];
__device__ __nv_bfloat16 g_dk[ND * DD];
__device__ __nv_bfloat16 g_dv[ND * DD];
__device__ __nv_bfloat16 g_ek[NE * DD];
__device__ __nv_bfloat16 g_ev[NE * DD];

__device__ __forceinline__ int lb_dev(const int* __restrict__ a, int n, int key) {
    int lo = 0, hi = n;
    while (lo < hi) { int mid = (lo + hi) >> 1; if (a[mid] < key) lo = mid + 1; else hi = mid; }
    return lo;
}

__global__ void offsets_kernel(const int* __restrict__ db, const int* __restrict__ eb) {
    int i = blockIdx.x * blockDim.x + threadIdx.x;
    if (i <= BB) { g_starts[0][i] = lb_dev(db, ND, i); g_starts[1][i] = lb_dev(eb, NE, i); }
}

__global__ void init_lat_kernel(const float* __restrict__ latents) {
    int i = blockIdx.x * blockDim.x + threadIdx.x;
    if (i < BB * NLAT * DD) g_lat[i] = latents[i & (NLAT * DD - 1)];
}

__device__ __forceinline__ uint32_t f2bf2(float x, float y) {
    __nv_bfloat162 h = __floats2bfloat162_rn(x, y);
    return *reinterpret_cast<uint32_t*>(&h);
}

// one-time fp32 -> bf16 conversion of all K/V
__global__ void cvt_kernel(const float* __restrict__ dk, const float* __restrict__ dv,
                           const float* __restrict__ ek, const float* __restrict__ ev) {
    int i = blockIdx.x * blockDim.x + threadIdx.x; // unit = 4 floats
    int i4 = i * 4;
    if (i4 < ND * DD) {
        float4 a = *(const float4*)(dk + i4);
        float4 b = *(const float4*)(dv + i4);
        *(uint2*)(g_dk + i4) = make_uint2(f2bf2(a.x, a.y), f2bf2(a.z, a.w));
        *(uint2*)(g_dv + i4) = make_uint2(f2bf2(b.x, b.y), f2bf2(b.z, b.w));
    }
    if (i4 < NE * DD) {
        float4 a = *(const float4*)(ek + i4);
        float4 b = *(const float4*)(ev + i4);
        *(uint2*)(g_ek + i4) = make_uint2(f2bf2(a.x, a.y), f2bf2(a.z, a.w));
        *(uint2*)(g_ev + i4) = make_uint2(f2bf2(b.x, b.y), f2bf2(b.z, b.w));
    }
}

// ---------------- latent-side helpers (fp32) ----------------
__device__ __forceinline__ void layernorm_rows(const float* __restrict__ src,
                                               const float* __restrict__ g,
                                               const float* __restrict__ bta,
                                               float (*dst)[DD], int t, int nthr) {
    int warp = t >> 5, lane = t & 31, nw = nthr >> 5;
    for (int r = warp; r < NLAT; r += nw) {
        float4 v = ((const float4*)(src + r * DD))[lane];
        float s = v.x + v.y + v.z + v.w;
        #pragma unroll
        for (int o = 16; o; o >>= 1) s += __shfl_xor_sync(0xffffffffu, s, o);
        float mean = s * (1.0f / DD);
        float dx = v.x - mean, dy = v.y - mean, dz = v.z - mean, dw = v.w - mean;
        float q = dx * dx + dy * dy + dz * dz + dw * dw;
        #pragma unroll
        for (int o = 16; o; o >>= 1) q += __shfl_xor_sync(0xffffffffu, q, o);
        float rstd = rsqrtf(q * (1.0f / DD) + 1e-5f);
        int c = lane * 4;
        dst[r][c + 0] = dx * rstd * g[c + 0] + bta[c + 0];
        dst[r][c + 1] = dy * rstd * g[c + 1] + bta[c + 1];
        dst[r][c + 2] = dz * rstd * g[c + 2] + bta[c + 2];
        dst[r][c + 3] = dw * rstd * g[c + 3] + bta[c + 3];
    }
}

__device__ __forceinline__ void proj128(const float (*src)[DD], float (*dst)[DD],
                                        const float* __restrict__ W,
                                        const float* __restrict__ bias, int t) {
    float acc[NLAT];
    float bv = bias[t];
    #pragma unroll
    for (int i = 0; i < NLAT; i++) acc[i] = bv;
    const float4* w4p = (const float4*)(W + t * DD);
    #pragma unroll 4
    for (int j4 = 0; j4 < DD / 4; j4++) {
        float4 w4 = w4p[j4];
        #pragma unroll
        for (int i = 0; i < NLAT; i++) {
            float4 n4 = *(const float4*)(&src[i][j4 * 4]);
            acc[i] = fmaf(n4.x, w4.x, fmaf(n4.y, w4.y, fmaf(n4.z, w4.z, fmaf(n4.w, w4.w, acc[i]))));
        }
    }
    __syncthreads();
    #pragma unroll
    for (int i = 0; i < NLAT; i++) dst[i][t] = acc[i];
}

__device__ __forceinline__ void qt_proj(const float (*qh)[DD], const float* __restrict__ W,
                                        float* __restrict__ qtg, int t) {
    const float scale = 0.17677669529663688f; // 1/sqrt(32)
    #pragma unroll
    for (int h = 0; h < NH; h++) {
        float acc[NLAT];
        #pragma unroll
        for (int i = 0; i < NLAT; i++) acc[i] = 0.0f;
        #pragma unroll 4
        for (int j = 0; j < HDIM; j++) {
            float wv = W[(DD + h * HDIM + j) * DD + t];
            #pragma unroll
            for (int i = 0; i < NLAT; i++) acc[i] = fmaf(qh[i][h * HDIM + j], wv, acc[i]);
        }
        #pragma unroll
        for (int i = 0; i < NLAT; i++) qtg[(i * NH + h) * DD + t] = acc[i] * scale;
    }
}

// grid (BB, 2): blockIdx.y = modality.
__global__ void __launch_bounds__(128) prep_q_kernel(
    const float* __restrict__ lng, const float* __restrict__ lnb,
    const float* __restrict__ wqd, const float* __restrict__ bqd,
    const float* __restrict__ mwd, const float* __restrict__ mbd,
    const float* __restrict__ wqe, const float* __restrict__ bqe,
    const float* __restrict__ mwe, const float* __restrict__ mbe) {
    __shared__ float nl[NLAT][DD];
    __shared__ float qb[NLAT][DD];
    __shared__ float qh[NLAT][DD];
    int b = blockIdx.x, t = threadIdx.x, mod = blockIdx.y;
    const float* wq = mod ? wqe : wqd;
    const float* bq = mod ? bqe : bqd;
    const float* mw = mod ? mwe : mwd;
    const float* mb = mod ? mbe : mbd;

    layernorm_rows(g_lat + (size_t)b * NLAT * DD, lng, lnb, nl, t, 128);
    __syncthreads();
    proj128(nl, qb, wq, bq, t); __syncthreads();
    proj128(qb, qh, mw, mb, t); __syncthreads();
    qt_proj(qh, mw, g_qt[mod] + (size_t)b * NPAIR * DD, t);
}

// ---------------- tensor-core attention, cp.async double-buffered ----------------
__device__ __forceinline__ uint32_t s2u(const void* p) {
    return (uint32_t)__cvta_generic_to_shared(p);
}

#define LDSM4(R, addr) asm volatile( \
    "ldmatrix.sync.aligned.m8n8.x4.shared.b16 {%0,%1,%2,%3},[%4];" \
    : "=r"((R)[0]), "=r"((R)[1]), "=r"((R)[2]), "=r"((R)[3]) : "r"(addr))
#define LDSM4T(R, addr) asm volatile( \
    "ldmatrix.sync.aligned.m8n8.x4.trans.shared.b16 {%0,%1,%2,%3},[%4];" \
    : "=r"((R)[0]), "=r"((R)[1]), "=r"((R)[2]), "=r"((R)[3]) : "r"(addr))
#define MMA16816(D, A, B0, B1) asm volatile( \
    "mma.sync.aligned.m16n8k16.row.col.f32.bf16.bf16.f32 " \
    "{%0,%1,%2,%3},{%4,%5,%6,%7},{%8,%9},{%0,%1,%2,%3};" \
    : "+f"((D)[0]), "+f"((D)[1]), "+f"((D)[2]), "+f"((D)[3]) \
    : "r"((A)[0]), "r"((A)[1]), "r"((A)[2]), "r"((A)[3]), "r"(B0), "r"(B1))
#define CP16(dst, src) asm volatile("cp.async.cg.shared.global [%0], [%1], 16;\n" :: "r"(dst), "l"(src))
#define CP_COMMIT() asm volatile("cp.async.commit_group;\n" ::: "memory")
#define CP_WAIT1() asm volatile("cp.async.wait_group 1;\n" ::: "memory")
#define CP_WAIT0() asm volatile("cp.async.wait_group 0;\n" ::: "memory")

// dyn smem: Ks[2][64*136] bf16, Vs[2][64*136] bf16, Ps[64*72] bf16, ss[64*68] f32, m/l/sc[64]
#define KV_ELE (64 * 136)
#define ATT_BYTES (4 * KV_ELE * 2 + 64 * 72 * 2 + 64 * 68 * 4 + 3 * 64 * 4)

__device__ __forceinline__ void issue_chunk(const __nv_bfloat16* __restrict__ Kg,
                                            const __nv_bfloat16* __restrict__ Vg,
                                            __nv_bfloat16* Ksb, __nv_bfloat16* Vsb,
                                            int row0, int nk, int t) {
    #pragma unroll
    for (int i = t; i < 1024; i += 256) {
        int r = i >> 4, seg = (i & 15) * 8;
        if (r < nk) {
            CP16(s2u(Ksb + r * 136 + seg), Kg + (size_t)(row0 + r) * DD + seg);
            CP16(s2u(Vsb + r * 136 + seg), Vg + (size_t)(row0 + r) * DD + seg);
        }
    }
}

// grid 1024: bid<512 -> enzyme (long blocks first), else drug. 256 threads.
__global__ void __launch_bounds__(256, 2) attn_kernel() {
    extern __shared__ char smraw[];
    __nv_bfloat16* Ks0 = (__nv_bfloat16*)smraw;          // [2][64*136]
    __nv_bfloat16* Vs0 = Ks0 + 2 * KV_ELE;               // [2][64*136]
    __nv_bfloat16* Ps  = Vs0 + 2 * KV_ELE;               // [64*72]
    float* ss  = (float*)(Ps + 64 * 72);                 // [64*68]
    float* m_s = ss + 64 * 68;
    float* l_s = m_s + 64;
    float* sc_s = l_s + 64;

    int bid = blockIdx.x, t = threadIdx.x;
    int mod = (bid < 512) ? 1 : 0;
    int b = bid & 511;
    const __nv_bfloat16* Kg = mod ? g_ek : g_dk;
    const __nv_bfloat16* Vg = mod ? g_ev : g_dv;
    int w = t >> 5, lane = t & 31;
    int g = lane >> 2, tc = lane & 3;
    int s0 = g_starts[mod][b];
    int cnt = g_starts[mod][b + 1] - s0;

    int pb = (w & 3) * 16;   // pair-row base
    int th = w >> 2;         // token half (scores) / dim half (ctx)

    // zero-init KV buffers (avoid NaN garbage under P=0 columns on first use)
    for (int i = t; i < (4 * KV_ELE * 2) / 16; i += 256)
        ((uint4*)smraw)[i] = make_uint4(0, 0, 0, 0);

    // Qt A-fragments persistent in regs
    uint32_t qa[8][4];
    {
        const float* qtb = g_qt[mod] + (size_t)b * NPAIR * DD;
        int r0 = pb + g, r1 = pb + g + 8;
        #pragma unroll
        for (int ks = 0; ks < 8; ks++) {
            int c0 = ks * 16 + tc * 2;
            float2 v00 = *(const float2*)(qtb + r0 * DD + c0);
            float2 v10 = *(const float2*)(qtb + r1 * DD + c0);
            float2 v01 = *(const float2*)(qtb + r0 * DD + c0 + 8);
            float2 v11 = *(const float2*)(qtb + r1 * DD + c0 + 8);
            qa[ks][0] = f2bf2(v00.x, v00.y);
            qa[ks][1] = f2bf2(v10.x, v10.y);
            qa[ks][2] = f2bf2(v01.x, v01.y);
            qa[ks][3] = f2bf2(v11.x, v11.y);
        }
    }
    if (t < 64) { m_s[t] = -1e30f; l_s[t] = 0.0f; }

    float cx[8][4];
    #pragma unroll
    for (int i = 0; i < 8; i++)
        #pragma unroll
        for (int j = 0; j < 4; j++) cx[i][j] = 0.0f;

    uint32_t aK1 = s2u(Ks0 + (th * 32 + ((lane >> 4) << 3) + (lane & 7)) * 136 + ((lane >> 3) & 1) * 8);
    uint32_t aK2 = aK1 + 16 * 136 * 2;
    uint32_t aP  = s2u(Ps + (pb + (lane & 15)) * 72 + (lane >> 4) * 8);
    uint32_t aV  = s2u(Vs0 + (lane & 15) * 136 + th * 64 + (lane >> 4) * 8);

    int nchunks = (cnt + 63) >> 6;
    __syncthreads();   // zero-init visible before first cp.async
    if (nchunks > 0) {
        issue_chunk(Kg, Vg, Ks0, Vs0, s0, min(64, cnt), t);
        CP_COMMIT();
    }

    for (int k = 0; k < nchunks; k++) {
        int cur = k & 1;
        int nk = min(64, cnt - k * 64);
        if (k + 1 < nchunks) {
            int nk2 = min(64, cnt - (k + 1) * 64);
            issue_chunk(Kg, Vg, Ks0 + (cur ^ 1) * KV_ELE, Vs0 + (cur ^ 1) * KV_ELE,
                        s0 + (k + 1) * 64, nk2, t);
            CP_COMMIT();
            CP_WAIT1();
        } else {
            CP_WAIT0();
        }
        __syncthreads();
        // scores: 16 pairs x 32 tokens per warp
        {
            uint32_t kbase1 = aK1 + cur * (KV_ELE * 2);
            uint32_t kbase2 = aK2 + cur * (KV_ELE * 2);
            float sa[4][4];
            #pragma unroll
            for (int j = 0; j < 4; j++)
                #pragma unroll
                for (int q = 0; q < 4; q++) sa[j][q] = 0.0f;
            #pragma unroll
            for (int ks = 0; ks < 8; ks++) {
                uint32_t kb1[4], kb2[4];
                LDSM4(kb1, kbase1 + ks * 32);
                LDSM4(kb2, kbase2 + ks * 32);
                MMA16816(sa[0], qa[ks], kb1[0], kb1[1]);
                MMA16816(sa[1], qa[ks], kb1[2], kb1[3]);
                MMA16816(sa[2], qa[ks], kb2[0], kb2[1]);
                MMA16816(sa[3], qa[ks], kb2[2], kb2[3]);
            }
            int r0 = pb + g, r1 = pb + g + 8;
            #pragma unroll
            for (int j = 0; j < 4; j++) {
                int c0 = th * 32 + j * 8 + tc * 2;
                *(float2*)&ss[r0 * 68 + c0] = make_float2(sa[j][0], sa[j][1]);
                *(float2*)&ss[r1 * 68 + c0] = make_float2(sa[j][2], sa[j][3]);
            }
        }
        __syncthreads();
        // parallel online softmax: 4 threads per pair
        {
            int p = t >> 2, sub = t & 3;
            int k0 = sub * 16;
            float mo = m_s[p];
            float cm = -1e30f;
            #pragma unroll 4
            for (int kk = k0; kk < k0 + 16; kk++) {
                float v = (kk < nk) ? ss[p * 68 + kk] : -1e30f;
                cm = fmaxf(cm, v);
            }
            cm = fmaxf(cm, __shfl_xor_sync(0xffffffffu, cm, 1));
            cm = fmaxf(cm, __shfl_xor_sync(0xffffffffu, cm, 2));
            cm = fmaxf(cm, mo);
            float sum = 0.0f;
            #pragma unroll 4
            for (int kk = k0; kk < k0 + 16; kk++) {
                float e = (kk < nk) ? __expf(ss[p * 68 + kk] - cm) : 0.0f;
                Ps[p * 72 + kk] = __float2bfloat16(e);
                sum += e;
            }
            sum += __shfl_xor_sync(0xffffffffu, sum, 1);
            sum += __shfl_xor_sync(0xffffffffu, sum, 2);
            if (sub == 0) {
                float scl = __expf(mo - cm);
                l_s[p] = l_s[p] * scl + sum;
                m_s[p] = cm;
                sc_s[p] = scl;
            }
        }
        __syncthreads();
        // ctx accumulate: rescale then += P @ V
        {
            uint32_t vbase = aV + cur * (KV_ELE * 2);
            float sc0 = sc_s[pb + g], sc1 = sc_s[pb + g + 8];
            #pragma unroll
            for (int nt = 0; nt < 8; nt++) {
                cx[nt][0] *= sc0; cx[nt][1] *= sc0;
                cx[nt][2] *= sc1; cx[nt][3] *= sc1;
            }
            #pragma unroll
            for (int ks = 0; ks < 4; ks++) {
                uint32_t pa[4];
                LDSM4(pa, aP + ks * 32);
                #pragma unroll
                for (int ntp = 0; ntp < 4; ntp++) {
                    uint32_t vb[4];
                    LDSM4T(vb, vbase + ks * 4352 + ntp * 32);
                    MMA16816(cx[ntp * 2 + 0], pa, vb[0], vb[1]);
                    MMA16816(cx[ntp * 2 + 1], pa, vb[2], vb[3]);
                }
            }
        }
        __syncthreads();  // done reading buf cur before it is refilled next iter
    }
    // normalize + store ctx
    int r0 = pb + g, r1 = pb + g + 8;
    float l0 = l_s[r0], l1 = l_s[r1];
    float i0 = (l0 > 0.0f) ? 1.0f / l0 : 0.0f;
    float i1 = (l1 > 0.0f) ? 1.0f / l1 : 0.0f;
    float* cbp = g_ctx[mod] + (size_t)b * NPAIR * DD;
    #pragma unroll
    for (int nt = 0; nt < 8; nt++) {
        int d0 = th * 64 + nt * 8 + tc * 2;
        *(float2*)(cbp + r0 * DD + d0) = make_float2(cx[nt][0] * i0, cx[nt][1] * i0);
        *(float2*)(cbp + r1 * DD + d0) = make_float2(cx[nt][2] * i1, cx[nt][3] * i1);
    }
}

// ---------------- fused: attn-out projection (both mods in parallel) + residual + LN2 + FFN ----------------
__global__ void __launch_bounds__(256) projffn_kernel(
    const float* __restrict__ mwd, const float* __restrict__ mbd,
    const float* __restrict__ owd, const float* __restrict__ obd,
    const float* __restrict__ mwe, const float* __restrict__ mbe,
    const float* __restrict__ owe, const float* __restrict__ obe,
    const float* __restrict__ lng, const float* __restrict__ lnb,
    const float* __restrict__ w1, const float* __restrict__ b1,
    const float* __restrict__ w2, const float* __restrict__ b2) {
    __shared__ float pool[8192];   // t1[2]:0..4096, op[2]:4096..8192; later nl:0..2048, hid:2048..6144
    __shared__ float latv[NLAT * DD];
    int b = blockIdx.x, t = threadIdx.x;
    int half = t >> 7, tt = t & 127;
    const float* mw = half ? mwe : mwd;
    const float* mb = half ? mbe : mbd;
    const float* ow = half ? owe : owd;
    const float* ob = half ? obe : obd;

    // phase 1: t1[half] = ctx[half] @ wv^T + bv
    {
        const float* ctxb = g_ctx[half] + (size_t)b * NPAIR * DD;
        int h = tt >> 5;
        float a1[NLAT];
        float bv = mb[2 * DD + tt];
        #pragma unroll
        for (int i = 0; i < NLAT; i++) a1[i] = bv;
        const float4* wvp = (const float4*)(mw + (size_t)(2 * DD + tt) * DD);
        #pragma unroll 2
        for (int d4 = 0; d4 < DD / 4; d4++) {
            float4 w4 = wvp[d4];
            #pragma unroll
            for (int i = 0; i < NLAT; i++) {
                float4 c4 = *(const float4*)(ctxb + ((i * NH + h) * DD + d4 * 4));
                a1[i] = fmaf(c4.x, w4.x, fmaf(c4.y, w4.y, fmaf(c4.z, w4.z, fmaf(c4.w, w4.w, a1[i]))));
            }
        }
        #pragma unroll
        for (int i = 0; i < NLAT; i++) pool[half * 2048 + i * DD + tt] = a1[i];
    }
    __syncthreads();
    // phase 2: op[half] = t1[half] @ ow^T + ob
    {
        float acc[NLAT];
        float obv = ob[tt];
        #pragma unroll
        for (int i = 0; i < NLAT; i++) acc[i] = obv;
        const float4* owp = (const float4*)(ow + (size_t)tt * DD);
        const float* t1b = pool + half * 2048;
        #pragma unroll 2
        for (int u4 = 0; u4 < DD / 4; u4++) {
            float4 w4 = owp[u4];
            #pragma unroll
            for (int i = 0; i < NLAT; i++) {
                float4 h4 = *(const float4*)(t1b + i * DD + u4 * 4);
                acc[i] = fmaf(h4.x, w4.x, fmaf(h4.y, w4.y, fmaf(h4.z, w4.z, fmaf(h4.w, w4.w, acc[i]))));
            }
        }
        __syncthreads();
        #pragma unroll
        for (int i = 0; i < NLAT; i++) pool[4096 + half * 2048 + i * DD + tt] = acc[i];
    }
    __syncthreads();
    // phase 3: latv = g_lat + op0 + op1
    {
        const float* latb = g_lat + (size_t)b * NLAT * DD;
        #pragma unroll
        for (int j = 0; j < 8; j++) {
            int idx = (half * 8 + j) * DD + tt;
            latv[idx] = latb[idx] + pool[4096 + idx] + pool[4096 + 2048 + idx];
        }
    }
    __syncthreads();
    // phase 4: nl = LN2(latv)
    layernorm_rows(latv, lng, lnb, (float(*)[DD])pool, t, 256);
    __syncthreads();
    // phase 5: hid = relu(nl @ w1^T + b1)   (256 outputs)
    {
        float acc[NLAT];
        float bv = b1[t];
        #pragma unroll
        for (int i = 0; i < NLAT; i++) acc[i] = bv;
        const float4* wp = (const float4*)(w1 + (size_t)t * DD);
        #pragma unroll 2
        for (int d4 = 0; d4 < DD / 4; d4++) {
            float4 w4 = wp[d4];
            #pragma unroll
            for (int i = 0; i < NLAT; i++) {
                float4 n4 = *(const float4*)(pool + i * DD + d4 * 4);
                acc[i] = fmaf(n4.x, w4.x, fmaf(n4.y, w4.y, fmaf(n4.z, w4.z, fmaf(n4.w, w4.w, acc[i]))));
            }
        }
        #pragma unroll
        for (int i = 0; i < NLAT; i++) pool[2048 + i * 256 + t] = fmaxf(acc[i], 0.0f);
    }
    __syncthreads();
    // phase 6: g_lat = latv + hid @ w2^T + b2 (each half covers 8 latent rows)
    {
        float* latb = g_lat + (size_t)b * NLAT * DD;
        float acc[8];
        float bv = b2[tt];
        #pragma unroll
        for (int j = 0; j < 8; j++) acc[j] = bv;
        const float4* wp = (const float4*)(w2 + (size_t)tt * 2 * DD);
        #pragma unroll 2
        for (int u4 = 0; u4 < 2 * DD / 4; u4++) {
            float4 w4 = wp[u4];
            #pragma unroll
            for (int j = 0; j < 8; j++) {
                float4 h4 = *(const float4*)(pool + 2048 + (half * 8 + j) * 256 + u4 * 4);
                acc[j] = fmaf(h4.x, w4.x, fmaf(h4.y, w4.y, fmaf(h4.z, w4.z, fmaf(h4.w, w4.w, acc[j]))));
            }
        }
        #pragma unroll
        for (int j = 0; j < 8; j++) {
            int idx = (half * 8 + j) * DD + tt;
            latb[idx] = latv[idx] + acc[j];
        }
    }
}

// ---------------- head ----------------
__global__ void __launch_bounds__(128) head_kernel(
    const float* __restrict__ w1, const float* __restrict__ b1,
    const float* __restrict__ w2, const float* __restrict__ b2,
    float* __restrict__ out) {
    __shared__ float part[4];
    int b = blockIdx.x, t = threadIdx.x;
    const float4* flat = (const float4*)(g_lat + (size_t)b * NLAT * DD);
    const float4* wp = (const float4*)(w1 + (size_t)t * NLAT * DD);
    float acc = b1[t];
    #pragma unroll 4
    for (int u4 = 0; u4 < NLAT * DD / 4; u4++) {
        float4 f4 = flat[u4];
        float4 w4 = wp[u4];
        acc = fmaf(f4.x, w4.x, fmaf(f4.y, w4.y, fmaf(f4.z, w4.z, fmaf(f4.w, w4.w, acc))));
    }
    float v = fmaxf(acc, 0.0f) * w2[t];
    #pragma unroll
    for (int o = 16; o; o >>= 1) v += __shfl_xor_sync(0xffffffffu, v, o);
    if ((t & 31) == 0) part[t >> 5] = v;
    __syncthreads();
    if (t == 0) {
        float x = part[0] + part[1] + part[2] + part[3] + b2[0];
        out[b] = (x > 20.0f) ? x : log1pf(__expf(x));
    }
}

extern "C" void kernel_launch(void* const* d_in, const int* in_sizes, int n_in,
                              void* d_out, int out_size) {
    const float* drug_k   = (const float*)d_in[0];
    const float* drug_v   = (const float*)d_in[1];
    const float* enz_k    = (const float*)d_in[2];
    const float* enz_v    = (const float*)d_in[3];
    const int*   drug_b   = (const int*)d_in[4];
    const int*   enz_b    = (const int*)d_in[5];
    const float* latents  = (const float*)d_in[6];
    const float* wq_d     = (const float*)d_in[7];
    const float* bq_d     = (const float*)d_in[8];
    const float* wq_e     = (const float*)d_in[9];
    const float* bq_e     = (const float*)d_in[10];
    const float* mha_d_w  = (const float*)d_in[11];
    const float* mha_d_b  = (const float*)d_in[12];
    const float* mha_d_ow = (const float*)d_in[13];
    const float* mha_d_ob = (const float*)d_in[14];
    const float* mha_e_w  = (const float*)d_in[15];
    const float* mha_e_b  = (const float*)d_in[16];
    const float* mha_e_ow = (const float*)d_in[17];
    const float* mha_e_ob = (const float*)d_in[18];
    const float* ln1_g    = (const float*)d_in[19];
    const float* ln1_b    = (const float*)d_in[20];
    const float* ln2_g    = (const float*)d_in[21];
    const float* ln2_b    = (const float*)d_in[22];
    const float* ffn_w1   = (const float*)d_in[23];
    const float* ffn_b1   = (const float*)d_in[24];
    const float* ffn_w2   = (const float*)d_in[25];
    const float* ffn_b2   = (const float*)d_in[26];
    const float* head_w1  = (const float*)d_in[27];
    const float* head_b1  = (const float*)d_in[28];
    const float* head_w2  = (const float*)d_in[29];
    const float* head_b2  = (const float*)d_in[30];
    float* out = (float*)d_out;

    static int s_attr_set = 0;
    if (!s_attr_set) {
        cudaFuncSetAttribute(attn_kernel, cudaFuncAttributeMaxDynamicSharedMemorySize, ATT_BYTES);
        s_attr_set = 1;
    }

    offsets_kernel<<<3, 256>>>(drug_b, enz_b);
    init_lat_kernel<<<(BB * NLAT * DD + 255) / 256, 256>>>(latents);
    cvt_kernel<<<(NE * DD / 4 + 255) / 256, 256>>>(drug_k, drug_v, enz_k, enz_v);

    dim3 gridp(BB, 2);
    for (int l = 0; l < LAYERS; l++) {
        size_t oD = (size_t)l * DD * DD;
        size_t o3D = (size_t)l * 3 * DD * DD;
        size_t o3b = (size_t)l * 3 * DD;
        size_t oV = (size_t)l * DD;
        size_t oF1 = (size_t)l * 2 * DD * DD;
        size_t oF1b = (size_t)l * 2 * DD;

        prep_q_kernel<<<gridp, 128>>>(
            ln1_g + oV, ln1_b + oV,
            wq_d + oD, bq_d + oV, mha_d_w + o3D, mha_d_b + o3b,
            wq_e + oD, bq_e + oV, mha_e_w + o3D, mha_e_b + o3b);

        attn_kernel<<<1024, 256, ATT_BYTES>>>();

        projffn_kernel<<<BB, 256>>>(
            mha_d_w + o3D, mha_d_b + o3b, mha_d_ow + oD, mha_d_ob + oV,
            mha_e_w + o3D, mha_e_b + o3b, mha_e_ow + oD, mha_e_ob + oV,
            ln2_g + oV, ln2_b + oV,
            ffn_w1 + oF1, ffn_b1 + oF1b, ffn_w2 + oF1, ffn_b2 + oV);
    }

    head_kernel<<<BB, 128>>>(head_w1, head_b1, head_w2, head_b2, out);
}

// round 9
// speedup vs baseline: 1.8247x; 1.1757x over previous
#include <cuda_runtime.h>
#include <cuda_bf16.h>
#include <stdint.h>
#include <math.h>

#define BB 512
#define DD 128
#define NLAT 16
#define NH 4
#define HDIM 32
#define ND 25600
#define NE 153600
#define NPAIR 64
#define LAYERS 4

// scratch (static device globals: allowed)
__device__ float g_lat[BB * NLAT * DD];
__device__ __nv_bfloat16 g_qth[2][BB * NPAIR * DD];      // [b][pair*128+t] == [b][i*512+h*128+t]
__device__ __nv_bfloat16 g_ctxh[BB * NLAT * 1024];       // [b][i*1024 + mod*512 + h*128 + d]
__device__ int   g_starts[2][BB + 1];
__device__ __nv_bfloat16 g_dk[ND * DD];
__device__ __nv_bfloat16 g_dv[ND * DD];
__device__ __nv_bfloat16 g_ek[NE * DD];
__device__ __nv_bfloat16 g_ev[NE * DD];
// composed weights
__device__ __nv_bfloat16 g_Aqt[LAYERS * 2 * 512 * 128];  // [(l,mod)][n=h*128+t'][d]
__device__ float g_cq[LAYERS * 2 * 512];
__device__ __nv_bfloat16 g_Bvo[LAYERS * 128 * 1024];     // [l][t'][k=mod*512+h*128+d]
__device__ float g_cvo[LAYERS * 2 * 128];

__device__ __forceinline__ int lb_dev(const int* __restrict__ a, int n, int key) {
    int lo = 0, hi = n;
    while (lo < hi) { int mid = (lo + hi) >> 1; if (a[mid] < key) lo = mid + 1; else hi = mid; }
    return lo;
}

__global__ void offsets_kernel(const int* __restrict__ db, const int* __restrict__ eb) {
    int i = blockIdx.x * blockDim.x + threadIdx.x;
    if (i <= BB) { g_starts[0][i] = lb_dev(db, ND, i); g_starts[1][i] = lb_dev(eb, NE, i); }
}

__global__ void init_lat_kernel(const float* __restrict__ latents) {
    int i = blockIdx.x * blockDim.x + threadIdx.x;
    if (i < BB * NLAT * DD) g_lat[i] = latents[i & (NLAT * DD - 1)];
}

__device__ __forceinline__ uint32_t f2bf2(float x, float y) {
    __nv_bfloat162 h = __floats2bfloat162_rn(x, y);
    return *reinterpret_cast<uint32_t*>(&h);
}

__global__ void cvt_kernel(const float* __restrict__ dk, const float* __restrict__ dv,
                           const float* __restrict__ ek, const float* __restrict__ ev) {
    int i = blockIdx.x * blockDim.x + threadIdx.x;
    int i4 = i * 4;
    if (i4 < ND * DD) {
        float4 a = *(const float4*)(dk + i4);
        float4 b = *(const float4*)(dv + i4);
        *(uint2*)(g_dk + i4) = make_uint2(f2bf2(a.x, a.y), f2bf2(a.z, a.w));
        *(uint2*)(g_dv + i4) = make_uint2(f2bf2(b.x, b.y), f2bf2(b.z, b.w));
    }
    if (i4 < NE * DD) {
        float4 a = *(const float4*)(ek + i4);
        float4 b = *(const float4*)(ev + i4);
        *(uint2*)(g_ek + i4) = make_uint2(f2bf2(a.x, a.y), f2bf2(a.z, a.w));
        *(uint2*)(g_ev + i4) = make_uint2(f2bf2(b.x, b.y), f2bf2(b.z, b.w));
    }
}

// ---------------- weight composition (per replay, 32 blocks, ~5us) ----------------
// smem floats: wq_s 16384 | U_s 4096 | P_s 4096 | V_s 4096 | cb_s 32
#define PC_BYTES ((16384 + 4096 + 4096 + 4096 + 32) * 4)

__global__ void __launch_bounds__(256) precompute_kernel(
    const float* __restrict__ wq_d, const float* __restrict__ bq_d,
    const float* __restrict__ wq_e, const float* __restrict__ bq_e,
    const float* __restrict__ mw_d, const float* __restrict__ mb_d,
    const float* __restrict__ ow_d, const float* __restrict__ ob_d,
    const float* __restrict__ mw_e, const float* __restrict__ mb_e,
    const float* __restrict__ ow_e, const float* __restrict__ ob_e) {
    extern __shared__ float sm[];
    float* wq_s = sm;
    float* U_s  = sm + 16384;
    float* P_s  = sm + 20480;
    float* V_s  = sm + 24576;
    float* cb_s = sm + 28672;
    int m = blockIdx.x, l = blockIdx.y, h = blockIdx.z, t = threadIdx.x;
    const float* wq = (m ? wq_e : wq_d) + (size_t)l * DD * DD;
    const float* bq = (m ? bq_e : bq_d) + l * DD;
    const float* W  = (m ? mw_e : mw_d) + (size_t)l * 3 * DD * DD;
    const float* mb = (m ? mb_e : mb_d) + l * 3 * DD;
    const float* ow = (m ? ow_e : ow_d) + (size_t)l * DD * DD;
    const float* ob = (m ? ob_e : ob_d) + l * DD;

    for (int i = t; i < 4096; i += 256) ((float4*)wq_s)[i] = ((const float4*)wq)[i];
    for (int i = t; i < 1024; i += 256) ((float4*)U_s)[i] = ((const float4*)(W + (size_t)h * 32 * DD))[i];
    __syncthreads();
    // P_s[j][d] = sum_dp U_s[j][dp] * wq_s[dp*128+d]; cb_s[j] = U_h@bq + bqm
    {
        int j = t >> 3, d0 = (t & 7) * 16;
        float acc[16];
        #pragma unroll
        for (int i = 0; i < 16; i++) acc[i] = 0.0f;
        for (int dp = 0; dp < 128; dp++) {
            float u = U_s[j * 128 + dp];
            const float4* wr = (const float4*)(wq_s + dp * 128 + d0);
            #pragma unroll
            for (int q = 0; q < 4; q++) {
                float4 w4 = wr[q];
                acc[q*4+0] = fmaf(u, w4.x, acc[q*4+0]);
                acc[q*4+1] = fmaf(u, w4.y, acc[q*4+1]);
                acc[q*4+2] = fmaf(u, w4.z, acc[q*4+2]);
                acc[q*4+3] = fmaf(u, w4.w, acc[q*4+3]);
            }
        }
        for (int i = 0; i < 16; i++) P_s[j * 128 + d0 + i] = acc[i];
        if ((t & 7) == 0) {
            float s = 0.0f;
            for (int dp = 0; dp < 128; dp++) s += U_s[j * 128 + dp] * bq[dp];
            cb_s[j] = s + mb[h * 32 + j];
        }
    }
    for (int i = t; i < 1024; i += 256) ((float4*)V_s)[i] = ((const float4*)(W + (size_t)(DD + h * 32) * DD))[i];
    __syncthreads();
    // Aqt[h*128+tp][d] = scale * sum_j V_s[j][tp] * P_s[j][d]
    {
        const float scale = 0.17677669529663688f;
        int tp = t >> 1, d0 = (t & 1) * 64;
        float acc[64];
        for (int i = 0; i < 64; i++) acc[i] = 0.0f;
        float cql = 0.0f;
        for (int j = 0; j < 32; j++) {
            float v = V_s[j * 128 + tp];
            const float* pr = P_s + j * 128 + d0;
            #pragma unroll 16
            for (int d = 0; d < 64; d++) acc[d] = fmaf(v, pr[d], acc[d]);
            cql += v * cb_s[j];
        }
        __nv_bfloat16* dst = g_Aqt + ((size_t)(l * 2 + m) * 512 + h * 128 + tp) * 128 + d0;
        for (int d = 0; d < 64; d++) dst[d] = __float2bfloat16(acc[d] * scale);
        if ((t & 1) == 0) g_cq[(l * 2 + m) * 512 + h * 128 + tp] = cql * scale;
    }
    __syncthreads();
    // reuse: U_s <- wv slice; V_s <- ow column slice [tp][j]
    for (int i = t; i < 1024; i += 256) ((float4*)U_s)[i] = ((const float4*)(W + (size_t)(2 * DD + h * 32) * DD))[i];
    for (int i = t; i < 1024; i += 256)
        ((float4*)V_s)[i] = *(const float4*)(ow + (size_t)(i >> 3) * DD + h * 32 + (i & 7) * 4);
    __syncthreads();
    // Bvo[tp][m*512+h*128+d] = sum_j wv[j][d] * ow[tp][h*32+j]
    {
        int tp = t >> 1, d0 = (t & 1) * 64;
        float acc[64];
        for (int i = 0; i < 64; i++) acc[i] = 0.0f;
        for (int j = 0; j < 32; j++) {
            float o = V_s[tp * 32 + j];
            const float* wr = U_s + j * 128 + d0;
            #pragma unroll 16
            for (int d = 0; d < 64; d++) acc[d] = fmaf(o, wr[d], acc[d]);
        }
        __nv_bfloat16* dst = g_Bvo + (size_t)l * DD * 1024 + (size_t)tp * 1024 + m * 512 + h * 128 + d0;
        for (int d = 0; d < 64; d++) dst[d] = __float2bfloat16(acc[d]);
    }
    if (h == 0 && t < 128) {
        float s = ob[t];
        const float* bv = mb + 2 * DD;
        for (int u = 0; u < 128; u++) s += ow[(size_t)t * 128 + u] * bv[u];
        g_cvo[(l * 2 + m) * 128 + t] = s;
    }
}

// ---------------- common helpers ----------------
__device__ __forceinline__ void layernorm_rows(const float* __restrict__ src,
                                               const float* __restrict__ g,
                                               const float* __restrict__ bta,
                                               float (*dst)[DD], int t, int nthr) {
    int warp = t >> 5, lane = t & 31, nw = nthr >> 5;
    for (int r = warp; r < NLAT; r += nw) {
        float4 v = ((const float4*)(src + r * DD))[lane];
        float s = v.x + v.y + v.z + v.w;
        #pragma unroll
        for (int o = 16; o; o >>= 1) s += __shfl_xor_sync(0xffffffffu, s, o);
        float mean = s * (1.0f / DD);
        float dx = v.x - mean, dy = v.y - mean, dz = v.z - mean, dw = v.w - mean;
        float q = dx * dx + dy * dy + dz * dz + dw * dw;
        #pragma unroll
        for (int o = 16; o; o >>= 1) q += __shfl_xor_sync(0xffffffffu, q, o);
        float rstd = rsqrtf(q * (1.0f / DD) + 1e-5f);
        int c = lane * 4;
        dst[r][c + 0] = dx * rstd * g[c + 0] + bta[c + 0];
        dst[r][c + 1] = dy * rstd * g[c + 1] + bta[c + 1];
        dst[r][c + 2] = dz * rstd * g[c + 2] + bta[c + 2];
        dst[r][c + 3] = dw * rstd * g[c + 3] + bta[c + 3];
    }
}

__device__ __forceinline__ uint32_t s2u(const void* p) {
    return (uint32_t)__cvta_generic_to_shared(p);
}

#define LDSM4(R, addr) asm volatile( \
    "ldmatrix.sync.aligned.m8n8.x4.shared.b16 {%0,%1,%2,%3},[%4];" \
    : "=r"((R)[0]), "=r"((R)[1]), "=r"((R)[2]), "=r"((R)[3]) : "r"(addr))
#define LDSM4T(R, addr) asm volatile( \
    "ldmatrix.sync.aligned.m8n8.x4.trans.shared.b16 {%0,%1,%2,%3},[%4];" \
    : "=r"((R)[0]), "=r"((R)[1]), "=r"((R)[2]), "=r"((R)[3]) : "r"(addr))
#define MMA16816(D, A, B0, B1) asm volatile( \
    "mma.sync.aligned.m16n8k16.row.col.f32.bf16.bf16.f32 " \
    "{%0,%1,%2,%3},{%4,%5,%6,%7},{%8,%9},{%0,%1,%2,%3};" \
    : "+f"((D)[0]), "+f"((D)[1]), "+f"((D)[2]), "+f"((D)[3]) \
    : "r"((A)[0]), "r"((A)[1]), "r"((A)[2]), "r"((A)[3]), "r"(B0), "r"(B1))
#define CP16(dst, src) asm volatile("cp.async.cg.shared.global [%0], [%1], 16;\n" :: "r"(dst), "l"(src))
#define CP_COMMIT() asm volatile("cp.async.commit_group;\n" ::: "memory")
#define CP_WAIT1() asm volatile("cp.async.wait_group 1;\n" ::: "memory")
#define CP_WAIT0() asm volatile("cp.async.wait_group 0;\n" ::: "memory")

// ---------------- prep_q: LN + single bf16 GEMM [16,128]@[128,512] ----------------
// grid (BB, 2), 256 threads
__global__ void __launch_bounds__(256) prep_q_kernel(int layer,
    const float* __restrict__ lng, const float* __restrict__ lnb) {
    __shared__ float nlf[NLAT][DD];
    __shared__ __nv_bfloat16 nlh[NLAT][136];
    int b = blockIdx.x, mod = blockIdx.y, t = threadIdx.x;
    layernorm_rows(g_lat + (size_t)b * NLAT * DD, lng, lnb, nlf, t, 256);
    __syncthreads();
    for (int i = t; i < NLAT * DD / 2; i += 256) {
        int r = i >> 6, c = (i & 63) * 2;
        *(uint32_t*)&nlh[r][c] = f2bf2(nlf[r][c], nlf[r][c + 1]);
    }
    __syncthreads();
    int w = t >> 5, lane = t & 31, g = lane >> 2, tc = lane & 3;
    const __nv_bfloat16* Aq = g_Aqt + (size_t)(layer * 2 + mod) * 512 * 128;
    const float* cq = g_cq + (layer * 2 + mod) * 512;
    uint32_t aAddr = s2u(&nlh[lane & 15][(lane >> 4) * 8]);
    float acc[8][4];
    #pragma unroll
    for (int i = 0; i < 8; i++)
        #pragma unroll
        for (int j = 0; j < 4; j++) acc[i][j] = 0.0f;
    #pragma unroll
    for (int ks = 0; ks < 8; ks++) {
        uint32_t aA[4];
        LDSM4(aA, aAddr + ks * 32);
        #pragma unroll
        for (int nt = 0; nt < 8; nt++) {
            int n = w * 64 + nt * 8 + g;
            uint32_t b0 = *(const uint32_t*)(Aq + (size_t)n * 128 + ks * 16 + tc * 2);
            uint32_t b1 = *(const uint32_t*)(Aq + (size_t)n * 128 + ks * 16 + tc * 2 + 8);
            MMA16816(acc[nt], aA, b0, b1);
        }
    }
    __nv_bfloat16* qtb = g_qth[mod] + (size_t)b * NPAIR * DD;
    #pragma unroll
    for (int nt = 0; nt < 8; nt++) {
        int n0 = w * 64 + nt * 8 + tc * 2;
        float c0v = cq[n0], c1v = cq[n0 + 1];
        *(uint32_t*)(qtb + (size_t)g * 512 + n0)       = f2bf2(acc[nt][0] + c0v, acc[nt][1] + c1v);
        *(uint32_t*)(qtb + (size_t)(g + 8) * 512 + n0) = f2bf2(acc[nt][2] + c0v, acc[nt][3] + c1v);
    }
}

// ---------------- attention (tensor cores, cp.async double-buffered) ----------------
#define KV_ELE (64 * 136)
#define ATT_BYTES (4 * KV_ELE * 2 + 64 * 72 * 2 + 64 * 68 * 4 + 3 * 64 * 4)

__device__ __forceinline__ void issue_chunk(const __nv_bfloat16* __restrict__ Kg,
                                            const __nv_bfloat16* __restrict__ Vg,
                                            __nv_bfloat16* Ksb, __nv_bfloat16* Vsb,
                                            int row0, int nk, int t) {
    #pragma unroll
    for (int i = t; i < 1024; i += 256) {
        int r = i >> 4, seg = (i & 15) * 8;
        if (r < nk) {
            CP16(s2u(Ksb + r * 136 + seg), Kg + (size_t)(row0 + r) * DD + seg);
            CP16(s2u(Vsb + r * 136 + seg), Vg + (size_t)(row0 + r) * DD + seg);
        }
    }
}

// grid 1024: bid<512 -> enzyme first, else drug. 256 threads.
__global__ void __launch_bounds__(256, 2) attn_kernel() {
    extern __shared__ char smraw[];
    __nv_bfloat16* Ks0 = (__nv_bfloat16*)smraw;
    __nv_bfloat16* Vs0 = Ks0 + 2 * KV_ELE;
    __nv_bfloat16* Ps  = Vs0 + 2 * KV_ELE;
    float* ss  = (float*)(Ps + 64 * 72);
    float* m_s = ss + 64 * 68;
    float* l_s = m_s + 64;
    float* sc_s = l_s + 64;

    int bid = blockIdx.x, t = threadIdx.x;
    int mod = (bid < 512) ? 1 : 0;
    int b = bid & 511;
    const __nv_bfloat16* Kg = mod ? g_ek : g_dk;
    const __nv_bfloat16* Vg = mod ? g_ev : g_dv;
    int w = t >> 5, lane = t & 31;
    int g = lane >> 2, tc = lane & 3;
    int s0 = g_starts[mod][b];
    int cnt = g_starts[mod][b + 1] - s0;

    int pb = (w & 3) * 16;
    int th = w >> 2;

    for (int i = t; i < (4 * KV_ELE * 2) / 16; i += 256)
        ((uint4*)smraw)[i] = make_uint4(0, 0, 0, 0);

    uint32_t qa[8][4];
    {
        const __nv_bfloat16* qtb = g_qth[mod] + (size_t)b * NPAIR * DD;
        int r0 = pb + g, r1 = pb + g + 8;
        #pragma unroll
        for (int ks = 0; ks < 8; ks++) {
            int c0 = ks * 16 + tc * 2;
            qa[ks][0] = *(const uint32_t*)(qtb + (size_t)r0 * DD + c0);
            qa[ks][1] = *(const uint32_t*)(qtb + (size_t)r1 * DD + c0);
            qa[ks][2] = *(const uint32_t*)(qtb + (size_t)r0 * DD + c0 + 8);
            qa[ks][3] = *(const uint32_t*)(qtb + (size_t)r1 * DD + c0 + 8);
        }
    }
    if (t < 64) { m_s[t] = -1e30f; l_s[t] = 0.0f; }

    float cx[8][4];
    #pragma unroll
    for (int i = 0; i < 8; i++)
        #pragma unroll
        for (int j = 0; j < 4; j++) cx[i][j] = 0.0f;

    uint32_t aK1 = s2u(Ks0 + (th * 32 + ((lane >> 4) << 3) + (lane & 7)) * 136 + ((lane >> 3) & 1) * 8);
    uint32_t aK2 = aK1 + 16 * 136 * 2;
    uint32_t aP  = s2u(Ps + (pb + (lane & 15)) * 72 + (lane >> 4) * 8);
    uint32_t aV  = s2u(Vs0 + (lane & 15) * 136 + th * 64 + (lane >> 4) * 8);

    int nchunks = (cnt + 63) >> 6;
    __syncthreads();
    if (nchunks > 0) {
        issue_chunk(Kg, Vg, Ks0, Vs0, s0, min(64, cnt), t);
        CP_COMMIT();
    }

    for (int k = 0; k < nchunks; k++) {
        int cur = k & 1;
        int nk = min(64, cnt - k * 64);
        if (k + 1 < nchunks) {
            int nk2 = min(64, cnt - (k + 1) * 64);
            issue_chunk(Kg, Vg, Ks0 + (cur ^ 1) * KV_ELE, Vs0 + (cur ^ 1) * KV_ELE,
                        s0 + (k + 1) * 64, nk2, t);
            CP_COMMIT();
            CP_WAIT1();
        } else {
            CP_WAIT0();
        }
        __syncthreads();
        {
            uint32_t kbase1 = aK1 + cur * (KV_ELE * 2);
            uint32_t kbase2 = aK2 + cur * (KV_ELE * 2);
            float sa[4][4];
            #pragma unroll
            for (int j = 0; j < 4; j++)
                #pragma unroll
                for (int q = 0; q < 4; q++) sa[j][q] = 0.0f;
            #pragma unroll
            for (int ks = 0; ks < 8; ks++) {
                uint32_t kb1[4], kb2[4];
                LDSM4(kb1, kbase1 + ks * 32);
                LDSM4(kb2, kbase2 + ks * 32);
                MMA16816(sa[0], qa[ks], kb1[0], kb1[1]);
                MMA16816(sa[1], qa[ks], kb1[2], kb1[3]);
                MMA16816(sa[2], qa[ks], kb2[0], kb2[1]);
                MMA16816(sa[3], qa[ks], kb2[2], kb2[3]);
            }
            int r0 = pb + g, r1 = pb + g + 8;
            #pragma unroll
            for (int j = 0; j < 4; j++) {
                int c0 = th * 32 + j * 8 + tc * 2;
                *(float2*)&ss[r0 * 68 + c0] = make_float2(sa[j][0], sa[j][1]);
                *(float2*)&ss[r1 * 68 + c0] = make_float2(sa[j][2], sa[j][3]);
            }
        }
        __syncthreads();
        {
            int p = t >> 2, sub = t & 3;
            int k0 = sub * 16;
            float mo = m_s[p];
            float cm = -1e30f;
            #pragma unroll 4
            for (int kk = k0; kk < k0 + 16; kk++) {
                float v = (kk < nk) ? ss[p * 68 + kk] : -1e30f;
                cm = fmaxf(cm, v);
            }
            cm = fmaxf(cm, __shfl_xor_sync(0xffffffffu, cm, 1));
            cm = fmaxf(cm, __shfl_xor_sync(0xffffffffu, cm, 2));
            cm = fmaxf(cm, mo);
            float sum = 0.0f;
            #pragma unroll 4
            for (int kk = k0; kk < k0 + 16; kk++) {
                float e = (kk < nk) ? __expf(ss[p * 68 + kk] - cm) : 0.0f;
                Ps[p * 72 + kk] = __float2bfloat16(e);
                sum += e;
            }
            sum += __shfl_xor_sync(0xffffffffu, sum, 1);
            sum += __shfl_xor_sync(0xffffffffu, sum, 2);
            if (sub == 0) {
                float scl = __expf(mo - cm);
                l_s[p] = l_s[p] * scl + sum;
                m_s[p] = cm;
                sc_s[p] = scl;
            }
        }
        __syncthreads();
        {
            uint32_t vbase = aV + cur * (KV_ELE * 2);
            float sc0 = sc_s[pb + g], sc1 = sc_s[pb + g + 8];
            #pragma unroll
            for (int nt = 0; nt < 8; nt++) {
                cx[nt][0] *= sc0; cx[nt][1] *= sc0;
                cx[nt][2] *= sc1; cx[nt][3] *= sc1;
            }
            #pragma unroll
            for (int ks = 0; ks < 4; ks++) {
                uint32_t pa[4];
                LDSM4(pa, aP + ks * 32);
                #pragma unroll
                for (int ntp = 0; ntp < 4; ntp++) {
                    uint32_t vb[4];
                    LDSM4T(vb, vbase + ks * 4352 + ntp * 32);
                    MMA16816(cx[ntp * 2 + 0], pa, vb[0], vb[1]);
                    MMA16816(cx[ntp * 2 + 1], pa, vb[2], vb[3]);
                }
            }
        }
        __syncthreads();
    }
    // normalize + store ctx (bf16, GEMM-ready layout)
    int r0 = pb + g, r1 = pb + g + 8;
    float l0 = l_s[r0], l1 = l_s[r1];
    float i0 = (l0 > 0.0f) ? 1.0f / l0 : 0.0f;
    float i1 = (l1 > 0.0f) ? 1.0f / l1 : 0.0f;
    __nv_bfloat16* cbp = g_ctxh + (size_t)b * 16384;
    int base0 = (r0 >> 2) * 1024 + mod * 512 + (r0 & 3) * 128;
    int base1 = (r1 >> 2) * 1024 + mod * 512 + (r1 & 3) * 128;
    #pragma unroll
    for (int nt = 0; nt < 8; nt++) {
        int d0 = th * 64 + nt * 8 + tc * 2;
        *(uint32_t*)(cbp + base0 + d0) = f2bf2(cx[nt][0] * i0, cx[nt][1] * i0);
        *(uint32_t*)(cbp + base1 + d0) = f2bf2(cx[nt][2] * i1, cx[nt][3] * i1);
    }
}

// ---------------- fused: VO GEMM (bf16 TC) + residual + LN2 + FFN (fp32) ----------------
// dyn smem: union( ctxs [16][1032] bf16 = 33024 B, pool: nl 16*128 f32 + hid 16*256 f32 = 24576 B ) + latv 8192 B
#define PF_BYTES (33024 + 8192)

__global__ void __launch_bounds__(256) projffn_kernel(int layer,
    const float* __restrict__ lng, const float* __restrict__ lnb,
    const float* __restrict__ w1, const float* __restrict__ b1,
    const float* __restrict__ w2, const float* __restrict__ b2) {
    extern __shared__ char dsm[];
    __nv_bfloat16* ctxs = (__nv_bfloat16*)dsm;      // [16][1032]
    float* pool = (float*)dsm;                       // after GEMM: nl @0, hid @2048 floats
    float* latv = (float*)(dsm + 33024);             // [16][128]
    int b = blockIdx.x, t = threadIdx.x;
    int w = t >> 5, lane = t & 31, g = lane >> 2, tc = lane & 3;
    int half = t >> 7, tt = t & 127;

    {
        const uint4* src = (const uint4*)(g_ctxh + (size_t)b * 16384);
        for (int i = t; i < 2048; i += 256) {
            int r = i >> 7, c8 = i & 127;
            *(uint4*)(ctxs + r * 1032 + c8 * 8) = src[i];
        }
        const float4* lsrc = (const float4*)(g_lat + (size_t)b * NLAT * DD);
        for (int i = t; i < 512; i += 256) ((float4*)latv)[i] = lsrc[i];
    }
    __syncthreads();
    // phase A: o[16][128] = ctxs[16][1024] @ Bvo + cvo; accumulate into latv
    {
        const __nv_bfloat16* Bvop = g_Bvo + (size_t)layer * DD * 1024;
        const float* cvo0 = g_cvo + (layer * 2 + 0) * 128;
        const float* cvo1 = g_cvo + (layer * 2 + 1) * 128;
        uint32_t aC = s2u(ctxs + (lane & 15) * 1032 + (lane >> 4) * 8);
        float acc[2][4];
        #pragma unroll
        for (int i = 0; i < 2; i++)
            #pragma unroll
            for (int j = 0; j < 4; j++) acc[i][j] = 0.0f;
        #pragma unroll 4
        for (int ks = 0; ks < 64; ks++) {
            uint32_t aA[4];
            LDSM4(aA, aC + ks * 32);
            #pragma unroll
            for (int nt = 0; nt < 2; nt++) {
                int n = w * 16 + nt * 8 + g;
                uint32_t b0 = *(const uint32_t*)(Bvop + (size_t)n * 1024 + ks * 16 + tc * 2);
                uint32_t b1 = *(const uint32_t*)(Bvop + (size_t)n * 1024 + ks * 16 + tc * 2 + 8);
                MMA16816(acc[nt], aA, b0, b1);
            }
        }
        __syncthreads();   // all ctxs reads done before any pool overlay writes later
        #pragma unroll
        for (int nt = 0; nt < 2; nt++) {
            int n0 = w * 16 + nt * 8 + tc * 2;
            float c0v = cvo0[n0] + cvo1[n0];
            float c1v = cvo0[n0 + 1] + cvo1[n0 + 1];
            latv[g * 128 + n0]           += acc[nt][0] + c0v;
            latv[g * 128 + n0 + 1]       += acc[nt][1] + c1v;
            latv[(g + 8) * 128 + n0]     += acc[nt][2] + c0v;
            latv[(g + 8) * 128 + n0 + 1] += acc[nt][3] + c1v;
        }
    }
    __syncthreads();
    layernorm_rows(latv, lng, lnb, (float(*)[DD])pool, t, 256);
    __syncthreads();
    // FFN1: hid = relu(nl @ w1^T + b1)
    {
        float acc[NLAT];
        float bv = b1[t];
        #pragma unroll
        for (int i = 0; i < NLAT; i++) acc[i] = bv;
        const float4* wp = (const float4*)(w1 + (size_t)t * DD);
        #pragma unroll 2
        for (int d4 = 0; d4 < DD / 4; d4++) {
            float4 w4 = wp[d4];
            #pragma unroll
            for (int i = 0; i < NLAT; i++) {
                float4 n4 = *(const float4*)(pool + i * DD + d4 * 4);
                acc[i] = fmaf(n4.x, w4.x, fmaf(n4.y, w4.y, fmaf(n4.z, w4.z, fmaf(n4.w, w4.w, acc[i]))));
            }
        }
        __syncthreads();
        #pragma unroll
        for (int i = 0; i < NLAT; i++) pool[2048 + i * 256 + t] = fmaxf(acc[i], 0.0f);
    }
    __syncthreads();
    // FFN2 + residual -> g_lat
    {
        float* latb = g_lat + (size_t)b * NLAT * DD;
        float acc[8];
        float bv = b2[tt];
        #pragma unroll
        for (int j = 0; j < 8; j++) acc[j] = bv;
        const float4* wp = (const float4*)(w2 + (size_t)tt * 2 * DD);
        #pragma unroll 2
        for (int u4 = 0; u4 < 2 * DD / 4; u4++) {
            float4 w4 = wp[u4];
            #pragma unroll
            for (int j = 0; j < 8; j++) {
                float4 h4 = *(const float4*)(pool + 2048 + (half * 8 + j) * 256 + u4 * 4);
                acc[j] = fmaf(h4.x, w4.x, fmaf(h4.y, w4.y, fmaf(h4.z, w4.z, fmaf(h4.w, w4.w, acc[j]))));
            }
        }
        #pragma unroll
        for (int j = 0; j < 8; j++) {
            int idx = (half * 8 + j) * DD + tt;
            latb[idx] = latv[idx] + acc[j];
        }
    }
}

// ---------------- head ----------------
__global__ void __launch_bounds__(128) head_kernel(
    const float* __restrict__ w1, const float* __restrict__ b1,
    const float* __restrict__ w2, const float* __restrict__ b2,
    float* __restrict__ out) {
    __shared__ float part[4];
    int b = blockIdx.x, t = threadIdx.x;
    const float4* flat = (const float4*)(g_lat + (size_t)b * NLAT * DD);
    const float4* wp = (const float4*)(w1 + (size_t)t * NLAT * DD);
    float acc = b1[t];
    #pragma unroll 4
    for (int u4 = 0; u4 < NLAT * DD / 4; u4++) {
        float4 f4 = flat[u4];
        float4 w4 = wp[u4];
        acc = fmaf(f4.x, w4.x, fmaf(f4.y, w4.y, fmaf(f4.z, w4.z, fmaf(f4.w, w4.w, acc))));
    }
    float v = fmaxf(acc, 0.0f) * w2[t];
    #pragma unroll
    for (int o = 16; o; o >>= 1) v += __shfl_xor_sync(0xffffffffu, v, o);
    if ((t & 31) == 0) part[t >> 5] = v;
    __syncthreads();
    if (t == 0) {
        float x = part[0] + part[1] + part[2] + part[3] + b2[0];
        out[b] = (x > 20.0f) ? x : log1pf(__expf(x));
    }
}

extern "C" void kernel_launch(void* const* d_in, const int* in_sizes, int n_in,
                              void* d_out, int out_size) {
    const float* drug_k   = (const float*)d_in[0];
    const float* drug_v   = (const float*)d_in[1];
    const float* enz_k    = (const float*)d_in[2];
    const float* enz_v    = (const float*)d_in[3];
    const int*   drug_b   = (const int*)d_in[4];
    const int*   enz_b    = (const int*)d_in[5];
    const float* latents  = (const float*)d_in[6];
    const float* wq_d     = (const float*)d_in[7];
    const float* bq_d     = (const float*)d_in[8];
    const float* wq_e     = (const float*)d_in[9];
    const float* bq_e     = (const float*)d_in[10];
    const float* mha_d_w  = (const float*)d_in[11];
    const float* mha_d_b  = (const float*)d_in[12];
    const float* mha_d_ow = (const float*)d_in[13];
    const float* mha_d_ob = (const float*)d_in[14];
    const float* mha_e_w  = (const float*)d_in[15];
    const float* mha_e_b  = (const float*)d_in[16];
    const float* mha_e_ow = (const float*)d_in[17];
    const float* mha_e_ob = (const float*)d_in[18];
    const float* ln1_g    = (const float*)d_in[19];
    const float* ln1_b    = (const float*)d_in[20];
    const float* ln2_g    = (const float*)d_in[21];
    const float* ln2_b    = (const float*)d_in[22];
    const float* ffn_w1   = (const float*)d_in[23];
    const float* ffn_b1   = (const float*)d_in[24];
    const float* ffn_w2   = (const float*)d_in[25];
    const float* ffn_b2   = (const float*)d_in[26];
    const float* head_w1  = (const float*)d_in[27];
    const float* head_b1  = (const float*)d_in[28];
    const float* head_w2  = (const float*)d_in[29];
    const float* head_b2  = (const float*)d_in[30];
    float* out = (float*)d_out;

    static int s_attr_set = 0;
    if (!s_attr_set) {
        cudaFuncSetAttribute(attn_kernel, cudaFuncAttributeMaxDynamicSharedMemorySize, ATT_BYTES);
        cudaFuncSetAttribute(precompute_kernel, cudaFuncAttributeMaxDynamicSharedMemorySize, PC_BYTES);
        s_attr_set = 1;
    }

    offsets_kernel<<<3, 256>>>(drug_b, enz_b);
    init_lat_kernel<<<(BB * NLAT * DD + 255) / 256, 256>>>(latents);
    cvt_kernel<<<(NE * DD / 4 + 255) / 256, 256>>>(drug_k, drug_v, enz_k, enz_v);
    precompute_kernel<<<dim3(2, LAYERS, 4), 256, PC_BYTES>>>(
        wq_d, bq_d, wq_e, bq_e,
        mha_d_w, mha_d_b, mha_d_ow, mha_d_ob,
        mha_e_w, mha_e_b, mha_e_ow, mha_e_ob);

    dim3 gridp(BB, 2);
    for (int l = 0; l < LAYERS; l++) {
        size_t oV = (size_t)l * DD;
        size_t oF1 = (size_t)l * 2 * DD * DD;
        size_t oF1b = (size_t)l * 2 * DD;

        prep_q_kernel<<<gridp, 256>>>(l, ln1_g + oV, ln1_b + oV);
        attn_kernel<<<1024, 256, ATT_BYTES>>>();
        projffn_kernel<<<BB, 256, PF_BYTES>>>(l,
            ln2_g + oV, ln2_b + oV,
            ffn_w1 + oF1, ffn_b1 + oF1b, ffn_w2 + oF1, ffn_b2 + oV);
    }

    head_kernel<<<BB, 128>>>(head_w1, head_b1, head_w2, head_b2, out);
}

// round 10
// speedup vs baseline: 1.9630x; 1.0758x over previous
#include <cuda_runtime.h>
#include <cuda_bf16.h>
#include <stdint.h>
#include <math.h>

#define BB 512
#define DD 128
#define NLAT 16
#define NH 4
#define HDIM 32
#define ND 25600
#define NE 153600
#define NPAIR 64
#define LAYERS 4

// scratch (static device globals: allowed)
__device__ float g_lat[BB * NLAT * DD];
__device__ __nv_bfloat16 g_qth[2][BB * NPAIR * DD];      // [b][pair*128+t] == [b][i*512+h*128+t]
__device__ __nv_bfloat16 g_ctxh[BB * NLAT * 1024];       // [b][i*1024 + mod*512 + h*128 + d]
__device__ int   g_starts[2][BB + 1];
__device__ __nv_bfloat16 g_dk[ND * DD];
__device__ __nv_bfloat16 g_dv[ND * DD];
__device__ __nv_bfloat16 g_ek[NE * DD];
__device__ __nv_bfloat16 g_ev[NE * DD];
// composed weights
__device__ __nv_bfloat16 g_Aqt[LAYERS * 2 * 512 * 128];  // [(l,mod)][n=h*128+t'][d]
__device__ float g_cq[LAYERS * 2 * 512];
__device__ __nv_bfloat16 g_Bvo[LAYERS * 128 * 1024];     // [l][t'][k=mod*512+h*128+d]
__device__ float g_cvo[LAYERS * 2 * 128];
// precompute scratch: P[c][j][d], cb[c][j], c = (l*2+m)*4+h
__device__ float g_P[32 * 32 * 128];
__device__ float g_cb[32 * 32];

__device__ __forceinline__ int lb_dev(const int* __restrict__ a, int n, int key) {
    int lo = 0, hi = n;
    while (lo < hi) { int mid = (lo + hi) >> 1; if (a[mid] < key) lo = mid + 1; else hi = mid; }
    return lo;
}

__global__ void offsets_kernel(const int* __restrict__ db, const int* __restrict__ eb) {
    int i = blockIdx.x * blockDim.x + threadIdx.x;
    if (i <= BB) { g_starts[0][i] = lb_dev(db, ND, i); g_starts[1][i] = lb_dev(eb, NE, i); }
}

__global__ void init_lat_kernel(const float* __restrict__ latents) {
    int i = blockIdx.x * blockDim.x + threadIdx.x;
    if (i < BB * NLAT * DD) g_lat[i] = latents[i & (NLAT * DD - 1)];
}

__device__ __forceinline__ uint32_t f2bf2(float x, float y) {
    __nv_bfloat162 h = __floats2bfloat162_rn(x, y);
    return *reinterpret_cast<uint32_t*>(&h);
}

__global__ void cvt_kernel(const float* __restrict__ dk, const float* __restrict__ dv,
                           const float* __restrict__ ek, const float* __restrict__ ev) {
    int i = blockIdx.x * blockDim.x + threadIdx.x;
    int i4 = i * 4;
    if (i4 < ND * DD) {
        float4 a = *(const float4*)(dk + i4);
        float4 b = *(const float4*)(dv + i4);
        *(uint2*)(g_dk + i4) = make_uint2(f2bf2(a.x, a.y), f2bf2(a.z, a.w));
        *(uint2*)(g_dv + i4) = make_uint2(f2bf2(b.x, b.y), f2bf2(b.z, b.w));
    }
    if (i4 < NE * DD) {
        float4 a = *(const float4*)(ek + i4);
        float4 b = *(const float4*)(ev + i4);
        *(uint2*)(g_ek + i4) = make_uint2(f2bf2(a.x, a.y), f2bf2(a.z, a.w));
        *(uint2*)(g_ev + i4) = make_uint2(f2bf2(b.x, b.y), f2bf2(b.z, b.w));
    }
}

// ---------------- weight composition: 4 well-parallelized kernels ----------------
// c = (l*2+m)*4+h throughout.

// P[c][j][d] = sum_dp U_h[j][dp] * wq[dp][d]; cb[c][j] = U_h@bq + mb_q[h*32+j]
// grid (32, 4=dsplit), 256 thr; 4 outputs/thread
__global__ void __launch_bounds__(256) pc_P_kernel(
    const float* __restrict__ wq_d, const float* __restrict__ bq_d,
    const float* __restrict__ wq_e, const float* __restrict__ bq_e,
    const float* __restrict__ mw_d, const float* __restrict__ mb_d,
    const float* __restrict__ mw_e, const float* __restrict__ mb_e) {
    __shared__ float U_s[32 * 128];
    int c = blockIdx.x, ds = blockIdx.y, t = threadIdx.x;
    int h = c & 3, m = (c >> 2) & 1, l = c >> 3;
    const float* wq = (m ? wq_e : wq_d) + (size_t)l * DD * DD;
    const float* W  = (m ? mw_e : mw_d) + (size_t)l * 3 * DD * DD;
    for (int i = t; i < 1024; i += 256)
        ((float4*)U_s)[i] = ((const float4*)(W + (size_t)h * 32 * DD))[i];
    __syncthreads();
    int j = t >> 3, d0 = ds * 32 + (t & 7) * 4;
    float a0 = 0, a1 = 0, a2 = 0, a3 = 0;
    #pragma unroll 4
    for (int dp = 0; dp < 128; dp++) {
        float u = U_s[j * 128 + dp];
        float4 w4 = *(const float4*)(wq + (size_t)dp * 128 + d0);
        a0 = fmaf(u, w4.x, a0); a1 = fmaf(u, w4.y, a1);
        a2 = fmaf(u, w4.z, a2); a3 = fmaf(u, w4.w, a3);
    }
    *(float4*)(g_P + (size_t)c * 4096 + j * 128 + d0) = make_float4(a0, a1, a2, a3);
    if (ds == 0 && t < 32) {
        const float* bq = (m ? bq_e : bq_d) + l * DD;
        const float* mb = (m ? mb_e : mb_d) + l * 3 * DD;
        float s = 0.0f;
        for (int dp = 0; dp < 128; dp++) s += U_s[t * 128 + dp] * bq[dp];
        g_cb[c * 32 + t] = s + mb[h * 32 + t];
    }
}

// Aqt[(l,m)][h*128+tp][d] = scale * sum_j wk[j][tp] * P[c][j][d]; cq likewise from cb
// grid (32, 4=tpsplit), 256 thr; 16 outputs/thread
__global__ void __launch_bounds__(256) pc_Aq_kernel(
    const float* __restrict__ mw_d, const float* __restrict__ mw_e) {
    __shared__ float P_s[32 * 128];
    __shared__ float V_s[32 * 32];   // [j][tpl]
    __shared__ float cb_s[32];
    int c = blockIdx.x, ts = blockIdx.y, t = threadIdx.x;
    int h = c & 3, m = (c >> 2) & 1, l = c >> 3;
    const float* W = (m ? mw_e : mw_d) + (size_t)l * 3 * DD * DD;
    const float* wk = W + (size_t)(DD + h * 32) * DD;
    for (int i = t; i < 1024; i += 256)
        ((float4*)P_s)[i] = ((const float4*)(g_P + (size_t)c * 4096))[i];
    for (int i = t; i < 1024; i += 256) {
        int j = i >> 5, tpl = i & 31;
        V_s[j * 32 + tpl] = wk[(size_t)j * 128 + ts * 32 + tpl];
    }
    if (t < 32) cb_s[t] = g_cb[c * 32 + t];
    __syncthreads();
    const float scale = 0.17677669529663688f;
    int tpl = t >> 3, d0 = (t & 7) * 16;
    float acc[16];
    #pragma unroll
    for (int i = 0; i < 16; i++) acc[i] = 0.0f;
    float cq = 0.0f;
    for (int j = 0; j < 32; j++) {
        float v = V_s[j * 32 + tpl];
        const float4* pr = (const float4*)(P_s + j * 128 + d0);
        #pragma unroll
        for (int q = 0; q < 4; q++) {
            float4 p4 = pr[q];
            acc[q*4+0] = fmaf(v, p4.x, acc[q*4+0]);
            acc[q*4+1] = fmaf(v, p4.y, acc[q*4+1]);
            acc[q*4+2] = fmaf(v, p4.z, acc[q*4+2]);
            acc[q*4+3] = fmaf(v, p4.w, acc[q*4+3]);
        }
        cq += v * cb_s[j];
    }
    int tp = ts * 32 + tpl;
    __nv_bfloat16* dst = g_Aqt + ((size_t)(l * 2 + m) * 512 + h * 128 + tp) * 128 + d0;
    #pragma unroll
    for (int q = 0; q < 8; q++)
        *(uint32_t*)(dst + q * 2) = f2bf2(acc[q*2] * scale, acc[q*2+1] * scale);
    if ((t & 7) == 0) g_cq[(l * 2 + m) * 512 + h * 128 + tp] = cq * scale;
}

// Bvo[l][tp][m*512+h*128+d] = sum_j wv[j][d] * ow[tp][h*32+j]
// grid (32, 4=tpsplit), 256 thr; 16 outputs/thread
__global__ void __launch_bounds__(256) pc_Bvo_kernel(
    const float* __restrict__ mw_d, const float* __restrict__ ow_d,
    const float* __restrict__ mw_e, const float* __restrict__ ow_e) {
    __shared__ float wv_s[32 * 128];  // [j][d]
    __shared__ float ow_s[32 * 32];   // [tpl][j]
    int c = blockIdx.x, ts = blockIdx.y, t = threadIdx.x;
    int h = c & 3, m = (c >> 2) & 1, l = c >> 3;
    const float* W  = (m ? mw_e : mw_d) + (size_t)l * 3 * DD * DD;
    const float* ow = (m ? ow_e : ow_d) + (size_t)l * DD * DD;
    for (int i = t; i < 1024; i += 256)
        ((float4*)wv_s)[i] = ((const float4*)(W + (size_t)(2 * DD + h * 32) * DD))[i];
    for (int i = t; i < 1024; i += 256) {
        int tpl = i >> 5, j = i & 31;
        ow_s[tpl * 32 + j] = ow[(size_t)(ts * 32 + tpl) * 128 + h * 32 + j];
    }
    __syncthreads();
    int tpl = t >> 3, d0 = (t & 7) * 16;
    float acc[16];
    #pragma unroll
    for (int i = 0; i < 16; i++) acc[i] = 0.0f;
    for (int j = 0; j < 32; j++) {
        float o = ow_s[tpl * 32 + j];
        const float4* wr = (const float4*)(wv_s + j * 128 + d0);
        #pragma unroll
        for (int q = 0; q < 4; q++) {
            float4 w4 = wr[q];
            acc[q*4+0] = fmaf(o, w4.x, acc[q*4+0]);
            acc[q*4+1] = fmaf(o, w4.y, acc[q*4+1]);
            acc[q*4+2] = fmaf(o, w4.z, acc[q*4+2]);
            acc[q*4+3] = fmaf(o, w4.w, acc[q*4+3]);
        }
    }
    int tp = ts * 32 + tpl;
    __nv_bfloat16* dst = g_Bvo + (size_t)l * DD * 1024 + (size_t)tp * 1024 + m * 512 + h * 128 + d0;
    #pragma unroll
    for (int q = 0; q < 8; q++)
        *(uint32_t*)(dst + q * 2) = f2bf2(acc[q*2], acc[q*2+1]);
}

// cvo[(l,m)][t] = ob[t] + ow[t]@bv ; grid (2,4), 128 thr
__global__ void __launch_bounds__(128) pc_cvo_kernel(
    const float* __restrict__ mb_d, const float* __restrict__ ow_d, const float* __restrict__ ob_d,
    const float* __restrict__ mb_e, const float* __restrict__ ow_e, const float* __restrict__ ob_e) {
    int m = blockIdx.x, l = blockIdx.y, t = threadIdx.x;
    const float* ow = (m ? ow_e : ow_d) + (size_t)l * DD * DD;
    const float* ob = (m ? ob_e : ob_d) + l * DD;
    const float* bv = (m ? mb_e : mb_d) + l * 3 * DD + 2 * DD;
    float s = ob[t];
    for (int u = 0; u < 128; u++) s += ow[(size_t)t * 128 + u] * bv[u];
    g_cvo[(l * 2 + m) * 128 + t] = s;
}

// ---------------- common helpers ----------------
__device__ __forceinline__ void layernorm_rows(const float* __restrict__ src,
                                               const float* __restrict__ g,
                                               const float* __restrict__ bta,
                                               float (*dst)[DD], int t, int nthr) {
    int warp = t >> 5, lane = t & 31, nw = nthr >> 5;
    for (int r = warp; r < NLAT; r += nw) {
        float4 v = ((const float4*)(src + r * DD))[lane];
        float s = v.x + v.y + v.z + v.w;
        #pragma unroll
        for (int o = 16; o; o >>= 1) s += __shfl_xor_sync(0xffffffffu, s, o);
        float mean = s * (1.0f / DD);
        float dx = v.x - mean, dy = v.y - mean, dz = v.z - mean, dw = v.w - mean;
        float q = dx * dx + dy * dy + dz * dz + dw * dw;
        #pragma unroll
        for (int o = 16; o; o >>= 1) q += __shfl_xor_sync(0xffffffffu, q, o);
        float rstd = rsqrtf(q * (1.0f / DD) + 1e-5f);
        int c = lane * 4;
        dst[r][c + 0] = dx * rstd * g[c + 0] + bta[c + 0];
        dst[r][c + 1] = dy * rstd * g[c + 1] + bta[c + 1];
        dst[r][c + 2] = dz * rstd * g[c + 2] + bta[c + 2];
        dst[r][c + 3] = dw * rstd * g[c + 3] + bta[c + 3];
    }
}

__device__ __forceinline__ uint32_t s2u(const void* p) {
    return (uint32_t)__cvta_generic_to_shared(p);
}

#define LDSM4(R, addr) asm volatile( \
    "ldmatrix.sync.aligned.m8n8.x4.shared.b16 {%0,%1,%2,%3},[%4];" \
    : "=r"((R)[0]), "=r"((R)[1]), "=r"((R)[2]), "=r"((R)[3]) : "r"(addr))
#define LDSM4T(R, addr) asm volatile( \
    "ldmatrix.sync.aligned.m8n8.x4.trans.shared.b16 {%0,%1,%2,%3},[%4];" \
    : "=r"((R)[0]), "=r"((R)[1]), "=r"((R)[2]), "=r"((R)[3]) : "r"(addr))
#define MMA16816(D, A, B0, B1) asm volatile( \
    "mma.sync.aligned.m16n8k16.row.col.f32.bf16.bf16.f32 " \
    "{%0,%1,%2,%3},{%4,%5,%6,%7},{%8,%9},{%0,%1,%2,%3};" \
    : "+f"((D)[0]), "+f"((D)[1]), "+f"((D)[2]), "+f"((D)[3]) \
    : "r"((A)[0]), "r"((A)[1]), "r"((A)[2]), "r"((A)[3]), "r"(B0), "r"(B1))
#define CP16(dst, src) asm volatile("cp.async.cg.shared.global [%0], [%1], 16;\n" :: "r"(dst), "l"(src))
#define CP_COMMIT() asm volatile("cp.async.commit_group;\n" ::: "memory")
#define CP_WAIT1() asm volatile("cp.async.wait_group 1;\n" ::: "memory")
#define CP_WAIT0() asm volatile("cp.async.wait_group 0;\n" ::: "memory")

// ---------------- prep_q: LN + single bf16 GEMM [16,128]@[128,512] ----------------
__global__ void __launch_bounds__(256) prep_q_kernel(int layer,
    const float* __restrict__ lng, const float* __restrict__ lnb) {
    __shared__ float nlf[NLAT][DD];
    __shared__ __nv_bfloat16 nlh[NLAT][136];
    int b = blockIdx.x, mod = blockIdx.y, t = threadIdx.x;
    layernorm_rows(g_lat + (size_t)b * NLAT * DD, lng, lnb, nlf, t, 256);
    __syncthreads();
    for (int i = t; i < NLAT * DD / 2; i += 256) {
        int r = i >> 6, c = (i & 63) * 2;
        *(uint32_t*)&nlh[r][c] = f2bf2(nlf[r][c], nlf[r][c + 1]);
    }
    __syncthreads();
    int w = t >> 5, lane = t & 31, g = lane >> 2, tc = lane & 3;
    const __nv_bfloat16* Aq = g_Aqt + (size_t)(layer * 2 + mod) * 512 * 128;
    const float* cq = g_cq + (layer * 2 + mod) * 512;
    uint32_t aAddr = s2u(&nlh[lane & 15][(lane >> 4) * 8]);
    float acc[8][4];
    #pragma unroll
    for (int i = 0; i < 8; i++)
        #pragma unroll
        for (int j = 0; j < 4; j++) acc[i][j] = 0.0f;
    #pragma unroll
    for (int ks = 0; ks < 8; ks++) {
        uint32_t aA[4];
        LDSM4(aA, aAddr + ks * 32);
        #pragma unroll
        for (int nt = 0; nt < 8; nt++) {
            int n = w * 64 + nt * 8 + g;
            uint32_t b0 = *(const uint32_t*)(Aq + (size_t)n * 128 + ks * 16 + tc * 2);
            uint32_t b1 = *(const uint32_t*)(Aq + (size_t)n * 128 + ks * 16 + tc * 2 + 8);
            MMA16816(acc[nt], aA, b0, b1);
        }
    }
    __nv_bfloat16* qtb = g_qth[mod] + (size_t)b * NPAIR * DD;
    #pragma unroll
    for (int nt = 0; nt < 8; nt++) {
        int n0 = w * 64 + nt * 8 + tc * 2;
        float c0v = cq[n0], c1v = cq[n0 + 1];
        *(uint32_t*)(qtb + (size_t)g * 512 + n0)       = f2bf2(acc[nt][0] + c0v, acc[nt][1] + c1v);
        *(uint32_t*)(qtb + (size_t)(g + 8) * 512 + n0) = f2bf2(acc[nt][2] + c0v, acc[nt][3] + c1v);
    }
}

// ---------------- attention (tensor cores, cp.async double-buffered) ----------------
#define KV_ELE (64 * 136)
#define ATT_BYTES (4 * KV_ELE * 2 + 64 * 72 * 2 + 64 * 68 * 4 + 3 * 64 * 4)

__device__ __forceinline__ void issue_chunk(const __nv_bfloat16* __restrict__ Kg,
                                            const __nv_bfloat16* __restrict__ Vg,
                                            __nv_bfloat16* Ksb, __nv_bfloat16* Vsb,
                                            int row0, int nk, int t) {
    #pragma unroll
    for (int i = t; i < 1024; i += 256) {
        int r = i >> 4, seg = (i & 15) * 8;
        if (r < nk) {
            CP16(s2u(Ksb + r * 136 + seg), Kg + (size_t)(row0 + r) * DD + seg);
            CP16(s2u(Vsb + r * 136 + seg), Vg + (size_t)(row0 + r) * DD + seg);
        }
    }
}

// grid 1024: bid<512 -> enzyme first, else drug. 256 threads.
__global__ void __launch_bounds__(256, 2) attn_kernel() {
    extern __shared__ char smraw[];
    __nv_bfloat16* Ks0 = (__nv_bfloat16*)smraw;
    __nv_bfloat16* Vs0 = Ks0 + 2 * KV_ELE;
    __nv_bfloat16* Ps  = Vs0 + 2 * KV_ELE;
    float* ss  = (float*)(Ps + 64 * 72);
    float* m_s = ss + 64 * 68;
    float* l_s = m_s + 64;
    float* sc_s = l_s + 64;

    int bid = blockIdx.x, t = threadIdx.x;
    int mod = (bid < 512) ? 1 : 0;
    int b = bid & 511;
    const __nv_bfloat16* Kg = mod ? g_ek : g_dk;
    const __nv_bfloat16* Vg = mod ? g_ev : g_dv;
    int w = t >> 5, lane = t & 31;
    int g = lane >> 2, tc = lane & 3;
    int s0 = g_starts[mod][b];
    int cnt = g_starts[mod][b + 1] - s0;

    int pb = (w & 3) * 16;
    int th = w >> 2;

    for (int i = t; i < (4 * KV_ELE * 2) / 16; i += 256)
        ((uint4*)smraw)[i] = make_uint4(0, 0, 0, 0);

    uint32_t qa[8][4];
    {
        const __nv_bfloat16* qtb = g_qth[mod] + (size_t)b * NPAIR * DD;
        int r0 = pb + g, r1 = pb + g + 8;
        #pragma unroll
        for (int ks = 0; ks < 8; ks++) {
            int c0 = ks * 16 + tc * 2;
            qa[ks][0] = *(const uint32_t*)(qtb + (size_t)r0 * DD + c0);
            qa[ks][1] = *(const uint32_t*)(qtb + (size_t)r1 * DD + c0);
            qa[ks][2] = *(const uint32_t*)(qtb + (size_t)r0 * DD + c0 + 8);
            qa[ks][3] = *(const uint32_t*)(qtb + (size_t)r1 * DD + c0 + 8);
        }
    }
    if (t < 64) { m_s[t] = -1e30f; l_s[t] = 0.0f; }

    float cx[8][4];
    #pragma unroll
    for (int i = 0; i < 8; i++)
        #pragma unroll
        for (int j = 0; j < 4; j++) cx[i][j] = 0.0f;

    uint32_t aK1 = s2u(Ks0 + (th * 32 + ((lane >> 4) << 3) + (lane & 7)) * 136 + ((lane >> 3) & 1) * 8);
    uint32_t aK2 = aK1 + 16 * 136 * 2;
    uint32_t aP  = s2u(Ps + (pb + (lane & 15)) * 72 + (lane >> 4) * 8);
    uint32_t aV  = s2u(Vs0 + (lane & 15) * 136 + th * 64 + (lane >> 4) * 8);

    int nchunks = (cnt + 63) >> 6;
    __syncthreads();
    if (nchunks > 0) {
        issue_chunk(Kg, Vg, Ks0, Vs0, s0, min(64, cnt), t);
        CP_COMMIT();
    }

    for (int k = 0; k < nchunks; k++) {
        int cur = k & 1;
        int nk = min(64, cnt - k * 64);
        if (k + 1 < nchunks) {
            int nk2 = min(64, cnt - (k + 1) * 64);
            issue_chunk(Kg, Vg, Ks0 + (cur ^ 1) * KV_ELE, Vs0 + (cur ^ 1) * KV_ELE,
                        s0 + (k + 1) * 64, nk2, t);
            CP_COMMIT();
            CP_WAIT1();
        } else {
            CP_WAIT0();
        }
        __syncthreads();
        {
            uint32_t kbase1 = aK1 + cur * (KV_ELE * 2);
            uint32_t kbase2 = aK2 + cur * (KV_ELE * 2);
            float sa[4][4];
            #pragma unroll
            for (int j = 0; j < 4; j++)
                #pragma unroll
                for (int q = 0; q < 4; q++) sa[j][q] = 0.0f;
            #pragma unroll
            for (int ks = 0; ks < 8; ks++) {
                uint32_t kb1[4], kb2[4];
                LDSM4(kb1, kbase1 + ks * 32);
                LDSM4(kb2, kbase2 + ks * 32);
                MMA16816(sa[0], qa[ks], kb1[0], kb1[1]);
                MMA16816(sa[1], qa[ks], kb1[2], kb1[3]);
                MMA16816(sa[2], qa[ks], kb2[0], kb2[1]);
                MMA16816(sa[3], qa[ks], kb2[2], kb2[3]);
            }
            int r0 = pb + g, r1 = pb + g + 8;
            #pragma unroll
            for (int j = 0; j < 4; j++) {
                int c0 = th * 32 + j * 8 + tc * 2;
                *(float2*)&ss[r0 * 68 + c0] = make_float2(sa[j][0], sa[j][1]);
                *(float2*)&ss[r1 * 68 + c0] = make_float2(sa[j][2], sa[j][3]);
            }
        }
        __syncthreads();
        {
            int p = t >> 2, sub = t & 3;
            int k0 = sub * 16;
            float mo = m_s[p];
            float cm = -1e30f;
            #pragma unroll 4
            for (int kk = k0; kk < k0 + 16; kk++) {
                float v = (kk < nk) ? ss[p * 68 + kk] : -1e30f;
                cm = fmaxf(cm, v);
            }
            cm = fmaxf(cm, __shfl_xor_sync(0xffffffffu, cm, 1));
            cm = fmaxf(cm, __shfl_xor_sync(0xffffffffu, cm, 2));
            cm = fmaxf(cm, mo);
            float sum = 0.0f;
            #pragma unroll 4
            for (int kk = k0; kk < k0 + 16; kk++) {
                float e = (kk < nk) ? __expf(ss[p * 68 + kk] - cm) : 0.0f;
                Ps[p * 72 + kk] = __float2bfloat16(e);
                sum += e;
            }
            sum += __shfl_xor_sync(0xffffffffu, sum, 1);
            sum += __shfl_xor_sync(0xffffffffu, sum, 2);
            if (sub == 0) {
                float scl = __expf(mo - cm);
                l_s[p] = l_s[p] * scl + sum;
                m_s[p] = cm;
                sc_s[p] = scl;
            }
        }
        __syncthreads();
        {
            uint32_t vbase = aV + cur * (KV_ELE * 2);
            float sc0 = sc_s[pb + g], sc1 = sc_s[pb + g + 8];
            #pragma unroll
            for (int nt = 0; nt < 8; nt++) {
                cx[nt][0] *= sc0; cx[nt][1] *= sc0;
                cx[nt][2] *= sc1; cx[nt][3] *= sc1;
            }
            #pragma unroll
            for (int ks = 0; ks < 4; ks++) {
                uint32_t pa[4];
                LDSM4(pa, aP + ks * 32);
                #pragma unroll
                for (int ntp = 0; ntp < 4; ntp++) {
                    uint32_t vb[4];
                    LDSM4T(vb, vbase + ks * 4352 + ntp * 32);
                    MMA16816(cx[ntp * 2 + 0], pa, vb[0], vb[1]);
                    MMA16816(cx[ntp * 2 + 1], pa, vb[2], vb[3]);
                }
            }
        }
        __syncthreads();
    }
    int r0 = pb + g, r1 = pb + g + 8;
    float l0 = l_s[r0], l1 = l_s[r1];
    float i0 = (l0 > 0.0f) ? 1.0f / l0 : 0.0f;
    float i1 = (l1 > 0.0f) ? 1.0f / l1 : 0.0f;
    __nv_bfloat16* cbp = g_ctxh + (size_t)b * 16384;
    int base0 = (r0 >> 2) * 1024 + mod * 512 + (r0 & 3) * 128;
    int base1 = (r1 >> 2) * 1024 + mod * 512 + (r1 & 3) * 128;
    #pragma unroll
    for (int nt = 0; nt < 8; nt++) {
        int d0 = th * 64 + nt * 8 + tc * 2;
        *(uint32_t*)(cbp + base0 + d0) = f2bf2(cx[nt][0] * i0, cx[nt][1] * i0);
        *(uint32_t*)(cbp + base1 + d0) = f2bf2(cx[nt][2] * i1, cx[nt][3] * i1);
    }
}

// ---------------- fused: VO GEMM (bf16 TC) + residual + LN2 + FFN (fp32) ----------------
#define PF_BYTES (33024 + 8192)

__global__ void __launch_bounds__(256) projffn_kernel(int layer,
    const float* __restrict__ lng, const float* __restrict__ lnb,
    const float* __restrict__ w1, const float* __restrict__ b1,
    const float* __restrict__ w2, const float* __restrict__ b2) {
    extern __shared__ char dsm[];
    __nv_bfloat16* ctxs = (__nv_bfloat16*)dsm;      // [16][1032]
    float* pool = (float*)dsm;                       // after GEMM: nl @0, hid @2048 floats
    float* latv = (float*)(dsm + 33024);             // [16][128]
    int b = blockIdx.x, t = threadIdx.x;
    int w = t >> 5, lane = t & 31, g = lane >> 2, tc = lane & 3;
    int half = t >> 7, tt = t & 127;

    {
        const uint4* src = (const uint4*)(g_ctxh + (size_t)b * 16384);
        for (int i = t; i < 2048; i += 256) {
            int r = i >> 7, c8 = i & 127;
            *(uint4*)(ctxs + r * 1032 + c8 * 8) = src[i];
        }
        const float4* lsrc = (const float4*)(g_lat + (size_t)b * NLAT * DD);
        for (int i = t; i < 512; i += 256) ((float4*)latv)[i] = lsrc[i];
    }
    __syncthreads();
    {
        const __nv_bfloat16* Bvop = g_Bvo + (size_t)layer * DD * 1024;
        const float* cvo0 = g_cvo + (layer * 2 + 0) * 128;
        const float* cvo1 = g_cvo + (layer * 2 + 1) * 128;
        uint32_t aC = s2u(ctxs + (lane & 15) * 1032 + (lane >> 4) * 8);
        float acc[2][4];
        #pragma unroll
        for (int i = 0; i < 2; i++)
            #pragma unroll
            for (int j = 0; j < 4; j++) acc[i][j] = 0.0f;
        #pragma unroll 4
        for (int ks = 0; ks < 64; ks++) {
            uint32_t aA[4];
            LDSM4(aA, aC + ks * 32);
            #pragma unroll
            for (int nt = 0; nt < 2; nt++) {
                int n = w * 16 + nt * 8 + g;
                uint32_t b0 = *(const uint32_t*)(Bvop + (size_t)n * 1024 + ks * 16 + tc * 2);
                uint32_t b1 = *(const uint32_t*)(Bvop + (size_t)n * 1024 + ks * 16 + tc * 2 + 8);
                MMA16816(acc[nt], aA, b0, b1);
            }
        }
        __syncthreads();
        #pragma unroll
        for (int nt = 0; nt < 2; nt++) {
            int n0 = w * 16 + nt * 8 + tc * 2;
            float c0v = cvo0[n0] + cvo1[n0];
            float c1v = cvo0[n0 + 1] + cvo1[n0 + 1];
            latv[g * 128 + n0]           += acc[nt][0] + c0v;
            latv[g * 128 + n0 + 1]       += acc[nt][1] + c1v;
            latv[(g + 8) * 128 + n0]     += acc[nt][2] + c0v;
            latv[(g + 8) * 128 + n0 + 1] += acc[nt][3] + c1v;
        }
    }
    __syncthreads();
    layernorm_rows(latv, lng, lnb, (float(*)[DD])pool, t, 256);
    __syncthreads();
    {
        float acc[NLAT];
        float bv = b1[t];
        #pragma unroll
        for (int i = 0; i < NLAT; i++) acc[i] = bv;
        const float4* wp = (const float4*)(w1 + (size_t)t * DD);
        #pragma unroll 2
        for (int d4 = 0; d4 < DD / 4; d4++) {
            float4 w4 = wp[d4];
            #pragma unroll
            for (int i = 0; i < NLAT; i++) {
                float4 n4 = *(const float4*)(pool + i * DD + d4 * 4);
                acc[i] = fmaf(n4.x, w4.x, fmaf(n4.y, w4.y, fmaf(n4.z, w4.z, fmaf(n4.w, w4.w, acc[i]))));
            }
        }
        __syncthreads();
        #pragma unroll
        for (int i = 0; i < NLAT; i++) pool[2048 + i * 256 + t] = fmaxf(acc[i], 0.0f);
    }
    __syncthreads();
    {
        float* latb = g_lat + (size_t)b * NLAT * DD;
        float acc[8];
        float bv = b2[tt];
        #pragma unroll
        for (int j = 0; j < 8; j++) acc[j] = bv;
        const float4* wp = (const float4*)(w2 + (size_t)tt * 2 * DD);
        #pragma unroll 2
        for (int u4 = 0; u4 < 2 * DD / 4; u4++) {
            float4 w4 = wp[u4];
            #pragma unroll
            for (int j = 0; j < 8; j++) {
                float4 h4 = *(const float4*)(pool + 2048 + (half * 8 + j) * 256 + u4 * 4);
                acc[j] = fmaf(h4.x, w4.x, fmaf(h4.y, w4.y, fmaf(h4.z, w4.z, fmaf(h4.w, w4.w, acc[j]))));
            }
        }
        #pragma unroll
        for (int j = 0; j < 8; j++) {
            int idx = (half * 8 + j) * DD + tt;
            latb[idx] = latv[idx] + acc[j];
        }
    }
}

// ---------------- head ----------------
__global__ void __launch_bounds__(128) head_kernel(
    const float* __restrict__ w1, const float* __restrict__ b1,
    const float* __restrict__ w2, const float* __restrict__ b2,
    float* __restrict__ out) {
    __shared__ float part[4];
    int b = blockIdx.x, t = threadIdx.x;
    const float4* flat = (const float4*)(g_lat + (size_t)b * NLAT * DD);
    const float4* wp = (const float4*)(w1 + (size_t)t * NLAT * DD);
    float acc = b1[t];
    #pragma unroll 4
    for (int u4 = 0; u4 < NLAT * DD / 4; u4++) {
        float4 f4 = flat[u4];
        float4 w4 = wp[u4];
        acc = fmaf(f4.x, w4.x, fmaf(f4.y, w4.y, fmaf(f4.z, w4.z, fmaf(f4.w, w4.w, acc))));
    }
    float v = fmaxf(acc, 0.0f) * w2[t];
    #pragma unroll
    for (int o = 16; o; o >>= 1) v += __shfl_xor_sync(0xffffffffu, v, o);
    if ((t & 31) == 0) part[t >> 5] = v;
    __syncthreads();
    if (t == 0) {
        float x = part[0] + part[1] + part[2] + part[3] + b2[0];
        out[b] = (x > 20.0f) ? x : log1pf(__expf(x));
    }
}

extern "C" void kernel_launch(void* const* d_in, const int* in_sizes, int n_in,
                              void* d_out, int out_size) {
    const float* drug_k   = (const float*)d_in[0];
    const float* drug_v   = (const float*)d_in[1];
    const float* enz_k    = (const float*)d_in[2];
    const float* enz_v    = (const float*)d_in[3];
    const int*   drug_b   = (const int*)d_in[4];
    const int*   enz_b    = (const int*)d_in[5];
    const float* latents  = (const float*)d_in[6];
    const float* wq_d     = (const float*)d_in[7];
    const float* bq_d     = (const float*)d_in[8];
    const float* wq_e     = (const float*)d_in[9];
    const float* bq_e     = (const float*)d_in[10];
    const float* mha_d_w  = (const float*)d_in[11];
    const float* mha_d_b  = (const float*)d_in[12];
    const float* mha_d_ow = (const float*)d_in[13];
    const float* mha_d_ob = (const float*)d_in[14];
    const float* mha_e_w  = (const float*)d_in[15];
    const float* mha_e_b  = (const float*)d_in[16];
    const float* mha_e_ow = (const float*)d_in[17];
    const float* mha_e_ob = (const float*)d_in[18];
    const float* ln1_g    = (const float*)d_in[19];
    const float* ln1_b    = (const float*)d_in[20];
    const float* ln2_g    = (const float*)d_in[21];
    const float* ln2_b    = (const float*)d_in[22];
    const float* ffn_w1   = (const float*)d_in[23];
    const float* ffn_b1   = (const float*)d_in[24];
    const float* ffn_w2   = (const float*)d_in[25];
    const float* ffn_b2   = (const float*)d_in[26];
    const float* head_w1  = (const float*)d_in[27];
    const float* head_b1  = (const float*)d_in[28];
    const float* head_w2  = (const float*)d_in[29];
    const float* head_b2  = (const float*)d_in[30];
    float* out = (float*)d_out;

    static int s_attr_set = 0;
    if (!s_attr_set) {
        cudaFuncSetAttribute(attn_kernel, cudaFuncAttributeMaxDynamicSharedMemorySize, ATT_BYTES);
        s_attr_set = 1;
    }

    offsets_kernel<<<3, 256>>>(drug_b, enz_b);
    init_lat_kernel<<<(BB * NLAT * DD + 255) / 256, 256>>>(latents);
    cvt_kernel<<<(NE * DD / 4 + 255) / 256, 256>>>(drug_k, drug_v, enz_k, enz_v);
    pc_P_kernel<<<dim3(32, 4), 256>>>(wq_d, bq_d, wq_e, bq_e, mha_d_w, mha_d_b, mha_e_w, mha_e_b);
    pc_Aq_kernel<<<dim3(32, 4), 256>>>(mha_d_w, mha_e_w);
    pc_Bvo_kernel<<<dim3(32, 4), 256>>>(mha_d_w, mha_d_ow, mha_e_w, mha_e_ow);
    pc_cvo_kernel<<<dim3(2, 4), 128>>>(mha_d_b, mha_d_ow, mha_d_ob, mha_e_b, mha_e_ow, mha_e_ob);

    dim3 gridp(BB, 2);
    for (int l = 0; l < LAYERS; l++) {
        size_t oV = (size_t)l * DD;
        size_t oF1 = (size_t)l * 2 * DD * DD;
        size_t oF1b = (size_t)l * 2 * DD;

        prep_q_kernel<<<gridp, 256>>>(l, ln1_g + oV, ln1_b + oV);
        attn_kernel<<<1024, 256, ATT_BYTES>>>();
        projffn_kernel<<<BB, 256, PF_BYTES>>>(l,
            ln2_g + oV, ln2_b + oV,
            ffn_w1 + oF1, ffn_b1 + oF1b, ffn_w2 + oF1, ffn_b2 + oV);
    }

    head_kernel<<<BB, 128>>>(head_w1, head_b1, head_w2, head_b2, out);
}

// round 11
// speedup vs baseline: 2.1673x; 1.1041x over previous
#include <cuda_runtime.h>
#include <cuda_bf16.h>
#include <stdint.h>
#include <math.h>

#define BB 512
#define DD 128
#define NLAT 16
#define NH 4
#define HDIM 32
#define ND 25600
#define NE 153600
#define NPAIR 64
#define LAYERS 4

// scratch (static device globals: allowed)
__device__ float g_lat[BB * NLAT * DD];
__device__ __nv_bfloat16 g_qth[2][BB * NPAIR * DD];      // [b][pair*128+t] == [b][i*512+h*128+t]
__device__ __nv_bfloat16 g_ctxh[BB * NLAT * 1024];       // [b][i*1024 + mod*512 + h*128 + d]
__device__ int   g_starts[2][BB + 1];
__device__ __nv_bfloat16 g_dk[ND * DD];
__device__ __nv_bfloat16 g_dv[ND * DD];
__device__ __nv_bfloat16 g_ek[NE * DD];
__device__ __nv_bfloat16 g_ev[NE * DD];
// composed weights
__device__ __nv_bfloat16 g_Aqt[LAYERS * 2 * 512 * 128];  // [(l,mod)][n=h*128+t'][d]
__device__ float g_cq[LAYERS * 2 * 512];
__device__ __nv_bfloat16 g_Bvo[LAYERS * 128 * 1024];     // [l][t'][k=mod*512+h*128+d]
__device__ float g_cvo[LAYERS * 2 * 128];
// precompute scratch: P[c][j][d], cb[c][j], c = (l*2+m)*4+h
__device__ float g_P[32 * 32 * 128];
__device__ float g_cb[32 * 32];

__device__ __forceinline__ int lb_dev(const int* __restrict__ a, int n, int key) {
    int lo = 0, hi = n;
    while (lo < hi) { int mid = (lo + hi) >> 1; if (a[mid] < key) lo = mid + 1; else hi = mid; }
    return lo;
}

__global__ void offsets_kernel(const int* __restrict__ db, const int* __restrict__ eb) {
    int i = blockIdx.x * blockDim.x + threadIdx.x;
    if (i <= BB) { g_starts[0][i] = lb_dev(db, ND, i); g_starts[1][i] = lb_dev(eb, NE, i); }
}

__global__ void init_lat_kernel(const float* __restrict__ latents) {
    int i = blockIdx.x * blockDim.x + threadIdx.x;
    if (i < BB * NLAT * DD) g_lat[i] = latents[i & (NLAT * DD - 1)];
}

__device__ __forceinline__ uint32_t f2bf2(float x, float y) {
    __nv_bfloat162 h = __floats2bfloat162_rn(x, y);
    return *reinterpret_cast<uint32_t*>(&h);
}

__global__ void cvt_kernel(const float* __restrict__ dk, const float* __restrict__ dv,
                           const float* __restrict__ ek, const float* __restrict__ ev) {
    int i = blockIdx.x * blockDim.x + threadIdx.x;
    int i4 = i * 4;
    if (i4 < ND * DD) {
        float4 a = *(const float4*)(dk + i4);
        float4 b = *(const float4*)(dv + i4);
        *(uint2*)(g_dk + i4) = make_uint2(f2bf2(a.x, a.y), f2bf2(a.z, a.w));
        *(uint2*)(g_dv + i4) = make_uint2(f2bf2(b.x, b.y), f2bf2(b.z, b.w));
    }
    if (i4 < NE * DD) {
        float4 a = *(const float4*)(ek + i4);
        float4 b = *(const float4*)(ev + i4);
        *(uint2*)(g_ek + i4) = make_uint2(f2bf2(a.x, a.y), f2bf2(a.z, a.w));
        *(uint2*)(g_ev + i4) = make_uint2(f2bf2(b.x, b.y), f2bf2(b.z, b.w));
    }
}

// ---------------- weight composition: 4 well-parallelized kernels ----------------
// c = (l*2+m)*4+h throughout.

// P[c][j][d] = sum_dp U_h[j][dp] * wq[dp][d]; cb[c][j] = U_h@bq + mb_q[h*32+j]
// grid (32, 4=dsplit), 256 thr; 4 outputs/thread; all-smem inner loop
__global__ void __launch_bounds__(256) pc_P_kernel(
    const float* __restrict__ wq_d, const float* __restrict__ bq_d,
    const float* __restrict__ wq_e, const float* __restrict__ bq_e,
    const float* __restrict__ mw_d, const float* __restrict__ mb_d,
    const float* __restrict__ mw_e, const float* __restrict__ mb_e) {
    __shared__ float U_s[32 * 128];
    __shared__ float wq_s[128 * 32];   // [dp][dcol] column slice
    int c = blockIdx.x, ds = blockIdx.y, t = threadIdx.x;
    int h = c & 3, m = (c >> 2) & 1, l = c >> 3;
    const float* wq = (m ? wq_e : wq_d) + (size_t)l * DD * DD;
    const float* W  = (m ? mw_e : mw_d) + (size_t)l * 3 * DD * DD;
    for (int i = t; i < 1024; i += 256)
        ((float4*)U_s)[i] = ((const float4*)(W + (size_t)h * 32 * DD))[i];
    for (int i = t; i < 1024; i += 256) {
        int dp = i >> 3, q = i & 7;
        *(float4*)(wq_s + dp * 32 + q * 4) = *(const float4*)(wq + (size_t)dp * 128 + ds * 32 + q * 4);
    }
    __syncthreads();
    int j = t >> 3, dl = (t & 7) * 4;
    float a0 = 0, a1 = 0, a2 = 0, a3 = 0;
    #pragma unroll 8
    for (int dp = 0; dp < 128; dp++) {
        float u = U_s[j * 128 + dp];
        float4 w4 = *(const float4*)(wq_s + dp * 32 + dl);
        a0 = fmaf(u, w4.x, a0); a1 = fmaf(u, w4.y, a1);
        a2 = fmaf(u, w4.z, a2); a3 = fmaf(u, w4.w, a3);
    }
    *(float4*)(g_P + (size_t)c * 4096 + j * 128 + ds * 32 + dl) = make_float4(a0, a1, a2, a3);
    if (ds == 0 && t < 32) {
        const float* bq = (m ? bq_e : bq_d) + l * DD;
        const float* mb = (m ? mb_e : mb_d) + l * 3 * DD;
        float s = 0.0f;
        #pragma unroll 8
        for (int dp = 0; dp < 128; dp++) s += U_s[t * 128 + dp] * bq[dp];
        g_cb[c * 32 + t] = s + mb[h * 32 + t];
    }
}

// Aqt[(l,m)][h*128+tp][d] = scale * sum_j wk[j][tp] * P[c][j][d]; cq likewise from cb
__global__ void __launch_bounds__(256) pc_Aq_kernel(
    const float* __restrict__ mw_d, const float* __restrict__ mw_e) {
    __shared__ float P_s[32 * 128];
    __shared__ float V_s[32 * 32];   // [j][tpl]
    __shared__ float cb_s[32];
    int c = blockIdx.x, ts = blockIdx.y, t = threadIdx.x;
    int h = c & 3, m = (c >> 2) & 1, l = c >> 3;
    const float* W = (m ? mw_e : mw_d) + (size_t)l * 3 * DD * DD;
    const float* wk = W + (size_t)(DD + h * 32) * DD;
    for (int i = t; i < 1024; i += 256)
        ((float4*)P_s)[i] = ((const float4*)(g_P + (size_t)c * 4096))[i];
    for (int i = t; i < 1024; i += 256) {
        int j = i >> 5, tpl = i & 31;
        V_s[j * 32 + tpl] = wk[(size_t)j * 128 + ts * 32 + tpl];
    }
    if (t < 32) cb_s[t] = g_cb[c * 32 + t];
    __syncthreads();
    const float scale = 0.17677669529663688f;
    int tpl = t >> 3, d0 = (t & 7) * 16;
    float acc[16];
    #pragma unroll
    for (int i = 0; i < 16; i++) acc[i] = 0.0f;
    float cq = 0.0f;
    for (int j = 0; j < 32; j++) {
        float v = V_s[j * 32 + tpl];
        const float4* pr = (const float4*)(P_s + j * 128 + d0);
        #pragma unroll
        for (int q = 0; q < 4; q++) {
            float4 p4 = pr[q];
            acc[q*4+0] = fmaf(v, p4.x, acc[q*4+0]);
            acc[q*4+1] = fmaf(v, p4.y, acc[q*4+1]);
            acc[q*4+2] = fmaf(v, p4.z, acc[q*4+2]);
            acc[q*4+3] = fmaf(v, p4.w, acc[q*4+3]);
        }
        cq += v * cb_s[j];
    }
    int tp = ts * 32 + tpl;
    __nv_bfloat16* dst = g_Aqt + ((size_t)(l * 2 + m) * 512 + h * 128 + tp) * 128 + d0;
    #pragma unroll
    for (int q = 0; q < 8; q++)
        *(uint32_t*)(dst + q * 2) = f2bf2(acc[q*2] * scale, acc[q*2+1] * scale);
    if ((t & 7) == 0) g_cq[(l * 2 + m) * 512 + h * 128 + tp] = cq * scale;
}

// Bvo[l][tp][m*512+h*128+d] = sum_j wv[j][d] * ow[tp][h*32+j]
__global__ void __launch_bounds__(256) pc_Bvo_kernel(
    const float* __restrict__ mw_d, const float* __restrict__ ow_d,
    const float* __restrict__ mw_e, const float* __restrict__ ow_e) {
    __shared__ float wv_s[32 * 128];  // [j][d]
    __shared__ float ow_s[32 * 32];   // [tpl][j]
    int c = blockIdx.x, ts = blockIdx.y, t = threadIdx.x;
    int h = c & 3, m = (c >> 2) & 1, l = c >> 3;
    const float* W  = (m ? mw_e : mw_d) + (size_t)l * 3 * DD * DD;
    const float* ow = (m ? ow_e : ow_d) + (size_t)l * DD * DD;
    for (int i = t; i < 1024; i += 256)
        ((float4*)wv_s)[i] = ((const float4*)(W + (size_t)(2 * DD + h * 32) * DD))[i];
    for (int i = t; i < 1024; i += 256) {
        int tpl = i >> 5, j = i & 31;
        ow_s[tpl * 32 + j] = ow[(size_t)(ts * 32 + tpl) * 128 + h * 32 + j];
    }
    __syncthreads();
    int tpl = t >> 3, d0 = (t & 7) * 16;
    float acc[16];
    #pragma unroll
    for (int i = 0; i < 16; i++) acc[i] = 0.0f;
    for (int j = 0; j < 32; j++) {
        float o = ow_s[tpl * 32 + j];
        const float4* wr = (const float4*)(wv_s + j * 128 + d0);
        #pragma unroll
        for (int q = 0; q < 4; q++) {
            float4 w4 = wr[q];
            acc[q*4+0] = fmaf(o, w4.x, acc[q*4+0]);
            acc[q*4+1] = fmaf(o, w4.y, acc[q*4+1]);
            acc[q*4+2] = fmaf(o, w4.z, acc[q*4+2]);
            acc[q*4+3] = fmaf(o, w4.w, acc[q*4+3]);
        }
    }
    int tp = ts * 32 + tpl;
    __nv_bfloat16* dst = g_Bvo + (size_t)l * DD * 1024 + (size_t)tp * 1024 + m * 512 + h * 128 + d0;
    #pragma unroll
    for (int q = 0; q < 8; q++)
        *(uint32_t*)(dst + q * 2) = f2bf2(acc[q*2], acc[q*2+1]);
}

// cvo[(l,m)][t] = ob[t] + ow[t]@bv ; grid (2,4), 128 thr; unrolled, smem bv
__global__ void __launch_bounds__(128) pc_cvo_kernel(
    const float* __restrict__ mb_d, const float* __restrict__ ow_d, const float* __restrict__ ob_d,
    const float* __restrict__ mb_e, const float* __restrict__ ow_e, const float* __restrict__ ob_e) {
    __shared__ float bv_s[128];
    int m = blockIdx.x, l = blockIdx.y, t = threadIdx.x;
    const float* ow = (m ? ow_e : ow_d) + (size_t)l * DD * DD;
    const float* ob = (m ? ob_e : ob_d) + l * DD;
    const float* bv = (m ? mb_e : mb_d) + l * 3 * DD + 2 * DD;
    bv_s[t] = bv[t];
    __syncthreads();
    float s = ob[t];
    const float4* owr = (const float4*)(ow + (size_t)t * 128);
    #pragma unroll
    for (int u4 = 0; u4 < 32; u4++) {
        float4 o4 = owr[u4];
        s = fmaf(o4.x, bv_s[u4*4+0], fmaf(o4.y, bv_s[u4*4+1],
            fmaf(o4.z, bv_s[u4*4+2], fmaf(o4.w, bv_s[u4*4+3], s))));
    }
    g_cvo[(l * 2 + m) * 128 + t] = s;
}

// ---------------- common helpers ----------------
__device__ __forceinline__ void layernorm_rows(const float* __restrict__ src,
                                               const float* __restrict__ g,
                                               const float* __restrict__ bta,
                                               float (*dst)[DD], int t, int nthr) {
    int warp = t >> 5, lane = t & 31, nw = nthr >> 5;
    for (int r = warp; r < NLAT; r += nw) {
        float4 v = ((const float4*)(src + r * DD))[lane];
        float s = v.x + v.y + v.z + v.w;
        #pragma unroll
        for (int o = 16; o; o >>= 1) s += __shfl_xor_sync(0xffffffffu, s, o);
        float mean = s * (1.0f / DD);
        float dx = v.x - mean, dy = v.y - mean, dz = v.z - mean, dw = v.w - mean;
        float q = dx * dx + dy * dy + dz * dz + dw * dw;
        #pragma unroll
        for (int o = 16; o; o >>= 1) q += __shfl_xor_sync(0xffffffffu, q, o);
        float rstd = rsqrtf(q * (1.0f / DD) + 1e-5f);
        int c = lane * 4;
        dst[r][c + 0] = dx * rstd * g[c + 0] + bta[c + 0];
        dst[r][c + 1] = dy * rstd * g[c + 1] + bta[c + 1];
        dst[r][c + 2] = dz * rstd * g[c + 2] + bta[c + 2];
        dst[r][c + 3] = dw * rstd * g[c + 3] + bta[c + 3];
    }
}

__device__ __forceinline__ uint32_t s2u(const void* p) {
    return (uint32_t)__cvta_generic_to_shared(p);
}

#define LDSM4(R, addr) asm volatile( \
    "ldmatrix.sync.aligned.m8n8.x4.shared.b16 {%0,%1,%2,%3},[%4];" \
    : "=r"((R)[0]), "=r"((R)[1]), "=r"((R)[2]), "=r"((R)[3]) : "r"(addr))
#define LDSM4T(R, addr) asm volatile( \
    "ldmatrix.sync.aligned.m8n8.x4.trans.shared.b16 {%0,%1,%2,%3},[%4];" \
    : "=r"((R)[0]), "=r"((R)[1]), "=r"((R)[2]), "=r"((R)[3]) : "r"(addr))
#define MMA16816(D, A, B0, B1) asm volatile( \
    "mma.sync.aligned.m16n8k16.row.col.f32.bf16.bf16.f32 " \
    "{%0,%1,%2,%3},{%4,%5,%6,%7},{%8,%9},{%0,%1,%2,%3};" \
    : "+f"((D)[0]), "+f"((D)[1]), "+f"((D)[2]), "+f"((D)[3]) \
    : "r"((A)[0]), "r"((A)[1]), "r"((A)[2]), "r"((A)[3]), "r"(B0), "r"(B1))
#define CP16(dst, src) asm volatile("cp.async.cg.shared.global [%0], [%1], 16;\n" :: "r"(dst), "l"(src))
#define CP_COMMIT() asm volatile("cp.async.commit_group;\n" ::: "memory")
#define CP_WAIT1() asm volatile("cp.async.wait_group 1;\n" ::: "memory")
#define CP_WAIT0() asm volatile("cp.async.wait_group 0;\n" ::: "memory")

// ---------------- prep_q: LN + single bf16 GEMM [16,128]@[128,512] ----------------
__global__ void __launch_bounds__(256) prep_q_kernel(int layer,
    const float* __restrict__ lng, const float* __restrict__ lnb) {
    __shared__ float nlf[NLAT][DD];
    __shared__ __nv_bfloat16 nlh[NLAT][136];
    int b = blockIdx.x, mod = blockIdx.y, t = threadIdx.x;
    layernorm_rows(g_lat + (size_t)b * NLAT * DD, lng, lnb, nlf, t, 256);
    __syncthreads();
    for (int i = t; i < NLAT * DD / 2; i += 256) {
        int r = i >> 6, c = (i & 63) * 2;
        *(uint32_t*)&nlh[r][c] = f2bf2(nlf[r][c], nlf[r][c + 1]);
    }
    __syncthreads();
    int w = t >> 5, lane = t & 31, g = lane >> 2, tc = lane & 3;
    const __nv_bfloat16* Aq = g_Aqt + (size_t)(layer * 2 + mod) * 512 * 128;
    const float* cq = g_cq + (layer * 2 + mod) * 512;
    uint32_t aAddr = s2u(&nlh[lane & 15][(lane >> 4) * 8]);
    float acc[8][4];
    #pragma unroll
    for (int i = 0; i < 8; i++)
        #pragma unroll
        for (int j = 0; j < 4; j++) acc[i][j] = 0.0f;
    #pragma unroll
    for (int ks = 0; ks < 8; ks++) {
        uint32_t aA[4];
        LDSM4(aA, aAddr + ks * 32);
        #pragma unroll
        for (int nt = 0; nt < 8; nt++) {
            int n = w * 64 + nt * 8 + g;
            uint32_t b0 = *(const uint32_t*)(Aq + (size_t)n * 128 + ks * 16 + tc * 2);
            uint32_t b1 = *(const uint32_t*)(Aq + (size_t)n * 128 + ks * 16 + tc * 2 + 8);
            MMA16816(acc[nt], aA, b0, b1);
        }
    }
    __nv_bfloat16* qtb = g_qth[mod] + (size_t)b * NPAIR * DD;
    #pragma unroll
    for (int nt = 0; nt < 8; nt++) {
        int n0 = w * 64 + nt * 8 + tc * 2;
        float c0v = cq[n0], c1v = cq[n0 + 1];
        *(uint32_t*)(qtb + (size_t)g * 512 + n0)       = f2bf2(acc[nt][0] + c0v, acc[nt][1] + c1v);
        *(uint32_t*)(qtb + (size_t)(g + 8) * 512 + n0) = f2bf2(acc[nt][2] + c0v, acc[nt][3] + c1v);
    }
}

// ---------------- attention (tensor cores, cp.async double-buffered) ----------------
#define KV_ELE (64 * 136)
#define ATT_BYTES (4 * KV_ELE * 2 + 64 * 72 * 2 + 64 * 68 * 4 + 3 * 64 * 4)

__device__ __forceinline__ void issue_chunk(const __nv_bfloat16* __restrict__ Kg,
                                            const __nv_bfloat16* __restrict__ Vg,
                                            __nv_bfloat16* Ksb, __nv_bfloat16* Vsb,
                                            int row0, int nk, int t) {
    #pragma unroll
    for (int i = t; i < 1024; i += 256) {
        int r = i >> 4, seg = (i & 15) * 8;
        if (r < nk) {
            CP16(s2u(Ksb + r * 136 + seg), Kg + (size_t)(row0 + r) * DD + seg);
            CP16(s2u(Vsb + r * 136 + seg), Vg + (size_t)(row0 + r) * DD + seg);
        }
    }
}

// grid 1024: bid<512 -> enzyme first, else drug. 256 threads.
__global__ void __launch_bounds__(256, 2) attn_kernel() {
    extern __shared__ char smraw[];
    __nv_bfloat16* Ks0 = (__nv_bfloat16*)smraw;
    __nv_bfloat16* Vs0 = Ks0 + 2 * KV_ELE;
    __nv_bfloat16* Ps  = Vs0 + 2 * KV_ELE;
    float* ss  = (float*)(Ps + 64 * 72);
    float* m_s = ss + 64 * 68;
    float* l_s = m_s + 64;
    float* sc_s = l_s + 64;

    int bid = blockIdx.x, t = threadIdx.x;
    int mod = (bid < 512) ? 1 : 0;
    int b = bid & 511;
    const __nv_bfloat16* Kg = mod ? g_ek : g_dk;
    const __nv_bfloat16* Vg = mod ? g_ev : g_dv;
    int w = t >> 5, lane = t & 31;
    int g = lane >> 2, tc = lane & 3;
    int s0 = g_starts[mod][b];
    int cnt = g_starts[mod][b + 1] - s0;

    int pb = (w & 3) * 16;
    int th = w >> 2;

    for (int i = t; i < (4 * KV_ELE * 2) / 16; i += 256)
        ((uint4*)smraw)[i] = make_uint4(0, 0, 0, 0);

    uint32_t qa[8][4];
    {
        const __nv_bfloat16* qtb = g_qth[mod] + (size_t)b * NPAIR * DD;
        int r0 = pb + g, r1 = pb + g + 8;
        #pragma unroll
        for (int ks = 0; ks < 8; ks++) {
            int c0 = ks * 16 + tc * 2;
            qa[ks][0] = *(const uint32_t*)(qtb + (size_t)r0 * DD + c0);
            qa[ks][1] = *(const uint32_t*)(qtb + (size_t)r1 * DD + c0);
            qa[ks][2] = *(const uint32_t*)(qtb + (size_t)r0 * DD + c0 + 8);
            qa[ks][3] = *(const uint32_t*)(qtb + (size_t)r1 * DD + c0 + 8);
        }
    }
    if (t < 64) { m_s[t] = -1e30f; l_s[t] = 0.0f; }

    float cx[8][4];
    #pragma unroll
    for (int i = 0; i < 8; i++)
        #pragma unroll
        for (int j = 0; j < 4; j++) cx[i][j] = 0.0f;

    uint32_t aK1 = s2u(Ks0 + (th * 32 + ((lane >> 4) << 3) + (lane & 7)) * 136 + ((lane >> 3) & 1) * 8);
    uint32_t aK2 = aK1 + 16 * 136 * 2;
    uint32_t aP  = s2u(Ps + (pb + (lane & 15)) * 72 + (lane >> 4) * 8);
    uint32_t aV  = s2u(Vs0 + (lane & 15) * 136 + th * 64 + (lane >> 4) * 8);

    int nchunks = (cnt + 63) >> 6;
    __syncthreads();
    if (nchunks > 0) {
        issue_chunk(Kg, Vg, Ks0, Vs0, s0, min(64, cnt), t);
        CP_COMMIT();
    }

    for (int k = 0; k < nchunks; k++) {
        int cur = k & 1;
        int nk = min(64, cnt - k * 64);
        if (k + 1 < nchunks) {
            int nk2 = min(64, cnt - (k + 1) * 64);
            issue_chunk(Kg, Vg, Ks0 + (cur ^ 1) * KV_ELE, Vs0 + (cur ^ 1) * KV_ELE,
                        s0 + (k + 1) * 64, nk2, t);
            CP_COMMIT();
            CP_WAIT1();
        } else {
            CP_WAIT0();
        }
        __syncthreads();
        {
            uint32_t kbase1 = aK1 + cur * (KV_ELE * 2);
            uint32_t kbase2 = aK2 + cur * (KV_ELE * 2);
            float sa[4][4];
            #pragma unroll
            for (int j = 0; j < 4; j++)
                #pragma unroll
                for (int q = 0; q < 4; q++) sa[j][q] = 0.0f;
            #pragma unroll
            for (int ks = 0; ks < 8; ks++) {
                uint32_t kb1[4], kb2[4];
                LDSM4(kb1, kbase1 + ks * 32);
                LDSM4(kb2, kbase2 + ks * 32);
                MMA16816(sa[0], qa[ks], kb1[0], kb1[1]);
                MMA16816(sa[1], qa[ks], kb1[2], kb1[3]);
                MMA16816(sa[2], qa[ks], kb2[0], kb2[1]);
                MMA16816(sa[3], qa[ks], kb2[2], kb2[3]);
            }
            int r0 = pb + g, r1 = pb + g + 8;
            #pragma unroll
            for (int j = 0; j < 4; j++) {
                int c0 = th * 32 + j * 8 + tc * 2;
                *(float2*)&ss[r0 * 68 + c0] = make_float2(sa[j][0], sa[j][1]);
                *(float2*)&ss[r1 * 68 + c0] = make_float2(sa[j][2], sa[j][3]);
            }
        }
        __syncthreads();
        {
            int p = t >> 2, sub = t & 3;
            int k0 = sub * 16;
            float mo = m_s[p];
            float cm = -1e30f;
            #pragma unroll 4
            for (int kk = k0; kk < k0 + 16; kk++) {
                float v = (kk < nk) ? ss[p * 68 + kk] : -1e30f;
                cm = fmaxf(cm, v);
            }
            cm = fmaxf(cm, __shfl_xor_sync(0xffffffffu, cm, 1));
            cm = fmaxf(cm, __shfl_xor_sync(0xffffffffu, cm, 2));
            cm = fmaxf(cm, mo);
            float sum = 0.0f;
            #pragma unroll 4
            for (int kk = k0; kk < k0 + 16; kk++) {
                float e = (kk < nk) ? __expf(ss[p * 68 + kk] - cm) : 0.0f;
                Ps[p * 72 + kk] = __float2bfloat16(e);
                sum += e;
            }
            sum += __shfl_xor_sync(0xffffffffu, sum, 1);
            sum += __shfl_xor_sync(0xffffffffu, sum, 2);
            if (sub == 0) {
                float scl = __expf(mo - cm);
                l_s[p] = l_s[p] * scl + sum;
                m_s[p] = cm;
                sc_s[p] = scl;
            }
        }
        __syncthreads();
        {
            uint32_t vbase = aV + cur * (KV_ELE * 2);
            float sc0 = sc_s[pb + g], sc1 = sc_s[pb + g + 8];
            #pragma unroll
            for (int nt = 0; nt < 8; nt++) {
                cx[nt][0] *= sc0; cx[nt][1] *= sc0;
                cx[nt][2] *= sc1; cx[nt][3] *= sc1;
            }
            #pragma unroll
            for (int ks = 0; ks < 4; ks++) {
                uint32_t pa[4];
                LDSM4(pa, aP + ks * 32);
                #pragma unroll
                for (int ntp = 0; ntp < 4; ntp++) {
                    uint32_t vb[4];
                    LDSM4T(vb, vbase + ks * 4352 + ntp * 32);
                    MMA16816(cx[ntp * 2 + 0], pa, vb[0], vb[1]);
                    MMA16816(cx[ntp * 2 + 1], pa, vb[2], vb[3]);
                }
            }
        }
        __syncthreads();
    }
    int r0 = pb + g, r1 = pb + g + 8;
    float l0 = l_s[r0], l1 = l_s[r1];
    float i0 = (l0 > 0.0f) ? 1.0f / l0 : 0.0f;
    float i1 = (l1 > 0.0f) ? 1.0f / l1 : 0.0f;
    __nv_bfloat16* cbp = g_ctxh + (size_t)b * 16384;
    int base0 = (r0 >> 2) * 1024 + mod * 512 + (r0 & 3) * 128;
    int base1 = (r1 >> 2) * 1024 + mod * 512 + (r1 & 3) * 128;
    #pragma unroll
    for (int nt = 0; nt < 8; nt++) {
        int d0 = th * 64 + nt * 8 + tc * 2;
        *(uint32_t*)(cbp + base0 + d0) = f2bf2(cx[nt][0] * i0, cx[nt][1] * i0);
        *(uint32_t*)(cbp + base1 + d0) = f2bf2(cx[nt][2] * i1, cx[nt][3] * i1);
    }
}

// ---------------- fused: VO GEMM (bf16 TC) + residual + LN2 + FFN (fp32) ----------------
#define PF_BYTES (33024 + 8192)

__global__ void __launch_bounds__(256) projffn_kernel(int layer,
    const float* __restrict__ lng, const float* __restrict__ lnb,
    const float* __restrict__ w1, const float* __restrict__ b1,
    const float* __restrict__ w2, const float* __restrict__ b2) {
    extern __shared__ char dsm[];
    __nv_bfloat16* ctxs = (__nv_bfloat16*)dsm;      // [16][1032]
    float* pool = (float*)dsm;                       // after GEMM: nl @0, hid @2048 floats
    float* latv = (float*)(dsm + 33024);             // [16][128]
    int b = blockIdx.x, t = threadIdx.x;
    int w = t >> 5, lane = t & 31, g = lane >> 2, tc = lane & 3;
    int half = t >> 7, tt = t & 127;

    {
        const uint4* src = (const uint4*)(g_ctxh + (size_t)b * 16384);
        for (int i = t; i < 2048; i += 256) {
            int r = i >> 7, c8 = i & 127;
            *(uint4*)(ctxs + r * 1032 + c8 * 8) = src[i];
        }
        const float4* lsrc = (const float4*)(g_lat + (size_t)b * NLAT * DD);
        for (int i = t; i < 512; i += 256) ((float4*)latv)[i] = lsrc[i];
    }
    __syncthreads();
    {
        const __nv_bfloat16* Bvop = g_Bvo + (size_t)layer * DD * 1024;
        const float* cvo0 = g_cvo + (layer * 2 + 0) * 128;
        const float* cvo1 = g_cvo + (layer * 2 + 1) * 128;
        uint32_t aC = s2u(ctxs + (lane & 15) * 1032 + (lane >> 4) * 8);
        float acc[2][4];
        #pragma unroll
        for (int i = 0; i < 2; i++)
            #pragma unroll
            for (int j = 0; j < 4; j++) acc[i][j] = 0.0f;
        #pragma unroll 4
        for (int ks = 0; ks < 64; ks++) {
            uint32_t aA[4];
            LDSM4(aA, aC + ks * 32);
            #pragma unroll
            for (int nt = 0; nt < 2; nt++) {
                int n = w * 16 + nt * 8 + g;
                uint32_t b0 = *(const uint32_t*)(Bvop + (size_t)n * 1024 + ks * 16 + tc * 2);
                uint32_t b1 = *(const uint32_t*)(Bvop + (size_t)n * 1024 + ks * 16 + tc * 2 + 8);
                MMA16816(acc[nt], aA, b0, b1);
            }
        }
        __syncthreads();
        #pragma unroll
        for (int nt = 0; nt < 2; nt++) {
            int n0 = w * 16 + nt * 8 + tc * 2;
            float c0v = cvo0[n0] + cvo1[n0];
            float c1v = cvo0[n0 + 1] + cvo1[n0 + 1];
            latv[g * 128 + n0]           += acc[nt][0] + c0v;
            latv[g * 128 + n0 + 1]       += acc[nt][1] + c1v;
            latv[(g + 8) * 128 + n0]     += acc[nt][2] + c0v;
            latv[(g + 8) * 128 + n0 + 1] += acc[nt][3] + c1v;
        }
    }
    __syncthreads();
    layernorm_rows(latv, lng, lnb, (float(*)[DD])pool, t, 256);
    __syncthreads();
    {
        float acc[NLAT];
        float bv = b1[t];
        #pragma unroll
        for (int i = 0; i < NLAT; i++) acc[i] = bv;
        const float4* wp = (const float4*)(w1 + (size_t)t * DD);
        #pragma unroll 2
        for (int d4 = 0; d4 < DD / 4; d4++) {
            float4 w4 = wp[d4];
            #pragma unroll
            for (int i = 0; i < NLAT; i++) {
                float4 n4 = *(const float4*)(pool + i * DD + d4 * 4);
                acc[i] = fmaf(n4.x, w4.x, fmaf(n4.y, w4.y, fmaf(n4.z, w4.z, fmaf(n4.w, w4.w, acc[i]))));
            }
        }
        __syncthreads();
        #pragma unroll
        for (int i = 0; i < NLAT; i++) pool[2048 + i * 256 + t] = fmaxf(acc[i], 0.0f);
    }
    __syncthreads();
    {
        float* latb = g_lat + (size_t)b * NLAT * DD;
        float acc[8];
        float bv = b2[tt];
        #pragma unroll
        for (int j = 0; j < 8; j++) acc[j] = bv;
        const float4* wp = (const float4*)(w2 + (size_t)tt * 2 * DD);
        #pragma unroll 2
        for (int u4 = 0; u4 < 2 * DD / 4; u4++) {
            float4 w4 = wp[u4];
            #pragma unroll
            for (int j = 0; j < 8; j++) {
                float4 h4 = *(const float4*)(pool + 2048 + (half * 8 + j) * 256 + u4 * 4);
                acc[j] = fmaf(h4.x, w4.x, fmaf(h4.y, w4.y, fmaf(h4.z, w4.z, fmaf(h4.w, w4.w, acc[j]))));
            }
        }
        #pragma unroll
        for (int j = 0; j < 8; j++) {
            int idx = (half * 8 + j) * DD + tt;
            latb[idx] = latv[idx] + acc[j];
        }
    }
}

// ---------------- head: grid 128, 4 batches/block; W1 traffic 4x lower ----------------
__global__ void __launch_bounds__(256) head_kernel(
    const float* __restrict__ w1, const float* __restrict__ b1,
    const float* __restrict__ w2, const float* __restrict__ b2,
    float* __restrict__ out) {
    __shared__ float flat_s[4][2048];
    __shared__ float hs[4][128];
    int blk = blockIdx.x, t = threadIdx.x;
    int b0 = blk * 4;
    const float4* src = (const float4*)(g_lat + (size_t)b0 * NLAT * DD);
    for (int i = t; i < 2048; i += 256) ((float4*)flat_s)[i] = src[i];
    __syncthreads();
    int tt = t & 127, bh = t >> 7;
    float acc0 = b1[tt], acc1 = acc0;
    const float4* w1r = (const float4*)(w1 + (size_t)tt * NLAT * DD);
    const float4* f0 = (const float4*)flat_s[bh * 2];
    const float4* f1 = (const float4*)flat_s[bh * 2 + 1];
    #pragma unroll 8
    for (int u4 = 0; u4 < 512; u4++) {
        float4 w4 = w1r[u4];
        float4 a4 = f0[u4];
        float4 c4 = f1[u4];
        acc0 = fmaf(w4.x, a4.x, fmaf(w4.y, a4.y, fmaf(w4.z, a4.z, fmaf(w4.w, a4.w, acc0))));
        acc1 = fmaf(w4.x, c4.x, fmaf(w4.y, c4.y, fmaf(w4.z, c4.z, fmaf(w4.w, c4.w, acc1))));
    }
    hs[bh * 2][tt] = fmaxf(acc0, 0.0f);
    hs[bh * 2 + 1][tt] = fmaxf(acc1, 0.0f);
    __syncthreads();
    int w = t >> 5, lane = t & 31;
    if (w < 4) {
        float s = 0.0f;
        #pragma unroll
        for (int q = 0; q < 4; q++) {
            int idx = q * 32 + lane;
            s += hs[w][idx] * w2[idx];
        }
        #pragma unroll
        for (int o = 16; o; o >>= 1) s += __shfl_xor_sync(0xffffffffu, s, o);
        if (lane == 0) {
            float x = s + b2[0];
            out[b0 + w] = (x > 20.0f) ? x : log1pf(__expf(x));
        }
    }
}

extern "C" void kernel_launch(void* const* d_in, const int* in_sizes, int n_in,
                              void* d_out, int out_size) {
    const float* drug_k   = (const float*)d_in[0];
    const float* drug_v   = (const float*)d_in[1];
    const float* enz_k    = (const float*)d_in[2];
    const float* enz_v    = (const float*)d_in[3];
    const int*   drug_b   = (const int*)d_in[4];
    const int*   enz_b    = (const int*)d_in[5];
    const float* latents  = (const float*)d_in[6];
    const float* wq_d     = (const float*)d_in[7];
    const float* bq_d     = (const float*)d_in[8];
    const float* wq_e     = (const float*)d_in[9];
    const float* bq_e     = (const float*)d_in[10];
    const float* mha_d_w  = (const float*)d_in[11];
    const float* mha_d_b  = (const float*)d_in[12];
    const float* mha_d_ow = (const float*)d_in[13];
    const float* mha_d_ob = (const float*)d_in[14];
    const float* mha_e_w  = (const float*)d_in[15];
    const float* mha_e_b  = (const float*)d_in[16];
    const float* mha_e_ow = (const float*)d_in[17];
    const float* mha_e_ob = (const float*)d_in[18];
    const float* ln1_g    = (const float*)d_in[19];
    const float* ln1_b    = (const float*)d_in[20];
    const float* ln2_g    = (const float*)d_in[21];
    const float* ln2_b    = (const float*)d_in[22];
    const float* ffn_w1   = (const float*)d_in[23];
    const float* ffn_b1   = (const float*)d_in[24];
    const float* ffn_w2   = (const float*)d_in[25];
    const float* ffn_b2   = (const float*)d_in[26];
    const float* head_w1  = (const float*)d_in[27];
    const float* head_b1  = (const float*)d_in[28];
    const float* head_w2  = (const float*)d_in[29];
    const float* head_b2  = (const float*)d_in[30];
    float* out = (float*)d_out;

    static int s_attr_set = 0;
    if (!s_attr_set) {
        cudaFuncSetAttribute(attn_kernel, cudaFuncAttributeMaxDynamicSharedMemorySize, ATT_BYTES);
        s_attr_set = 1;
    }

    offsets_kernel<<<3, 256>>>(drug_b, enz_b);
    init_lat_kernel<<<(BB * NLAT * DD + 255) / 256, 256>>>(latents);
    cvt_kernel<<<(NE * DD / 4 + 255) / 256, 256>>>(drug_k, drug_v, enz_k, enz_v);
    pc_P_kernel<<<dim3(32, 4), 256>>>(wq_d, bq_d, wq_e, bq_e, mha_d_w, mha_d_b, mha_e_w, mha_e_b);
    pc_Aq_kernel<<<dim3(32, 4), 256>>>(mha_d_w, mha_e_w);
    pc_Bvo_kernel<<<dim3(32, 4), 256>>>(mha_d_w, mha_d_ow, mha_e_w, mha_e_ow);
    pc_cvo_kernel<<<dim3(2, 4), 128>>>(mha_d_b, mha_d_ow, mha_d_ob, mha_e_b, mha_e_ow, mha_e_ob);

    dim3 gridp(BB, 2);
    for (int l = 0; l < LAYERS; l++) {
        size_t oV = (size_t)l * DD;
        size_t oF1 = (size_t)l * 2 * DD * DD;
        size_t oF1b = (size_t)l * 2 * DD;

        prep_q_kernel<<<gridp, 256>>>(l, ln1_g + oV, ln1_b + oV);
        attn_kernel<<<1024, 256, ATT_BYTES>>>();
        projffn_kernel<<<BB, 256, PF_BYTES>>>(l,
            ln2_g + oV, ln2_b + oV,
            ffn_w1 + oF1, ffn_b1 + oF1b, ffn_w2 + oF1, ffn_b2 + oV);
    }

    head_kernel<<<128, 256>>>(head_w1, head_b1, head_w2, head_b2, out);
}

// round 12
// speedup vs baseline: 2.2626x; 1.0439x over previous
#include <cuda_runtime.h>
#include <cuda_bf16.h>
#include <stdint.h>
#include <math.h>

#define BB 512
#define DD 128
#define NLAT 16
#define NH 4
#define HDIM 32
#define ND 25600
#define NE 153600
#define NPAIR 64
#define LAYERS 4

// scratch (static device globals: allowed)
__device__ float g_lat[BB * NLAT * DD];
__device__ __nv_bfloat16 g_ctxh[BB * NLAT * 1024];       // [b][i*1024 + mod*512 + h*128 + d]
__device__ int   g_starts[2][BB + 1];
__device__ __nv_bfloat16 g_dk[ND * DD];
__device__ __nv_bfloat16 g_dv[ND * DD];
__device__ __nv_bfloat16 g_ek[NE * DD];
__device__ __nv_bfloat16 g_ev[NE * DD];
// composed weights
__device__ __nv_bfloat16 g_Aqt[LAYERS * 2 * 512 * 128];  // [(l,mod)][n=h*128+t'][d]
__device__ float g_cq[LAYERS * 2 * 512];
__device__ __nv_bfloat16 g_Bvo[LAYERS * 128 * 1024];     // [l][t'][k=mod*512+h*128+d]
__device__ float g_cvo[LAYERS * 2 * 128];
// precompute scratch
__device__ float g_P[32 * 32 * 128];
__device__ float g_cb[32 * 32];

__device__ __forceinline__ int lb_dev(const int* __restrict__ a, int n, int key) {
    int lo = 0, hi = n;
    while (lo < hi) { int mid = (lo + hi) >> 1; if (a[mid] < key) lo = mid + 1; else hi = mid; }
    return lo;
}

__global__ void offsets_kernel(const int* __restrict__ db, const int* __restrict__ eb) {
    int i = blockIdx.x * blockDim.x + threadIdx.x;
    if (i <= BB) { g_starts[0][i] = lb_dev(db, ND, i); g_starts[1][i] = lb_dev(eb, NE, i); }
}

__global__ void init_lat_kernel(const float* __restrict__ latents) {
    int i = blockIdx.x * blockDim.x + threadIdx.x;
    if (i < BB * NLAT * DD) g_lat[i] = latents[i & (NLAT * DD - 1)];
}

__device__ __forceinline__ uint32_t f2bf2(float x, float y) {
    __nv_bfloat162 h = __floats2bfloat162_rn(x, y);
    return *reinterpret_cast<uint32_t*>(&h);
}

__global__ void cvt_kernel(const float* __restrict__ dk, const float* __restrict__ dv,
                           const float* __restrict__ ek, const float* __restrict__ ev) {
    int i = blockIdx.x * blockDim.x + threadIdx.x;
    int i4 = i * 4;
    if (i4 < ND * DD) {
        float4 a = *(const float4*)(dk + i4);
        float4 b = *(const float4*)(dv + i4);
        *(uint2*)(g_dk + i4) = make_uint2(f2bf2(a.x, a.y), f2bf2(a.z, a.w));
        *(uint2*)(g_dv + i4) = make_uint2(f2bf2(b.x, b.y), f2bf2(b.z, b.w));
    }
    if (i4 < NE * DD) {
        float4 a = *(const float4*)(ek + i4);
        float4 b = *(const float4*)(ev + i4);
        *(uint2*)(g_ek + i4) = make_uint2(f2bf2(a.x, a.y), f2bf2(a.z, a.w));
        *(uint2*)(g_ev + i4) = make_uint2(f2bf2(b.x, b.y), f2bf2(b.z, b.w));
    }
}

// ---------------- weight composition ----------------
__global__ void __launch_bounds__(256) pc_P_kernel(
    const float* __restrict__ wq_d, const float* __restrict__ bq_d,
    const float* __restrict__ wq_e, const float* __restrict__ bq_e,
    const float* __restrict__ mw_d, const float* __restrict__ mb_d,
    const float* __restrict__ mw_e, const float* __restrict__ mb_e) {
    __shared__ float U_s[32 * 128];
    __shared__ float wq_s[128 * 32];
    int c = blockIdx.x, ds = blockIdx.y, t = threadIdx.x;
    int h = c & 3, m = (c >> 2) & 1, l = c >> 3;
    const float* wq = (m ? wq_e : wq_d) + (size_t)l * DD * DD;
    const float* W  = (m ? mw_e : mw_d) + (size_t)l * 3 * DD * DD;
    for (int i = t; i < 1024; i += 256)
        ((float4*)U_s)[i] = ((const float4*)(W + (size_t)h * 32 * DD))[i];
    for (int i = t; i < 1024; i += 256) {
        int dp = i >> 3, q = i & 7;
        *(float4*)(wq_s + dp * 32 + q * 4) = *(const float4*)(wq + (size_t)dp * 128 + ds * 32 + q * 4);
    }
    __syncthreads();
    int j = t >> 3, dl = (t & 7) * 4;
    float a0 = 0, a1 = 0, a2 = 0, a3 = 0;
    #pragma unroll 8
    for (int dp = 0; dp < 128; dp++) {
        float u = U_s[j * 128 + dp];
        float4 w4 = *(const float4*)(wq_s + dp * 32 + dl);
        a0 = fmaf(u, w4.x, a0); a1 = fmaf(u, w4.y, a1);
        a2 = fmaf(u, w4.z, a2); a3 = fmaf(u, w4.w, a3);
    }
    *(float4*)(g_P + (size_t)c * 4096 + j * 128 + ds * 32 + dl) = make_float4(a0, a1, a2, a3);
    if (ds == 0 && t < 32) {
        const float* bq = (m ? bq_e : bq_d) + l * DD;
        const float* mb = (m ? mb_e : mb_d) + l * 3 * DD;
        float s = 0.0f;
        #pragma unroll 8
        for (int dp = 0; dp < 128; dp++) s += U_s[t * 128 + dp] * bq[dp];
        g_cb[c * 32 + t] = s + mb[h * 32 + t];
    }
}

__global__ void __launch_bounds__(256) pc_Aq_kernel(
    const float* __restrict__ mw_d, const float* __restrict__ mw_e) {
    __shared__ float P_s[32 * 128];
    __shared__ float V_s[32 * 32];
    __shared__ float cb_s[32];
    int c = blockIdx.x, ts = blockIdx.y, t = threadIdx.x;
    int h = c & 3, m = (c >> 2) & 1, l = c >> 3;
    const float* W = (m ? mw_e : mw_d) + (size_t)l * 3 * DD * DD;
    const float* wk = W + (size_t)(DD + h * 32) * DD;
    for (int i = t; i < 1024; i += 256)
        ((float4*)P_s)[i] = ((const float4*)(g_P + (size_t)c * 4096))[i];
    for (int i = t; i < 1024; i += 256) {
        int j = i >> 5, tpl = i & 31;
        V_s[j * 32 + tpl] = wk[(size_t)j * 128 + ts * 32 + tpl];
    }
    if (t < 32) cb_s[t] = g_cb[c * 32 + t];
    __syncthreads();
    const float scale = 0.17677669529663688f;
    int tpl = t >> 3, d0 = (t & 7) * 16;
    float acc[16];
    #pragma unroll
    for (int i = 0; i < 16; i++) acc[i] = 0.0f;
    float cq = 0.0f;
    for (int j = 0; j < 32; j++) {
        float v = V_s[j * 32 + tpl];
        const float4* pr = (const float4*)(P_s + j * 128 + d0);
        #pragma unroll
        for (int q = 0; q < 4; q++) {
            float4 p4 = pr[q];
            acc[q*4+0] = fmaf(v, p4.x, acc[q*4+0]);
            acc[q*4+1] = fmaf(v, p4.y, acc[q*4+1]);
            acc[q*4+2] = fmaf(v, p4.z, acc[q*4+2]);
            acc[q*4+3] = fmaf(v, p4.w, acc[q*4+3]);
        }
        cq += v * cb_s[j];
    }
    int tp = ts * 32 + tpl;
    __nv_bfloat16* dst = g_Aqt + ((size_t)(l * 2 + m) * 512 + h * 128 + tp) * 128 + d0;
    #pragma unroll
    for (int q = 0; q < 8; q++)
        *(uint32_t*)(dst + q * 2) = f2bf2(acc[q*2] * scale, acc[q*2+1] * scale);
    if ((t & 7) == 0) g_cq[(l * 2 + m) * 512 + h * 128 + tp] = cq * scale;
}

__global__ void __launch_bounds__(256) pc_Bvo_kernel(
    const float* __restrict__ mw_d, const float* __restrict__ ow_d,
    const float* __restrict__ mw_e, const float* __restrict__ ow_e) {
    __shared__ float wv_s[32 * 128];
    __shared__ float ow_s[32 * 32];
    int c = blockIdx.x, ts = blockIdx.y, t = threadIdx.x;
    int h = c & 3, m = (c >> 2) & 1, l = c >> 3;
    const float* W  = (m ? mw_e : mw_d) + (size_t)l * 3 * DD * DD;
    const float* ow = (m ? ow_e : ow_d) + (size_t)l * DD * DD;
    for (int i = t; i < 1024; i += 256)
        ((float4*)wv_s)[i] = ((const float4*)(W + (size_t)(2 * DD + h * 32) * DD))[i];
    for (int i = t; i < 1024; i += 256) {
        int tpl = i >> 5, j = i & 31;
        ow_s[tpl * 32 + j] = ow[(size_t)(ts * 32 + tpl) * 128 + h * 32 + j];
    }
    __syncthreads();
    int tpl = t >> 3, d0 = (t & 7) * 16;
    float acc[16];
    #pragma unroll
    for (int i = 0; i < 16; i++) acc[i] = 0.0f;
    for (int j = 0; j < 32; j++) {
        float o = ow_s[tpl * 32 + j];
        const float4* wr = (const float4*)(wv_s + j * 128 + d0);
        #pragma unroll
        for (int q = 0; q < 4; q++) {
            float4 w4 = wr[q];
            acc[q*4+0] = fmaf(o, w4.x, acc[q*4+0]);
            acc[q*4+1] = fmaf(o, w4.y, acc[q*4+1]);
            acc[q*4+2] = fmaf(o, w4.z, acc[q*4+2]);
            acc[q*4+3] = fmaf(o, w4.w, acc[q*4+3]);
        }
    }
    int tp = ts * 32 + tpl;
    __nv_bfloat16* dst = g_Bvo + (size_t)l * DD * 1024 + (size_t)tp * 1024 + m * 512 + h * 128 + d0;
    #pragma unroll
    for (int q = 0; q < 8; q++)
        *(uint32_t*)(dst + q * 2) = f2bf2(acc[q*2], acc[q*2+1]);
}

__global__ void __launch_bounds__(128) pc_cvo_kernel(
    const float* __restrict__ mb_d, const float* __restrict__ ow_d, const float* __restrict__ ob_d,
    const float* __restrict__ mb_e, const float* __restrict__ ow_e, const float* __restrict__ ob_e) {
    __shared__ float bv_s[128];
    int m = blockIdx.x, l = blockIdx.y, t = threadIdx.x;
    const float* ow = (m ? ow_e : ow_d) + (size_t)l * DD * DD;
    const float* ob = (m ? ob_e : ob_d) + l * DD;
    const float* bv = (m ? mb_e : mb_d) + l * 3 * DD + 2 * DD;
    bv_s[t] = bv[t];
    __syncthreads();
    float s = ob[t];
    const float4* owr = (const float4*)(ow + (size_t)t * 128);
    #pragma unroll
    for (int u4 = 0; u4 < 32; u4++) {
        float4 o4 = owr[u4];
        s = fmaf(o4.x, bv_s[u4*4+0], fmaf(o4.y, bv_s[u4*4+1],
            fmaf(o4.z, bv_s[u4*4+2], fmaf(o4.w, bv_s[u4*4+3], s))));
    }
    g_cvo[(l * 2 + m) * 128 + t] = s;
}

// ---------------- common helpers ----------------
__device__ __forceinline__ void layernorm_rows(const float* __restrict__ src,
                                               const float* __restrict__ g,
                                               const float* __restrict__ bta,
                                               float (*dst)[DD], int t, int nthr) {
    int warp = t >> 5, lane = t & 31, nw = nthr >> 5;
    for (int r = warp; r < NLAT; r += nw) {
        float4 v = ((const float4*)(src + r * DD))[lane];
        float s = v.x + v.y + v.z + v.w;
        #pragma unroll
        for (int o = 16; o; o >>= 1) s += __shfl_xor_sync(0xffffffffu, s, o);
        float mean = s * (1.0f / DD);
        float dx = v.x - mean, dy = v.y - mean, dz = v.z - mean, dw = v.w - mean;
        float q = dx * dx + dy * dy + dz * dz + dw * dw;
        #pragma unroll
        for (int o = 16; o; o >>= 1) q += __shfl_xor_sync(0xffffffffu, q, o);
        float rstd = rsqrtf(q * (1.0f / DD) + 1e-5f);
        int c = lane * 4;
        dst[r][c + 0] = dx * rstd * g[c + 0] + bta[c + 0];
        dst[r][c + 1] = dy * rstd * g[c + 1] + bta[c + 1];
        dst[r][c + 2] = dz * rstd * g[c + 2] + bta[c + 2];
        dst[r][c + 3] = dw * rstd * g[c + 3] + bta[c + 3];
    }
}

__device__ __forceinline__ uint32_t s2u(const void* p) {
    return (uint32_t)__cvta_generic_to_shared(p);
}

#define LDSM4(R, addr) asm volatile( \
    "ldmatrix.sync.aligned.m8n8.x4.shared.b16 {%0,%1,%2,%3},[%4];" \
    : "=r"((R)[0]), "=r"((R)[1]), "=r"((R)[2]), "=r"((R)[3]) : "r"(addr))
#define LDSM4T(R, addr) asm volatile( \
    "ldmatrix.sync.aligned.m8n8.x4.trans.shared.b16 {%0,%1,%2,%3},[%4];" \
    : "=r"((R)[0]), "=r"((R)[1]), "=r"((R)[2]), "=r"((R)[3]) : "r"(addr))
#define MMA16816(D, A, B0, B1) asm volatile( \
    "mma.sync.aligned.m16n8k16.row.col.f32.bf16.bf16.f32 " \
    "{%0,%1,%2,%3},{%4,%5,%6,%7},{%8,%9},{%0,%1,%2,%3};" \
    : "+f"((D)[0]), "+f"((D)[1]), "+f"((D)[2]), "+f"((D)[3]) \
    : "r"((A)[0]), "r"((A)[1]), "r"((A)[2]), "r"((A)[3]), "r"(B0), "r"(B1))
#define CP16(dst, src) asm volatile("cp.async.cg.shared.global [%0], [%1], 16;\n" :: "r"(dst), "l"(src))
#define CP_COMMIT() asm volatile("cp.async.commit_group;\n" ::: "memory")
#define CP_WAIT1() asm volatile("cp.async.wait_group 1;\n" ::: "memory")
#define CP_WAIT0() asm volatile("cp.async.wait_group 0;\n" ::: "memory")

// ---------------- fused attention: LN + Q-GEMM prologue + flash attention ----------------
#define KV_ELE (64 * 136)
#define ATT_BYTES (4 * KV_ELE * 2 + 64 * 72 * 2 + 64 * 68 * 4 + 3 * 64 * 4)

__device__ __forceinline__ void issue_chunk(const __nv_bfloat16* __restrict__ Kg,
                                            const __nv_bfloat16* __restrict__ Vg,
                                            __nv_bfloat16* Ksb, __nv_bfloat16* Vsb,
                                            int row0, int nk, int t) {
    #pragma unroll
    for (int i = t; i < 1024; i += 256) {
        int r = i >> 4, seg = (i & 15) * 8;
        if (r < nk) {
            CP16(s2u(Ksb + r * 136 + seg), Kg + (size_t)(row0 + r) * DD + seg);
            CP16(s2u(Vsb + r * 136 + seg), Vg + (size_t)(row0 + r) * DD + seg);
        }
    }
}

// grid 1024: bid<512 -> enzyme first, else drug. 256 threads.
__global__ void __launch_bounds__(256, 2) attn_kernel(int layer,
    const float* __restrict__ lng, const float* __restrict__ lnb) {
    extern __shared__ char smraw[];
    __nv_bfloat16* Ks0 = (__nv_bfloat16*)smraw;
    __nv_bfloat16* Vs0 = Ks0 + 2 * KV_ELE;
    __nv_bfloat16* Ps  = Vs0 + 2 * KV_ELE;
    float* ss  = (float*)(Ps + 64 * 72);
    float* m_s = ss + 64 * 68;
    float* l_s = m_s + 64;
    float* sc_s = l_s + 64;
    // prologue overlays (dead regions during prologue)
    float* nlf = (float*)Ps;                         // 8192B <= 9216B
    __nv_bfloat16* nlh = Vs0 + KV_ELE;               // V buf1, [16][136] = 4352B
    __nv_bfloat16* qts = (__nv_bfloat16*)ss;         // [64][136] = 17408B == sizeof(ss)

    int bid = blockIdx.x, t = threadIdx.x;
    int mod = (bid < 512) ? 1 : 0;
    int b = bid & 511;
    const __nv_bfloat16* Kg = mod ? g_ek : g_dk;
    const __nv_bfloat16* Vg = mod ? g_ev : g_dv;
    int w = t >> 5, lane = t & 31;
    int g = lane >> 2, tc = lane & 3;
    int s0 = g_starts[mod][b];
    int cnt = g_starts[mod][b + 1] - s0;

    int pb = (w & 3) * 16;
    int th = w >> 2;

    // zero all 4 KV buffers (pad rows must be 0)
    for (int i = t; i < (4 * KV_ELE * 2) / 16; i += 256)
        ((uint4*)smraw)[i] = make_uint4(0, 0, 0, 0);
    __syncthreads();

    // kick off chunk 0 loads, then overlap Q-prep with them
    int nchunks = (cnt + 63) >> 6;
    if (nchunks > 0) {
        issue_chunk(Kg, Vg, Ks0, Vs0, s0, min(64, cnt), t);
        CP_COMMIT();
    }

    // ---- prologue: LN + Q-GEMM (qt = LN(lat) @ Aq + cq), result -> qts ----
    layernorm_rows(g_lat + (size_t)b * NLAT * DD, lng, lnb, (float(*)[DD])nlf, t, 256);
    __syncthreads();
    for (int i = t; i < NLAT * DD / 2; i += 256) {
        int r = i >> 6, c = (i & 63) * 2;
        *(uint32_t*)(nlh + r * 136 + c) = f2bf2(nlf[r * DD + c], nlf[r * DD + c + 1]);
    }
    __syncthreads();
    {
        const __nv_bfloat16* Aq = g_Aqt + (size_t)(layer * 2 + mod) * 512 * 128;
        const float* cq = g_cq + (layer * 2 + mod) * 512;
        uint32_t aN = s2u(nlh + (lane & 15) * 136 + (lane >> 4) * 8);
        float acc[8][4];
        #pragma unroll
        for (int i = 0; i < 8; i++)
            #pragma unroll
            for (int j = 0; j < 4; j++) acc[i][j] = 0.0f;
        #pragma unroll
        for (int ks = 0; ks < 8; ks++) {
            uint32_t aA[4];
            LDSM4(aA, aN + ks * 32);
            #pragma unroll
            for (int nt = 0; nt < 8; nt++) {
                int n = w * 64 + nt * 8 + g;
                uint32_t b0 = *(const uint32_t*)(Aq + (size_t)n * 128 + ks * 16 + tc * 2);
                uint32_t b1 = *(const uint32_t*)(Aq + (size_t)n * 128 + ks * 16 + tc * 2 + 8);
                MMA16816(acc[nt], aA, b0, b1);
            }
        }
        // store qt (bf16) into qts[pair][t'] with bias; pair = lat*4 + h
        #pragma unroll
        for (int nt = 0; nt < 8; nt++) {
            int n0 = w * 64 + nt * 8 + tc * 2;
            int h = n0 >> 7, col = n0 & 127;
            float c0v = cq[n0], c1v = cq[n0 + 1];
            *(uint32_t*)(qts + (g * 4 + h) * 136 + col)       = f2bf2(acc[nt][0] + c0v, acc[nt][1] + c1v);
            *(uint32_t*)(qts + ((g + 8) * 4 + h) * 136 + col) = f2bf2(acc[nt][2] + c0v, acc[nt][3] + c1v);
        }
    }
    __syncthreads();
    // load persistent qa A-fragments from qts
    uint32_t qa[8][4];
    {
        uint32_t aQ = s2u(qts + (pb + (lane & 15)) * 136 + (lane >> 4) * 8);
        #pragma unroll
        for (int ks = 0; ks < 8; ks++) LDSM4(qa[ks], aQ + ks * 32);
    }
    if (t < 64) { m_s[t] = -1e30f; l_s[t] = 0.0f; }

    float cx[8][4];
    #pragma unroll
    for (int i = 0; i < 8; i++)
        #pragma unroll
        for (int j = 0; j < 4; j++) cx[i][j] = 0.0f;

    uint32_t aK1 = s2u(Ks0 + (th * 32 + ((lane >> 4) << 3) + (lane & 7)) * 136 + ((lane >> 3) & 1) * 8);
    uint32_t aK2 = aK1 + 16 * 136 * 2;
    uint32_t aP  = s2u(Ps + (pb + (lane & 15)) * 72 + (lane >> 4) * 8);
    uint32_t aV  = s2u(Vs0 + (lane & 15) * 136 + th * 64 + (lane >> 4) * 8);

    for (int k = 0; k < nchunks; k++) {
        int cur = k & 1;
        int nk = min(64, cnt - k * 64);
        if (k + 1 < nchunks) {
            int nk2 = min(64, cnt - (k + 1) * 64);
            issue_chunk(Kg, Vg, Ks0 + (cur ^ 1) * KV_ELE, Vs0 + (cur ^ 1) * KV_ELE,
                        s0 + (k + 1) * 64, nk2, t);
            CP_COMMIT();
            CP_WAIT1();
        } else {
            CP_WAIT0();
        }
        __syncthreads();
        {
            uint32_t kbase1 = aK1 + cur * (KV_ELE * 2);
            uint32_t kbase2 = aK2 + cur * (KV_ELE * 2);
            float sa[4][4];
            #pragma unroll
            for (int j = 0; j < 4; j++)
                #pragma unroll
                for (int q = 0; q < 4; q++) sa[j][q] = 0.0f;
            #pragma unroll
            for (int ks = 0; ks < 8; ks++) {
                uint32_t kb1[4], kb2[4];
                LDSM4(kb1, kbase1 + ks * 32);
                LDSM4(kb2, kbase2 + ks * 32);
                MMA16816(sa[0], qa[ks], kb1[0], kb1[1]);
                MMA16816(sa[1], qa[ks], kb1[2], kb1[3]);
                MMA16816(sa[2], qa[ks], kb2[0], kb2[1]);
                MMA16816(sa[3], qa[ks], kb2[2], kb2[3]);
            }
            int r0 = pb + g, r1 = pb + g + 8;
            #pragma unroll
            for (int j = 0; j < 4; j++) {
                int c0 = th * 32 + j * 8 + tc * 2;
                *(float2*)&ss[r0 * 68 + c0] = make_float2(sa[j][0], sa[j][1]);
                *(float2*)&ss[r1 * 68 + c0] = make_float2(sa[j][2], sa[j][3]);
            }
        }
        __syncthreads();
        {
            int p = t >> 2, sub = t & 3;
            int k0 = sub * 16;
            float mo = m_s[p];
            float cm = -1e30f;
            #pragma unroll 4
            for (int kk = k0; kk < k0 + 16; kk++) {
                float v = (kk < nk) ? ss[p * 68 + kk] : -1e30f;
                cm = fmaxf(cm, v);
            }
            cm = fmaxf(cm, __shfl_xor_sync(0xffffffffu, cm, 1));
            cm = fmaxf(cm, __shfl_xor_sync(0xffffffffu, cm, 2));
            cm = fmaxf(cm, mo);
            float sum = 0.0f;
            #pragma unroll 4
            for (int kk = k0; kk < k0 + 16; kk++) {
                float e = (kk < nk) ? __expf(ss[p * 68 + kk] - cm) : 0.0f;
                Ps[p * 72 + kk] = __float2bfloat16(e);
                sum += e;
            }
            sum += __shfl_xor_sync(0xffffffffu, sum, 1);
            sum += __shfl_xor_sync(0xffffffffu, sum, 2);
            if (sub == 0) {
                float scl = __expf(mo - cm);
                l_s[p] = l_s[p] * scl + sum;
                m_s[p] = cm;
                sc_s[p] = scl;
            }
        }
        __syncthreads();
        {
            uint32_t vbase = aV + cur * (KV_ELE * 2);
            float sc0 = sc_s[pb + g], sc1 = sc_s[pb + g + 8];
            #pragma unroll
            for (int nt = 0; nt < 8; nt++) {
                cx[nt][0] *= sc0; cx[nt][1] *= sc0;
                cx[nt][2] *= sc1; cx[nt][3] *= sc1;
            }
            #pragma unroll
            for (int ks = 0; ks < 4; ks++) {
                uint32_t pa[4];
                LDSM4(pa, aP + ks * 32);
                #pragma unroll
                for (int ntp = 0; ntp < 4; ntp++) {
                    uint32_t vb[4];
                    LDSM4T(vb, vbase + ks * 4352 + ntp * 32);
                    MMA16816(cx[ntp * 2 + 0], pa, vb[0], vb[1]);
                    MMA16816(cx[ntp * 2 + 1], pa, vb[2], vb[3]);
                }
            }
        }
        __syncthreads();
    }
    int r0 = pb + g, r1 = pb + g + 8;
    float l0 = l_s[r0], l1 = l_s[r1];
    float i0 = (l0 > 0.0f) ? 1.0f / l0 : 0.0f;
    float i1 = (l1 > 0.0f) ? 1.0f / l1 : 0.0f;
    __nv_bfloat16* cbp = g_ctxh + (size_t)b * 16384;
    int base0 = (r0 >> 2) * 1024 + mod * 512 + (r0 & 3) * 128;
    int base1 = (r1 >> 2) * 1024 + mod * 512 + (r1 & 3) * 128;
    #pragma unroll
    for (int nt = 0; nt < 8; nt++) {
        int d0 = th * 64 + nt * 8 + tc * 2;
        *(uint32_t*)(cbp + base0 + d0) = f2bf2(cx[nt][0] * i0, cx[nt][1] * i0);
        *(uint32_t*)(cbp + base1 + d0) = f2bf2(cx[nt][2] * i1, cx[nt][3] * i1);
    }
}

// ---------------- fused: VO GEMM (bf16 TC) + residual + LN2 + FFN (fp32) ----------------
#define PF_BYTES (33024 + 8192)

__global__ void __launch_bounds__(256) projffn_kernel(int layer,
    const float* __restrict__ lng, const float* __restrict__ lnb,
    const float* __restrict__ w1, const float* __restrict__ b1,
    const float* __restrict__ w2, const float* __restrict__ b2) {
    extern __shared__ char dsm[];
    __nv_bfloat16* ctxs = (__nv_bfloat16*)dsm;      // [16][1032]
    float* pool = (float*)dsm;                       // after GEMM: nl @0, hid @2048 floats
    float* latv = (float*)(dsm + 33024);             // [16][128]
    int b = blockIdx.x, t = threadIdx.x;
    int w = t >> 5, lane = t & 31, g = lane >> 2, tc = lane & 3;
    int half = t >> 7, tt = t & 127;

    {
        const uint4* src = (const uint4*)(g_ctxh + (size_t)b * 16384);
        for (int i = t; i < 2048; i += 256) {
            int r = i >> 7, c8 = i & 127;
            *(uint4*)(ctxs + r * 1032 + c8 * 8) = src[i];
        }
        const float4* lsrc = (const float4*)(g_lat + (size_t)b * NLAT * DD);
        for (int i = t; i < 512; i += 256) ((float4*)latv)[i] = lsrc[i];
    }
    __syncthreads();
    {
        const __nv_bfloat16* Bvop = g_Bvo + (size_t)layer * DD * 1024;
        const float* cvo0 = g_cvo + (layer * 2 + 0) * 128;
        const float* cvo1 = g_cvo + (layer * 2 + 1) * 128;
        uint32_t aC = s2u(ctxs + (lane & 15) * 1032 + (lane >> 4) * 8);
        float acc[2][4];
        #pragma unroll
        for (int i = 0; i < 2; i++)
            #pragma unroll
            for (int j = 0; j < 4; j++) acc[i][j] = 0.0f;
        #pragma unroll 4
        for (int ks = 0; ks < 64; ks++) {
            uint32_t aA[4];
            LDSM4(aA, aC + ks * 32);
            #pragma unroll
            for (int nt = 0; nt < 2; nt++) {
                int n = w * 16 + nt * 8 + g;
                uint32_t b0 = *(const uint32_t*)(Bvop + (size_t)n * 1024 + ks * 16 + tc * 2);
                uint32_t b1 = *(const uint32_t*)(Bvop + (size_t)n * 1024 + ks * 16 + tc * 2 + 8);
                MMA16816(acc[nt], aA, b0, b1);
            }
        }
        __syncthreads();
        #pragma unroll
        for (int nt = 0; nt < 2; nt++) {
            int n0 = w * 16 + nt * 8 + tc * 2;
            float c0v = cvo0[n0] + cvo1[n0];
            float c1v = cvo0[n0 + 1] + cvo1[n0 + 1];
            latv[g * 128 + n0]           += acc[nt][0] + c0v;
            latv[g * 128 + n0 + 1]       += acc[nt][1] + c1v;
            latv[(g + 8) * 128 + n0]     += acc[nt][2] + c0v;
            latv[(g + 8) * 128 + n0 + 1] += acc[nt][3] + c1v;
        }
    }
    __syncthreads();
    layernorm_rows(latv, lng, lnb, (float(*)[DD])pool, t, 256);
    __syncthreads();
    {
        float acc[NLAT];
        float bv = b1[t];
        #pragma unroll
        for (int i = 0; i < NLAT; i++) acc[i] = bv;
        const float4* wp = (const float4*)(w1 + (size_t)t * DD);
        #pragma unroll 2
        for (int d4 = 0; d4 < DD / 4; d4++) {
            float4 w4 = wp[d4];
            #pragma unroll
            for (int i = 0; i < NLAT; i++) {
                float4 n4 = *(const float4*)(pool + i * DD + d4 * 4);
                acc[i] = fmaf(n4.x, w4.x, fmaf(n4.y, w4.y, fmaf(n4.z, w4.z, fmaf(n4.w, w4.w, acc[i]))));
            }
        }
        __syncthreads();
        #pragma unroll
        for (int i = 0; i < NLAT; i++) pool[2048 + i * 256 + t] = fmaxf(acc[i], 0.0f);
    }
    __syncthreads();
    {
        float* latb = g_lat + (size_t)b * NLAT * DD;
        float acc[8];
        float bv = b2[tt];
        #pragma unroll
        for (int j = 0; j < 8; j++) acc[j] = bv;
        const float4* wp = (const float4*)(w2 + (size_t)tt * 2 * DD);
        #pragma unroll 2
        for (int u4 = 0; u4 < 2 * DD / 4; u4++) {
            float4 w4 = wp[u4];
            #pragma unroll
            for (int j = 0; j < 8; j++) {
                float4 h4 = *(const float4*)(pool + 2048 + (half * 8 + j) * 256 + u4 * 4);
                acc[j] = fmaf(h4.x, w4.x, fmaf(h4.y, w4.y, fmaf(h4.z, w4.z, fmaf(h4.w, w4.w, acc[j]))));
            }
        }
        #pragma unroll
        for (int j = 0; j < 8; j++) {
            int idx = (half * 8 + j) * DD + tt;
            latb[idx] = latv[idx] + acc[j];
        }
    }
}

// ---------------- head: grid 128, 4 batches/block ----------------
__global__ void __launch_bounds__(256) head_kernel(
    const float* __restrict__ w1, const float* __restrict__ b1,
    const float* __restrict__ w2, const float* __restrict__ b2,
    float* __restrict__ out) {
    __shared__ float flat_s[4][2048];
    __shared__ float hs[4][128];
    int blk = blockIdx.x, t = threadIdx.x;
    int b0 = blk * 4;
    const float4* src = (const float4*)(g_lat + (size_t)b0 * NLAT * DD);
    for (int i = t; i < 2048; i += 256) ((float4*)flat_s)[i] = src[i];
    __syncthreads();
    int tt = t & 127, bh = t >> 7;
    float acc0 = b1[tt], acc1 = acc0;
    const float4* w1r = (const float4*)(w1 + (size_t)tt * NLAT * DD);
    const float4* f0 = (const float4*)flat_s[bh * 2];
    const float4* f1 = (const float4*)flat_s[bh * 2 + 1];
    #pragma unroll 8
    for (int u4 = 0; u4 < 512; u4++) {
        float4 w4 = w1r[u4];
        float4 a4 = f0[u4];
        float4 c4 = f1[u4];
        acc0 = fmaf(w4.x, a4.x, fmaf(w4.y, a4.y, fmaf(w4.z, a4.z, fmaf(w4.w, a4.w, acc0))));
        acc1 = fmaf(w4.x, c4.x, fmaf(w4.y, c4.y, fmaf(w4.z, c4.z, fmaf(w4.w, c4.w, acc1))));
    }
    hs[bh * 2][tt] = fmaxf(acc0, 0.0f);
    hs[bh * 2 + 1][tt] = fmaxf(acc1, 0.0f);
    __syncthreads();
    int w = t >> 5, lane = t & 31;
    if (w < 4) {
        float s = 0.0f;
        #pragma unroll
        for (int q = 0; q < 4; q++) {
            int idx = q * 32 + lane;
            s += hs[w][idx] * w2[idx];
        }
        #pragma unroll
        for (int o = 16; o; o >>= 1) s += __shfl_xor_sync(0xffffffffu, s, o);
        if (lane == 0) {
            float x = s + b2[0];
            out[b0 + w] = (x > 20.0f) ? x : log1pf(__expf(x));
        }
    }
}

extern "C" void kernel_launch(void* const* d_in, const int* in_sizes, int n_in,
                              void* d_out, int out_size) {
    const float* drug_k   = (const float*)d_in[0];
    const float* drug_v   = (const float*)d_in[1];
    const float* enz_k    = (const float*)d_in[2];
    const float* enz_v    = (const float*)d_in[3];
    const int*   drug_b   = (const int*)d_in[4];
    const int*   enz_b    = (const int*)d_in[5];
    const float* latents  = (const float*)d_in[6];
    const float* wq_d     = (const float*)d_in[7];
    const float* bq_d     = (const float*)d_in[8];
    const float* wq_e     = (const float*)d_in[9];
    const float* bq_e     = (const float*)d_in[10];
    const float* mha_d_w  = (const float*)d_in[11];
    const float* mha_d_b  = (const float*)d_in[12];
    const float* mha_d_ow = (const float*)d_in[13];
    const float* mha_d_ob = (const float*)d_in[14];
    const float* mha_e_w  = (const float*)d_in[15];
    const float* mha_e_b  = (const float*)d_in[16];
    const float* mha_e_ow = (const float*)d_in[17];
    const float* mha_e_ob = (const float*)d_in[18];
    const float* ln1_g    = (const float*)d_in[19];
    const float* ln1_b    = (const float*)d_in[20];
    const float* ln2_g    = (const float*)d_in[21];
    const float* ln2_b    = (const float*)d_in[22];
    const float* ffn_w1   = (const float*)d_in[23];
    const float* ffn_b1   = (const float*)d_in[24];
    const float* ffn_w2   = (const float*)d_in[25];
    const float* ffn_b2   = (const float*)d_in[26];
    const float* head_w1  = (const float*)d_in[27];
    const float* head_b1  = (const float*)d_in[28];
    const float* head_w2  = (const float*)d_in[29];
    const float* head_b2  = (const float*)d_in[30];
    float* out = (float*)d_out;

    static int s_attr_set = 0;
    if (!s_attr_set) {
        cudaFuncSetAttribute(attn_kernel, cudaFuncAttributeMaxDynamicSharedMemorySize, ATT_BYTES);
        s_attr_set = 1;
    }

    offsets_kernel<<<3, 256>>>(drug_b, enz_b);
    init_lat_kernel<<<(BB * NLAT * DD + 255) / 256, 256>>>(latents);
    cvt_kernel<<<(NE * DD / 4 + 255) / 256, 256>>>(drug_k, drug_v, enz_k, enz_v);
    pc_P_kernel<<<dim3(32, 4), 256>>>(wq_d, bq_d, wq_e, bq_e, mha_d_w, mha_d_b, mha_e_w, mha_e_b);
    pc_Aq_kernel<<<dim3(32, 4), 256>>>(mha_d_w, mha_e_w);
    pc_Bvo_kernel<<<dim3(32, 4), 256>>>(mha_d_w, mha_d_ow, mha_e_w, mha_e_ow);
    pc_cvo_kernel<<<dim3(2, 4), 128>>>(mha_d_b, mha_d_ow, mha_d_ob, mha_e_b, mha_e_ow, mha_e_ob);

    for (int l = 0; l < LAYERS; l++) {
        size_t oV = (size_t)l * DD;
        size_t oF1 = (size_t)l * 2 * DD * DD;
        size_t oF1b = (size_t)l * 2 * DD;

        attn_kernel<<<1024, 256, ATT_BYTES>>>(l, ln1_g + oV, ln1_b + oV);
        projffn_kernel<<<BB, 256, PF_BYTES>>>(l,
            ln2_g + oV, ln2_b + oV,
            ffn_w1 + oF1, ffn_b1 + oF1b, ffn_w2 + oF1, ffn_b2 + oV);
    }

    head_kernel<<<128, 256>>>(head_w1, head_b1, head_w2, head_b2, out);
}

// round 13
// speedup vs baseline: 3.9627x; 1.7514x over previous
#include <cuda_runtime.h>
#include <cuda_bf16.h>
#include <stdint.h>
#include <math.h>

#define BB 512
#define DD 128
#define NLAT 16
#define NH 4
#define HDIM 32
#define ND 25600
#define NE 153600
#define NPAIR 64
#define LAYERS 4

// scratch (static device globals: allowed)
__device__ float g_lat[BB * NLAT * DD];
__device__ __nv_bfloat16 g_ctxh[BB * NLAT * 1024];       // [b][i*1024 + mod*512 + h*128 + d]
__device__ int   g_starts[2][BB + 1];
__device__ __nv_bfloat16 g_dk[ND * DD];
__device__ __nv_bfloat16 g_dv[ND * DD];
__device__ __nv_bfloat16 g_ek[NE * DD];
__device__ __nv_bfloat16 g_ev[NE * DD];
// composed weights, MMA B-fragment packed: [n_tile][kstep][lane][2 words]
__device__ uint32_t g_AqP[LAYERS * 2 * 32768];   // n=512 (64 tiles), k=128 (8 ksteps)
__device__ float g_cq[LAYERS * 2 * 512];
__device__ uint32_t g_BvoP[LAYERS * 65536];      // n=128 (16 tiles), k=1024 (64 ksteps)
__device__ float g_cvo[LAYERS * 2 * 128];
__device__ uint32_t g_w1P[LAYERS * 16384];       // n=256 (32 tiles), k=128 (8 ksteps)
__device__ uint32_t g_w2P[LAYERS * 16384];       // n=128 (16 tiles), k=256 (16 ksteps)
// precompute scratch
__device__ float g_P[32 * 32 * 128];
__device__ float g_cb[32 * 32];

__device__ __forceinline__ int lb_dev(const int* __restrict__ a, int n, int key) {
    int lo = 0, hi = n;
    while (lo < hi) { int mid = (lo + hi) >> 1; if (a[mid] < key) lo = mid + 1; else hi = mid; }
    return lo;
}

__global__ void offsets_kernel(const int* __restrict__ db, const int* __restrict__ eb) {
    int i = blockIdx.x * blockDim.x + threadIdx.x;
    if (i <= BB) { g_starts[0][i] = lb_dev(db, ND, i); g_starts[1][i] = lb_dev(eb, NE, i); }
}

__global__ void init_lat_kernel(const float* __restrict__ latents) {
    int i = blockIdx.x * blockDim.x + threadIdx.x;
    if (i < BB * NLAT * DD) g_lat[i] = latents[i & (NLAT * DD - 1)];
}

__device__ __forceinline__ uint32_t f2bf2(float x, float y) {
    __nv_bfloat162 h = __floats2bfloat162_rn(x, y);
    return *reinterpret_cast<uint32_t*>(&h);
}

__global__ void cvt_kernel(const float* __restrict__ dk, const float* __restrict__ dv,
                           const float* __restrict__ ek, const float* __restrict__ ev) {
    int i = blockIdx.x * blockDim.x + threadIdx.x;
    int i4 = i * 4;
    if (i4 < ND * DD) {
        float4 a = *(const float4*)(dk + i4);
        float4 b = *(const float4*)(dv + i4);
        *(uint2*)(g_dk + i4) = make_uint2(f2bf2(a.x, a.y), f2bf2(a.z, a.w));
        *(uint2*)(g_dv + i4) = make_uint2(f2bf2(b.x, b.y), f2bf2(b.z, b.w));
    }
    if (i4 < NE * DD) {
        float4 a = *(const float4*)(ek + i4);
        float4 b = *(const float4*)(ev + i4);
        *(uint2*)(g_ek + i4) = make_uint2(f2bf2(a.x, a.y), f2bf2(a.z, a.w));
        *(uint2*)(g_ev + i4) = make_uint2(f2bf2(b.x, b.y), f2bf2(b.z, b.w));
    }
}

// frag scatter: element (n, k_in pair j) -> lane = (n&7)*4 + (j&3), word = j>>2
__device__ __forceinline__ void frag_store8(uint32_t* base32, int n_in, const float* acc, float scl) {
    #pragma unroll
    for (int j = 0; j < 8; j++) {
        int lane = n_in * 4 + (j & 3);
        int word = j >> 2;
        base32[lane * 2 + word] = f2bf2(acc[2 * j] * scl, acc[2 * j + 1] * scl);
    }
}

// ---------------- weight composition ----------------
__global__ void __launch_bounds__(256) pc_P_kernel(
    const float* __restrict__ wq_d, const float* __restrict__ bq_d,
    const float* __restrict__ wq_e, const float* __restrict__ bq_e,
    const float* __restrict__ mw_d, const float* __restrict__ mb_d,
    const float* __restrict__ mw_e, const float* __restrict__ mb_e) {
    __shared__ float U_s[32 * 128];
    __shared__ float wq_s[128 * 32];
    int c = blockIdx.x, ds = blockIdx.y, t = threadIdx.x;
    int h = c & 3, m = (c >> 2) & 1, l = c >> 3;
    const float* wq = (m ? wq_e : wq_d) + (size_t)l * DD * DD;
    const float* W  = (m ? mw_e : mw_d) + (size_t)l * 3 * DD * DD;
    for (int i = t; i < 1024; i += 256)
        ((float4*)U_s)[i] = ((const float4*)(W + (size_t)h * 32 * DD))[i];
    for (int i = t; i < 1024; i += 256) {
        int dp = i >> 3, q = i & 7;
        *(float4*)(wq_s + dp * 32 + q * 4) = *(const float4*)(wq + (size_t)dp * 128 + ds * 32 + q * 4);
    }
    __syncthreads();
    int j = t >> 3, dl = (t & 7) * 4;
    float a0 = 0, a1 = 0, a2 = 0, a3 = 0;
    #pragma unroll 8
    for (int dp = 0; dp < 128; dp++) {
        float u = U_s[j * 128 + dp];
        float4 w4 = *(const float4*)(wq_s + dp * 32 + dl);
        a0 = fmaf(u, w4.x, a0); a1 = fmaf(u, w4.y, a1);
        a2 = fmaf(u, w4.z, a2); a3 = fmaf(u, w4.w, a3);
    }
    *(float4*)(g_P + (size_t)c * 4096 + j * 128 + ds * 32 + dl) = make_float4(a0, a1, a2, a3);
    if (ds == 0 && t < 32) {
        const float* bq = (m ? bq_e : bq_d) + l * DD;
        const float* mb = (m ? mb_e : mb_d) + l * 3 * DD;
        float s = 0.0f;
        #pragma unroll 8
        for (int dp = 0; dp < 128; dp++) s += U_s[t * 128 + dp] * bq[dp];
        g_cb[c * 32 + t] = s + mb[h * 32 + t];
    }
}

__global__ void __launch_bounds__(256) pc_Aq_kernel(
    const float* __restrict__ mw_d, const float* __restrict__ mw_e) {
    __shared__ float P_s[32 * 128];
    __shared__ float V_s[32 * 32];
    __shared__ float cb_s[32];
    int c = blockIdx.x, ts = blockIdx.y, t = threadIdx.x;
    int h = c & 3, m = (c >> 2) & 1, l = c >> 3;
    const float* W = (m ? mw_e : mw_d) + (size_t)l * 3 * DD * DD;
    const float* wk = W + (size_t)(DD + h * 32) * DD;
    for (int i = t; i < 1024; i += 256)
        ((float4*)P_s)[i] = ((const float4*)(g_P + (size_t)c * 4096))[i];
    for (int i = t; i < 1024; i += 256) {
        int j = i >> 5, tpl = i & 31;
        V_s[j * 32 + tpl] = wk[(size_t)j * 128 + ts * 32 + tpl];
    }
    if (t < 32) cb_s[t] = g_cb[c * 32 + t];
    __syncthreads();
    const float scale = 0.17677669529663688f;
    int tpl = t >> 3, d0 = (t & 7) * 16;
    float acc[16];
    #pragma unroll
    for (int i = 0; i < 16; i++) acc[i] = 0.0f;
    float cq = 0.0f;
    for (int j = 0; j < 32; j++) {
        float v = V_s[j * 32 + tpl];
        const float4* pr = (const float4*)(P_s + j * 128 + d0);
        #pragma unroll
        for (int q = 0; q < 4; q++) {
            float4 p4 = pr[q];
            acc[q*4+0] = fmaf(v, p4.x, acc[q*4+0]);
            acc[q*4+1] = fmaf(v, p4.y, acc[q*4+1]);
            acc[q*4+2] = fmaf(v, p4.z, acc[q*4+2]);
            acc[q*4+3] = fmaf(v, p4.w, acc[q*4+3]);
        }
        cq += v * cb_s[j];
    }
    int n = ts * 32 + tpl;                 // output column 0..511 within (l,mod)
    int n_t = n >> 3, n_in = n & 7, ks = t & 7;
    uint32_t* base = g_AqP + (size_t)(l * 2 + m) * 32768 + (size_t)(n_t * 8 + ks) * 64;
    frag_store8(base, n_in, acc, scale);
    if ((t & 7) == 0) g_cq[(l * 2 + m) * 512 + n] = cq * scale;
}

__global__ void __launch_bounds__(256) pc_Bvo_kernel(
    const float* __restrict__ mw_d, const float* __restrict__ ow_d,
    const float* __restrict__ mw_e, const float* __restrict__ ow_e) {
    __shared__ float wv_s[32 * 128];
    __shared__ float ow_s[32 * 32];
    int c = blockIdx.x, ts = blockIdx.y, t = threadIdx.x;
    int h = c & 3, m = (c >> 2) & 1, l = c >> 3;
    const float* W  = (m ? mw_e : mw_d) + (size_t)l * 3 * DD * DD;
    const float* ow = (m ? ow_e : ow_d) + (size_t)l * DD * DD;
    for (int i = t; i < 1024; i += 256)
        ((float4*)wv_s)[i] = ((const float4*)(W + (size_t)(2 * DD + h * 32) * DD))[i];
    for (int i = t; i < 1024; i += 256) {
        int tpl = i >> 5, j = i & 31;
        ow_s[tpl * 32 + j] = ow[(size_t)(ts * 32 + tpl) * 128 + h * 32 + j];
    }
    __syncthreads();
    int tpl = t >> 3, d0 = (t & 7) * 16;
    float acc[16];
    #pragma unroll
    for (int i = 0; i < 16; i++) acc[i] = 0.0f;
    for (int j = 0; j < 32; j++) {
        float o = ow_s[tpl * 32 + j];
        const float4* wr = (const float4*)(wv_s + j * 128 + d0);
        #pragma unroll
        for (int q = 0; q < 4; q++) {
            float4 w4 = wr[q];
            acc[q*4+0] = fmaf(o, w4.x, acc[q*4+0]);
            acc[q*4+1] = fmaf(o, w4.y, acc[q*4+1]);
            acc[q*4+2] = fmaf(o, w4.z, acc[q*4+2]);
            acc[q*4+3] = fmaf(o, w4.w, acc[q*4+3]);
        }
    }
    int n = ts * 32 + tpl;                 // output row 0..127
    int kk0 = m * 512 + h * 128 + d0;      // k position 0..1023 (16-aligned)
    int n_t = n >> 3, n_in = n & 7, ks = kk0 >> 4;
    uint32_t* base = g_BvoP + (size_t)l * 65536 + (size_t)(n_t * 64 + ks) * 64;
    frag_store8(base, n_in, acc, 1.0f);
}

__global__ void __launch_bounds__(128) pc_cvo_kernel(
    const float* __restrict__ mb_d, const float* __restrict__ ow_d, const float* __restrict__ ob_d,
    const float* __restrict__ mb_e, const float* __restrict__ ow_e, const float* __restrict__ ob_e) {
    __shared__ float bv_s[128];
    int m = blockIdx.x, l = blockIdx.y, t = threadIdx.x;
    const float* ow = (m ? ow_e : ow_d) + (size_t)l * DD * DD;
    const float* ob = (m ? ob_e : ob_d) + l * DD;
    const float* bv = (m ? mb_e : mb_d) + l * 3 * DD + 2 * DD;
    bv_s[t] = bv[t];
    __syncthreads();
    float s = ob[t];
    const float4* owr = (const float4*)(ow + (size_t)t * 128);
    #pragma unroll
    for (int u4 = 0; u4 < 32; u4++) {
        float4 o4 = owr[u4];
        s = fmaf(o4.x, bv_s[u4*4+0], fmaf(o4.y, bv_s[u4*4+1],
            fmaf(o4.z, bv_s[u4*4+2], fmaf(o4.w, bv_s[u4*4+3], s))));
    }
    g_cvo[(l * 2 + m) * 128 + t] = s;
}

// pack FFN weights to bf16 frags. grid LAYERS, 256 thr.
__global__ void __launch_bounds__(256) pc_ffn_kernel(
    const float* __restrict__ w1, const float* __restrict__ w2) {
    int l = blockIdx.x, t = threadIdx.x;
    // w1: n = t (0..255), k = 0..127
    {
        const float* src = w1 + (size_t)l * 2 * DD * DD + (size_t)t * DD;
        int n_t = t >> 3, n_in = t & 7;
        for (int ks = 0; ks < 8; ks++) {
            float v[16];
            #pragma unroll
            for (int q = 0; q < 4; q++) {
                float4 f = *(const float4*)(src + ks * 16 + q * 4);
                v[q*4+0] = f.x; v[q*4+1] = f.y; v[q*4+2] = f.z; v[q*4+3] = f.w;
            }
            uint32_t* base = g_w1P + (size_t)l * 16384 + (size_t)(n_t * 8 + ks) * 64;
            frag_store8(base, n_in, v, 1.0f);
        }
    }
    // w2: n = t&127, ks-half = t>>7
    {
        int n = t & 127, half = t >> 7;
        const float* src = w2 + (size_t)l * DD * 2 * DD + (size_t)n * 2 * DD;
        int n_t = n >> 3, n_in = n & 7;
        for (int kk = 0; kk < 8; kk++) {
            int ks = half * 8 + kk;
            float v[16];
            #pragma unroll
            for (int q = 0; q < 4; q++) {
                float4 f = *(const float4*)(src + ks * 16 + q * 4);
                v[q*4+0] = f.x; v[q*4+1] = f.y; v[q*4+2] = f.z; v[q*4+3] = f.w;
            }
            uint32_t* base = g_w2P + (size_t)l * 16384 + (size_t)(n_t * 16 + ks) * 64;
            frag_store8(base, n_in, v, 1.0f);
        }
    }
}

// ---------------- common helpers ----------------
__device__ __forceinline__ void layernorm_rows(const float* __restrict__ src,
                                               const float* __restrict__ g,
                                               const float* __restrict__ bta,
                                               float (*dst)[DD], int t, int nthr) {
    int warp = t >> 5, lane = t & 31, nw = nthr >> 5;
    for (int r = warp; r < NLAT; r += nw) {
        float4 v = ((const float4*)(src + r * DD))[lane];
        float s = v.x + v.y + v.z + v.w;
        #pragma unroll
        for (int o = 16; o; o >>= 1) s += __shfl_xor_sync(0xffffffffu, s, o);
        float mean = s * (1.0f / DD);
        float dx = v.x - mean, dy = v.y - mean, dz = v.z - mean, dw = v.w - mean;
        float q = dx * dx + dy * dy + dz * dz + dw * dw;
        #pragma unroll
        for (int o = 16; o; o >>= 1) q += __shfl_xor_sync(0xffffffffu, q, o);
        float rstd = rsqrtf(q * (1.0f / DD) + 1e-5f);
        int c = lane * 4;
        dst[r][c + 0] = dx * rstd * g[c + 0] + bta[c + 0];
        dst[r][c + 1] = dy * rstd * g[c + 1] + bta[c + 1];
        dst[r][c + 2] = dz * rstd * g[c + 2] + bta[c + 2];
        dst[r][c + 3] = dw * rstd * g[c + 3] + bta[c + 3];
    }
}

__device__ __forceinline__ uint32_t s2u(const void* p) {
    return (uint32_t)__cvta_generic_to_shared(p);
}

#define LDSM4(R, addr) asm volatile( \
    "ldmatrix.sync.aligned.m8n8.x4.shared.b16 {%0,%1,%2,%3},[%4];" \
    : "=r"((R)[0]), "=r"((R)[1]), "=r"((R)[2]), "=r"((R)[3]) : "r"(addr))
#define LDSM4T(R, addr) asm volatile( \
    "ldmatrix.sync.aligned.m8n8.x4.trans.shared.b16 {%0,%1,%2,%3},[%4];" \
    : "=r"((R)[0]), "=r"((R)[1]), "=r"((R)[2]), "=r"((R)[3]) : "r"(addr))
#define MMA16816(D, A, B0, B1) asm volatile( \
    "mma.sync.aligned.m16n8k16.row.col.f32.bf16.bf16.f32 " \
    "{%0,%1,%2,%3},{%4,%5,%6,%7},{%8,%9},{%0,%1,%2,%3};" \
    : "+f"((D)[0]), "+f"((D)[1]), "+f"((D)[2]), "+f"((D)[3]) \
    : "r"((A)[0]), "r"((A)[1]), "r"((A)[2]), "r"((A)[3]), "r"(B0), "r"(B1))
#define CP16(dst, src) asm volatile("cp.async.cg.shared.global [%0], [%1], 16;\n" :: "r"(dst), "l"(src))
#define CP_COMMIT() asm volatile("cp.async.commit_group;\n" ::: "memory")
#define CP_WAIT1() asm volatile("cp.async.wait_group 1;\n" ::: "memory")
#define CP_WAIT0() asm volatile("cp.async.wait_group 0;\n" ::: "memory")

// ---------------- fused attention: LN + Q-GEMM prologue + flash attention ----------------
#define KV_ELE (64 * 136)
#define ATT_BYTES (4 * KV_ELE * 2 + 64 * 72 * 2 + 64 * 68 * 4 + 3 * 64 * 4)

__device__ __forceinline__ void issue_chunk(const __nv_bfloat16* __restrict__ Kg,
                                            const __nv_bfloat16* __restrict__ Vg,
                                            __nv_bfloat16* Ksb, __nv_bfloat16* Vsb,
                                            int row0, int nk, int t) {
    #pragma unroll
    for (int i = t; i < 1024; i += 256) {
        int r = i >> 4, seg = (i & 15) * 8;
        if (r < nk) {
            CP16(s2u(Ksb + r * 136 + seg), Kg + (size_t)(row0 + r) * DD + seg);
            CP16(s2u(Vsb + r * 136 + seg), Vg + (size_t)(row0 + r) * DD + seg);
        }
    }
}

// grid 1024: bid<512 -> enzyme first, else drug. 256 threads.
__global__ void __launch_bounds__(256, 2) attn_kernel(int layer,
    const float* __restrict__ lng, const float* __restrict__ lnb) {
    extern __shared__ char smraw[];
    __nv_bfloat16* Ks0 = (__nv_bfloat16*)smraw;
    __nv_bfloat16* Vs0 = Ks0 + 2 * KV_ELE;
    __nv_bfloat16* Ps  = Vs0 + 2 * KV_ELE;
    float* ss  = (float*)(Ps + 64 * 72);
    float* m_s = ss + 64 * 68;
    float* l_s = m_s + 64;
    float* sc_s = l_s + 64;
    // prologue overlays
    float* nlf = (float*)Ps;
    __nv_bfloat16* nlh = Vs0 + KV_ELE;
    __nv_bfloat16* qts = (__nv_bfloat16*)ss;

    int bid = blockIdx.x, t = threadIdx.x;
    int mod = (bid < 512) ? 1 : 0;
    int b = bid & 511;
    const __nv_bfloat16* Kg = mod ? g_ek : g_dk;
    const __nv_bfloat16* Vg = mod ? g_ev : g_dv;
    int w = t >> 5, lane = t & 31;
    int g = lane >> 2, tc = lane & 3;
    int s0 = g_starts[mod][b];
    int cnt = g_starts[mod][b + 1] - s0;

    int pb = (w & 3) * 16;
    int th = w >> 2;

    for (int i = t; i < (4 * KV_ELE * 2) / 16; i += 256)
        ((uint4*)smraw)[i] = make_uint4(0, 0, 0, 0);
    __syncthreads();

    int nchunks = (cnt + 63) >> 6;
    if (nchunks > 0) {
        issue_chunk(Kg, Vg, Ks0, Vs0, s0, min(64, cnt), t);
        CP_COMMIT();
    }

    // prologue: LN + Q-GEMM (packed Aq frags)
    layernorm_rows(g_lat + (size_t)b * NLAT * DD, lng, lnb, (float(*)[DD])nlf, t, 256);
    __syncthreads();
    for (int i = t; i < NLAT * DD / 2; i += 256) {
        int r = i >> 6, c = (i & 63) * 2;
        *(uint32_t*)(nlh + r * 136 + c) = f2bf2(nlf[r * DD + c], nlf[r * DD + c + 1]);
    }
    __syncthreads();
    {
        const uint32_t* AqP = g_AqP + (size_t)(layer * 2 + mod) * 32768;
        const float* cq = g_cq + (layer * 2 + mod) * 512;
        uint32_t aN = s2u(nlh + (lane & 15) * 136 + (lane >> 4) * 8);
        float acc[8][4];
        #pragma unroll
        for (int i = 0; i < 8; i++)
            #pragma unroll
            for (int j = 0; j < 4; j++) acc[i][j] = 0.0f;
        #pragma unroll
        for (int ks = 0; ks < 8; ks++) {
            uint32_t aA[4];
            LDSM4(aA, aN + ks * 32);
            #pragma unroll
            for (int nt = 0; nt < 8; nt++) {
                int n_t = w * 8 + nt;
                uint2 bb = *(const uint2*)(AqP + (size_t)(n_t * 8 + ks) * 64 + lane * 2);
                MMA16816(acc[nt], aA, bb.x, bb.y);
            }
        }
        #pragma unroll
        for (int nt = 0; nt < 8; nt++) {
            int n0 = w * 64 + nt * 8 + tc * 2;
            int h = n0 >> 7, col = n0 & 127;
            float c0v = cq[n0], c1v = cq[n0 + 1];
            *(uint32_t*)(qts + (g * 4 + h) * 136 + col)       = f2bf2(acc[nt][0] + c0v, acc[nt][1] + c1v);
            *(uint32_t*)(qts + ((g + 8) * 4 + h) * 136 + col) = f2bf2(acc[nt][2] + c0v, acc[nt][3] + c1v);
        }
    }
    __syncthreads();
    uint32_t qa[8][4];
    {
        uint32_t aQ = s2u(qts + (pb + (lane & 15)) * 136 + (lane >> 4) * 8);
        #pragma unroll
        for (int ks = 0; ks < 8; ks++) LDSM4(qa[ks], aQ + ks * 32);
    }
    if (t < 64) { m_s[t] = -1e30f; l_s[t] = 0.0f; }

    float cx[8][4];
    #pragma unroll
    for (int i = 0; i < 8; i++)
        #pragma unroll
        for (int j = 0; j < 4; j++) cx[i][j] = 0.0f;

    uint32_t aK1 = s2u(Ks0 + (th * 32 + ((lane >> 4) << 3) + (lane & 7)) * 136 + ((lane >> 3) & 1) * 8);
    uint32_t aK2 = aK1 + 16 * 136 * 2;
    uint32_t aP  = s2u(Ps + (pb + (lane & 15)) * 72 + (lane >> 4) * 8);
    uint32_t aV  = s2u(Vs0 + (lane & 15) * 136 + th * 64 + (lane >> 4) * 8);

    for (int k = 0; k < nchunks; k++) {
        int cur = k & 1;
        int nk = min(64, cnt - k * 64);
        if (k + 1 < nchunks) {
            int nk2 = min(64, cnt - (k + 1) * 64);
            issue_chunk(Kg, Vg, Ks0 + (cur ^ 1) * KV_ELE, Vs0 + (cur ^ 1) * KV_ELE,
                        s0 + (k + 1) * 64, nk2, t);
            CP_COMMIT();
            CP_WAIT1();
        } else {
            CP_WAIT0();
        }
        __syncthreads();
        {
            uint32_t kbase1 = aK1 + cur * (KV_ELE * 2);
            uint32_t kbase2 = aK2 + cur * (KV_ELE * 2);
            float sa[4][4];
            #pragma unroll
            for (int j = 0; j < 4; j++)
                #pragma unroll
                for (int q = 0; q < 4; q++) sa[j][q] = 0.0f;
            #pragma unroll
            for (int ks = 0; ks < 8; ks++) {
                uint32_t kb1[4], kb2[4];
                LDSM4(kb1, kbase1 + ks * 32);
                LDSM4(kb2, kbase2 + ks * 32);
                MMA16816(sa[0], qa[ks], kb1[0], kb1[1]);
                MMA16816(sa[1], qa[ks], kb1[2], kb1[3]);
                MMA16816(sa[2], qa[ks], kb2[0], kb2[1]);
                MMA16816(sa[3], qa[ks], kb2[2], kb2[3]);
            }
            int r0 = pb + g, r1 = pb + g + 8;
            #pragma unroll
            for (int j = 0; j < 4; j++) {
                int c0 = th * 32 + j * 8 + tc * 2;
                *(float2*)&ss[r0 * 68 + c0] = make_float2(sa[j][0], sa[j][1]);
                *(float2*)&ss[r1 * 68 + c0] = make_float2(sa[j][2], sa[j][3]);
            }
        }
        __syncthreads();
        {
            int p = t >> 2, sub = t & 3;
            int k0 = sub * 16;
            float mo = m_s[p];
            float cm = -1e30f;
            #pragma unroll 4
            for (int kk = k0; kk < k0 + 16; kk++) {
                float v = (kk < nk) ? ss[p * 68 + kk] : -1e30f;
                cm = fmaxf(cm, v);
            }
            cm = fmaxf(cm, __shfl_xor_sync(0xffffffffu, cm, 1));
            cm = fmaxf(cm, __shfl_xor_sync(0xffffffffu, cm, 2));
            cm = fmaxf(cm, mo);
            float sum = 0.0f;
            #pragma unroll 4
            for (int kk = k0; kk < k0 + 16; kk++) {
                float e = (kk < nk) ? __expf(ss[p * 68 + kk] - cm) : 0.0f;
                Ps[p * 72 + kk] = __float2bfloat16(e);
                sum += e;
            }
            sum += __shfl_xor_sync(0xffffffffu, sum, 1);
            sum += __shfl_xor_sync(0xffffffffu, sum, 2);
            if (sub == 0) {
                float scl = __expf(mo - cm);
                l_s[p] = l_s[p] * scl + sum;
                m_s[p] = cm;
                sc_s[p] = scl;
            }
        }
        __syncthreads();
        {
            uint32_t vbase = aV + cur * (KV_ELE * 2);
            float sc0 = sc_s[pb + g], sc1 = sc_s[pb + g + 8];
            #pragma unroll
            for (int nt = 0; nt < 8; nt++) {
                cx[nt][0] *= sc0; cx[nt][1] *= sc0;
                cx[nt][2] *= sc1; cx[nt][3] *= sc1;
            }
            #pragma unroll
            for (int ks = 0; ks < 4; ks++) {
                uint32_t pa[4];
                LDSM4(pa, aP + ks * 32);
                #pragma unroll
                for (int ntp = 0; ntp < 4; ntp++) {
                    uint32_t vb[4];
                    LDSM4T(vb, vbase + ks * 4352 + ntp * 32);
                    MMA16816(cx[ntp * 2 + 0], pa, vb[0], vb[1]);
                    MMA16816(cx[ntp * 2 + 1], pa, vb[2], vb[3]);
                }
            }
        }
        __syncthreads();
    }
    int r0 = pb + g, r1 = pb + g + 8;
    float l0 = l_s[r0], l1 = l_s[r1];
    float i0 = (l0 > 0.0f) ? 1.0f / l0 : 0.0f;
    float i1 = (l1 > 0.0f) ? 1.0f / l1 : 0.0f;
    __nv_bfloat16* cbp = g_ctxh + (size_t)b * 16384;
    int base0 = (r0 >> 2) * 1024 + mod * 512 + (r0 & 3) * 128;
    int base1 = (r1 >> 2) * 1024 + mod * 512 + (r1 & 3) * 128;
    #pragma unroll
    for (int nt = 0; nt < 8; nt++) {
        int d0 = th * 64 + nt * 8 + tc * 2;
        *(uint32_t*)(cbp + base0 + d0) = f2bf2(cx[nt][0] * i0, cx[nt][1] * i0);
        *(uint32_t*)(cbp + base1 + d0) = f2bf2(cx[nt][2] * i1, cx[nt][3] * i1);
    }
}

// ---------------- fused: VO GEMM + residual + LN2 + FFN (all tensor-core) ----------------
// dsm layout: phase A: ctxs [16][1032] bf16 (33024B). After: nlf f32 @0 (8192B),
// nlh bf16 @8192 ([16][136]=4352B), hidh bf16 @16384 ([16][264]=8448B). latv @33024 (8192B).
#define PF_BYTES (33024 + 8192)

__global__ void __launch_bounds__(256) projffn_kernel(int layer,
    const float* __restrict__ lng, const float* __restrict__ lnb,
    const float* __restrict__ b1, const float* __restrict__ b2) {
    extern __shared__ char dsm[];
    __nv_bfloat16* ctxs = (__nv_bfloat16*)dsm;
    float* nlf = (float*)dsm;
    __nv_bfloat16* nlh = (__nv_bfloat16*)(dsm + 8192);
    __nv_bfloat16* hidh = (__nv_bfloat16*)(dsm + 16384);
    float* latv = (float*)(dsm + 33024);
    int b = blockIdx.x, t = threadIdx.x;
    int w = t >> 5, lane = t & 31, g = lane >> 2, tc = lane & 3;

    {
        const uint4* src = (const uint4*)(g_ctxh + (size_t)b * 16384);
        for (int i = t; i < 2048; i += 256) {
            int r = i >> 7, c8 = i & 127;
            *(uint4*)(ctxs + r * 1032 + c8 * 8) = src[i];
        }
        const float4* lsrc = (const float4*)(g_lat + (size_t)b * NLAT * DD);
        for (int i = t; i < 512; i += 256) ((float4*)latv)[i] = lsrc[i];
    }
    __syncthreads();
    // phase A: VO GEMM (packed Bvo) -> latv
    {
        const uint32_t* BvP = g_BvoP + (size_t)layer * 65536;
        const float* cvo0 = g_cvo + (layer * 2 + 0) * 128;
        const float* cvo1 = g_cvo + (layer * 2 + 1) * 128;
        uint32_t aC = s2u(ctxs + (lane & 15) * 1032 + (lane >> 4) * 8);
        float acc[2][4];
        #pragma unroll
        for (int i = 0; i < 2; i++)
            #pragma unroll
            for (int j = 0; j < 4; j++) acc[i][j] = 0.0f;
        #pragma unroll 4
        for (int ks = 0; ks < 64; ks++) {
            uint32_t aA[4];
            LDSM4(aA, aC + ks * 32);
            #pragma unroll
            for (int nt = 0; nt < 2; nt++) {
                int n_t = w * 2 + nt;
                uint2 bb = *(const uint2*)(BvP + (size_t)(n_t * 64 + ks) * 64 + lane * 2);
                MMA16816(acc[nt], aA, bb.x, bb.y);
            }
        }
        __syncthreads();   // all ctxs reads done before nlf overlay
        #pragma unroll
        for (int nt = 0; nt < 2; nt++) {
            int n0 = w * 16 + nt * 8 + tc * 2;
            float c0v = cvo0[n0] + cvo1[n0];
            float c1v = cvo0[n0 + 1] + cvo1[n0 + 1];
            latv[g * 128 + n0]           += acc[nt][0] + c0v;
            latv[g * 128 + n0 + 1]       += acc[nt][1] + c1v;
            latv[(g + 8) * 128 + n0]     += acc[nt][2] + c0v;
            latv[(g + 8) * 128 + n0 + 1] += acc[nt][3] + c1v;
        }
    }
    __syncthreads();
    layernorm_rows(latv, lng, lnb, (float(*)[DD])nlf, t, 256);
    __syncthreads();
    for (int i = t; i < NLAT * DD / 2; i += 256) {
        int r = i >> 6, c = (i & 63) * 2;
        *(uint32_t*)(nlh + r * 136 + c) = f2bf2(nlf[r * DD + c], nlf[r * DD + c + 1]);
    }
    __syncthreads();
    // FFN1 (TC): hid = relu(nl @ w1^T + b1), bf16 -> hidh [16][264]
    {
        const uint32_t* W1P = g_w1P + (size_t)layer * 16384;
        uint32_t aN = s2u(nlh + (lane & 15) * 136 + (lane >> 4) * 8);
        float f1a[4][4];
        #pragma unroll
        for (int i = 0; i < 4; i++)
            #pragma unroll
            for (int j = 0; j < 4; j++) f1a[i][j] = 0.0f;
        #pragma unroll
        for (int ks = 0; ks < 8; ks++) {
            uint32_t aA[4];
            LDSM4(aA, aN + ks * 32);
            #pragma unroll
            for (int nt = 0; nt < 4; nt++) {
                int n_t = w * 4 + nt;
                uint2 bb = *(const uint2*)(W1P + (size_t)(n_t * 8 + ks) * 64 + lane * 2);
                MMA16816(f1a[nt], aA, bb.x, bb.y);
            }
        }
        #pragma unroll
        for (int nt = 0; nt < 4; nt++) {
            int n0 = (w * 4 + nt) * 8 + tc * 2;
            float b0v = b1[n0], b1v = b1[n0 + 1];
            *(uint32_t*)(hidh + g * 264 + n0) =
                f2bf2(fmaxf(f1a[nt][0] + b0v, 0.0f), fmaxf(f1a[nt][1] + b1v, 0.0f));
            *(uint32_t*)(hidh + (g + 8) * 264 + n0) =
                f2bf2(fmaxf(f1a[nt][2] + b0v, 0.0f), fmaxf(f1a[nt][3] + b1v, 0.0f));
        }
    }
    __syncthreads();
    // FFN2 (TC) + residual -> g_lat
    {
        const uint32_t* W2P = g_w2P + (size_t)layer * 16384;
        uint32_t aH = s2u(hidh + (lane & 15) * 264 + (lane >> 4) * 8);
        float f2a[2][4];
        #pragma unroll
        for (int i = 0; i < 2; i++)
            #pragma unroll
            for (int j = 0; j < 4; j++) f2a[i][j] = 0.0f;
        #pragma unroll 4
        for (int ks = 0; ks < 16; ks++) {
            uint32_t aA[4];
            LDSM4(aA, aH + ks * 32);
            #pragma unroll
            for (int nt = 0; nt < 2; nt++) {
                int n_t = w * 2 + nt;
                uint2 bb = *(const uint2*)(W2P + (size_t)(n_t * 16 + ks) * 64 + lane * 2);
                MMA16816(f2a[nt], aA, bb.x, bb.y);
            }
        }
        float* latb = g_lat + (size_t)b * NLAT * DD;
        #pragma unroll
        for (int nt = 0; nt < 2; nt++) {
            int n0 = (w * 2 + nt) * 8 + tc * 2;
            float b0v = b2[n0], b1v = b2[n0 + 1];
            latb[g * 128 + n0]           = latv[g * 128 + n0] + f2a[nt][0] + b0v;
            latb[g * 128 + n0 + 1]       = latv[g * 128 + n0 + 1] + f2a[nt][1] + b1v;
            latb[(g + 8) * 128 + n0]     = latv[(g + 8) * 128 + n0] + f2a[nt][2] + b0v;
            latb[(g + 8) * 128 + n0 + 1] = latv[(g + 8) * 128 + n0 + 1] + f2a[nt][3] + b1v;
        }
    }
}

// ---------------- head: grid 128, 4 batches/block ----------------
__global__ void __launch_bounds__(256) head_kernel(
    const float* __restrict__ w1, const float* __restrict__ b1,
    const float* __restrict__ w2, const float* __restrict__ b2,
    float* __restrict__ out) {
    __shared__ float flat_s[4][2048];
    __shared__ float hs[4][128];
    int blk = blockIdx.x, t = threadIdx.x;
    int b0 = blk * 4;
    const float4* src = (const float4*)(g_lat + (size_t)b0 * NLAT * DD);
    for (int i = t; i < 2048; i += 256) ((float4*)flat_s)[i] = src[i];
    __syncthreads();
    int tt = t & 127, bh = t >> 7;
    float acc0 = b1[tt], acc1 = acc0;
    const float4* w1r = (const float4*)(w1 + (size_t)tt * NLAT * DD);
    const float4* f0 = (const float4*)flat_s[bh * 2];
    const float4* f1 = (const float4*)flat_s[bh * 2 + 1];
    #pragma unroll 8
    for (int u4 = 0; u4 < 512; u4++) {
        float4 w4 = w1r[u4];
        float4 a4 = f0[u4];
        float4 c4 = f1[u4];
        acc0 = fmaf(w4.x, a4.x, fmaf(w4.y, a4.y, fmaf(w4.z, a4.z, fmaf(w4.w, a4.w, acc0))));
        acc1 = fmaf(w4.x, c4.x, fmaf(w4.y, c4.y, fmaf(w4.z, c4.z, fmaf(w4.w, c4.w, acc1))));
    }
    hs[bh * 2][tt] = fmaxf(acc0, 0.0f);
    hs[bh * 2 + 1][tt] = fmaxf(acc1, 0.0f);
    __syncthreads();
    int w = t >> 5, lane = t & 31;
    if (w < 4) {
        float s = 0.0f;
        #pragma unroll
        for (int q = 0; q < 4; q++) {
            int idx = q * 32 + lane;
            s += hs[w][idx] * w2[idx];
        }
        #pragma unroll
        for (int o = 16; o; o >>= 1) s += __shfl_xor_sync(0xffffffffu, s, o);
        if (lane == 0) {
            float x = s + b2[0];
            out[b0 + w] = (x > 20.0f) ? x : log1pf(__expf(x));
        }
    }
}

extern "C" void kernel_launch(void* const* d_in, const int* in_sizes, int n_in,
                              void* d_out, int out_size) {
    const float* drug_k   = (const float*)d_in[0];
    const float* drug_v   = (const float*)d_in[1];
    const float* enz_k    = (const float*)d_in[2];
    const float* enz_v    = (const float*)d_in[3];
    const int*   drug_b   = (const int*)d_in[4];
    const int*   enz_b    = (const int*)d_in[5];
    const float* latents  = (const float*)d_in[6];
    const float* wq_d     = (const float*)d_in[7];
    const float* bq_d     = (const float*)d_in[8];
    const float* wq_e     = (const float*)d_in[9];
    const float* bq_e     = (const float*)d_in[10];
    const float* mha_d_w  = (const float*)d_in[11];
    const float* mha_d_b  = (const float*)d_in[12];
    const float* mha_d_ow = (const float*)d_in[13];
    const float* mha_d_ob = (const float*)d_in[14];
    const float* mha_e_w  = (const float*)d_in[15];
    const float* mha_e_b  = (const float*)d_in[16];
    const float* mha_e_ow = (const float*)d_in[17];
    const float* mha_e_ob = (const float*)d_in[18];
    const float* ln1_g    = (const float*)d_in[19];
    const float* ln1_b    = (const float*)d_in[20];
    const float* ln2_g    = (const float*)d_in[21];
    const float* ln2_b    = (const float*)d_in[22];
    const float* ffn_w1   = (const float*)d_in[23];
    const float* ffn_b1   = (const float*)d_in[24];
    const float* ffn_w2   = (const float*)d_in[25];
    const float* ffn_b2   = (const float*)d_in[26];
    const float* head_w1  = (const float*)d_in[27];
    const float* head_b1  = (const float*)d_in[28];
    const float* head_w2  = (const float*)d_in[29];
    const float* head_b2  = (const float*)d_in[30];
    float* out = (float*)d_out;

    static int s_attr_set = 0;
    if (!s_attr_set) {
        cudaFuncSetAttribute(attn_kernel, cudaFuncAttributeMaxDynamicSharedMemorySize, ATT_BYTES);
        s_attr_set = 1;
    }

    offsets_kernel<<<3, 256>>>(drug_b, enz_b);
    init_lat_kernel<<<(BB * NLAT * DD + 255) / 256, 256>>>(latents);
    cvt_kernel<<<(NE * DD / 4 + 255) / 256, 256>>>(drug_k, drug_v, enz_k, enz_v);
    pc_P_kernel<<<dim3(32, 4), 256>>>(wq_d, bq_d, wq_e, bq_e, mha_d_w, mha_d_b, mha_e_w, mha_e_b);
    pc_Aq_kernel<<<dim3(32, 4), 256>>>(mha_d_w, mha_e_w);
    pc_Bvo_kernel<<<dim3(32, 4), 256>>>(mha_d_w, mha_d_ow, mha_e_w, mha_e_ow);
    pc_cvo_kernel<<<dim3(2, 4), 128>>>(mha_d_b, mha_d_ow, mha_d_ob, mha_e_b, mha_e_ow, mha_e_ob);
    pc_ffn_kernel<<<LAYERS, 256>>>(ffn_w1, ffn_w2);

    for (int l = 0; l < LAYERS; l++) {
        size_t oV = (size_t)l * DD;
        size_t oF1b = (size_t)l * 2 * DD;

        attn_kernel<<<1024, 256, ATT_BYTES>>>(l, ln1_g + oV, ln1_b + oV);
        projffn_kernel<<<BB, 256, PF_BYTES>>>(l,
            ln2_g + oV, ln2_b + oV,
            ffn_b1 + oF1b, ffn_b2 + oV);
    }

    head_kernel<<<128, 256>>>(head_w1, head_b1, head_w2, head_b2, out);
}

// round 14
// speedup vs baseline: 4.3831x; 1.1061x over previous
#include <cuda_runtime.h>
#include <cuda_bf16.h>
#include <stdint.h>
#include <math.h>

#define BB 512
#define DD 128
#define NLAT 16
#define NH 4
#define HDIM 32
#define ND 25600
#define NE 153600
#define NPAIR 64
#define LAYERS 4

// scratch (static device globals: allowed)
__device__ float g_lat[BB * NLAT * DD];
__device__ __nv_bfloat16 g_ctxh[BB * NLAT * 1024];
__device__ int   g_starts[2][BB + 1];
__device__ __nv_bfloat16 g_dk[ND * DD];
__device__ __nv_bfloat16 g_dv[ND * DD];
__device__ __nv_bfloat16 g_ek[NE * DD];
__device__ __nv_bfloat16 g_ev[NE * DD];
// composed weights, MMA B-fragment packed: [n_tile][kstep][lane][2 words]
__device__ uint32_t g_AqP[LAYERS * 2 * 32768];
__device__ float g_cq[LAYERS * 2 * 512];
__device__ uint32_t g_BvoP[LAYERS * 65536];
__device__ float g_cvo[LAYERS * 2 * 128];
__device__ uint32_t g_w1P[LAYERS * 16384];
__device__ uint32_t g_w2P[LAYERS * 16384];
// precompute scratch
__device__ float g_P[32 * 32 * 128];
__device__ float g_cb[32 * 32];

__device__ __forceinline__ int lb_dev(const int* __restrict__ a, int n, int key) {
    int lo = 0, hi = n;
    while (lo < hi) { int mid = (lo + hi) >> 1; if (a[mid] < key) lo = mid + 1; else hi = mid; }
    return lo;
}

__device__ __forceinline__ uint32_t f2bf2(float x, float y) {
    __nv_bfloat162 h = __floats2bfloat162_rn(x, y);
    return *reinterpret_cast<uint32_t*>(&h);
}

// frag scatter: element (n, k pair j) -> lane = (n&7)*4 + (j&3), word = j>>2
__device__ __forceinline__ void frag_store8(uint32_t* base32, int n_in, const float* acc, float scl) {
    #pragma unroll
    for (int j = 0; j < 8; j++) {
        int lane = n_in * 4 + (j & 3);
        int word = j >> 2;
        base32[lane * 2 + word] = f2bf2(acc[2 * j] * scl, acc[2 * j + 1] * scl);
    }
}

// ---------------- mega setup: all independent setup roles in ONE launch ----------------
// block ranges: [0,128) pc_P | [128,256) pc_Bvo | [256,264) pc_cvo | [264,268) pc_ffn
//               [268,271) offsets | [271,4367) init_lat | [4367,23567) cvt
#define PCP0 0
#define PCB0 128
#define CVO0 256
#define FFN0 264
#define OFF0 268
#define INIT0 271
#define CVT0 4367
#define SETUP_GRID 23567

__global__ void __launch_bounds__(256) mega_setup_kernel(
    const float* __restrict__ dk, const float* __restrict__ dv,
    const float* __restrict__ ek, const float* __restrict__ ev,
    const int* __restrict__ db, const int* __restrict__ eb,
    const float* __restrict__ latents,
    const float* __restrict__ wq_d, const float* __restrict__ bq_d,
    const float* __restrict__ wq_e, const float* __restrict__ bq_e,
    const float* __restrict__ mw_d, const float* __restrict__ mb_d,
    const float* __restrict__ ow_d, const float* __restrict__ ob_d,
    const float* __restrict__ mw_e, const float* __restrict__ mb_e,
    const float* __restrict__ ow_e, const float* __restrict__ ob_e,
    const float* __restrict__ w1, const float* __restrict__ w2) {
    __shared__ float sb[8224];
    int bid = blockIdx.x, t = threadIdx.x;

    if (bid >= CVT0) {                       // ---- cvt fp32 -> bf16 ----
        int i = (bid - CVT0) * 256 + t;
        int i4 = i * 4;
        if (i4 < ND * DD) {
            float4 a = *(const float4*)(dk + i4);
            float4 b = *(const float4*)(dv + i4);
            *(uint2*)(g_dk + i4) = make_uint2(f2bf2(a.x, a.y), f2bf2(a.z, a.w));
            *(uint2*)(g_dv + i4) = make_uint2(f2bf2(b.x, b.y), f2bf2(b.z, b.w));
        }
        if (i4 < NE * DD) {
            float4 a = *(const float4*)(ek + i4);
            float4 b = *(const float4*)(ev + i4);
            *(uint2*)(g_ek + i4) = make_uint2(f2bf2(a.x, a.y), f2bf2(a.z, a.w));
            *(uint2*)(g_ev + i4) = make_uint2(f2bf2(b.x, b.y), f2bf2(b.z, b.w));
        }
        return;
    }
    if (bid >= INIT0) {                      // ---- init latents ----
        int i = (bid - INIT0) * 256 + t;
        if (i < BB * NLAT * DD) g_lat[i] = latents[i & (NLAT * DD - 1)];
        return;
    }
    if (bid >= OFF0) {                       // ---- segment offsets ----
        int i = (bid - OFF0) * 256 + t;
        if (i <= BB) { g_starts[0][i] = lb_dev(db, ND, i); g_starts[1][i] = lb_dev(eb, NE, i); }
        return;
    }
    if (bid >= FFN0) {                       // ---- pack FFN weights ----
        int l = bid - FFN0;
        {
            const float* src = w1 + (size_t)l * 2 * DD * DD + (size_t)t * DD;
            int n_t = t >> 3, n_in = t & 7;
            for (int ks = 0; ks < 8; ks++) {
                float v[16];
                #pragma unroll
                for (int q = 0; q < 4; q++) {
                    float4 f = *(const float4*)(src + ks * 16 + q * 4);
                    v[q*4+0] = f.x; v[q*4+1] = f.y; v[q*4+2] = f.z; v[q*4+3] = f.w;
                }
                frag_store8(g_w1P + (size_t)l * 16384 + (size_t)(n_t * 8 + ks) * 64, n_in, v, 1.0f);
            }
        }
        {
            int n = t & 127, half = t >> 7;
            const float* src = w2 + (size_t)l * DD * 2 * DD + (size_t)n * 2 * DD;
            int n_t = n >> 3, n_in = n & 7;
            for (int kk = 0; kk < 8; kk++) {
                int ks = half * 8 + kk;
                float v[16];
                #pragma unroll
                for (int q = 0; q < 4; q++) {
                    float4 f = *(const float4*)(src + ks * 16 + q * 4);
                    v[q*4+0] = f.x; v[q*4+1] = f.y; v[q*4+2] = f.z; v[q*4+3] = f.w;
                }
                frag_store8(g_w2P + (size_t)l * 16384 + (size_t)(n_t * 16 + ks) * 64, n_in, v, 1.0f);
            }
        }
        return;
    }
    if (bid >= CVO0) {                       // ---- cvo bias fold ----
        int r = bid - CVO0;
        int m = r & 1, l = r >> 1;
        const float* ow = (m ? ow_e : ow_d) + (size_t)l * DD * DD;
        const float* ob = (m ? ob_e : ob_d) + l * DD;
        const float* bv = (m ? mb_e : mb_d) + l * 3 * DD + 2 * DD;
        float* bv_s = sb;
        if (t < 128) bv_s[t] = bv[t];
        __syncthreads();
        if (t < 128) {
            float s = ob[t];
            const float4* owr = (const float4*)(ow + (size_t)t * 128);
            #pragma unroll
            for (int u4 = 0; u4 < 32; u4++) {
                float4 o4 = owr[u4];
                s = fmaf(o4.x, bv_s[u4*4+0], fmaf(o4.y, bv_s[u4*4+1],
                    fmaf(o4.z, bv_s[u4*4+2], fmaf(o4.w, bv_s[u4*4+3], s))));
            }
            g_cvo[(l * 2 + m) * 128 + t] = s;
        }
        return;
    }
    if (bid >= PCB0) {                       // ---- Bvo composition ----
        int r = bid - PCB0;
        int c = r >> 2, ts = r & 3;
        int h = c & 3, m = (c >> 2) & 1, l = c >> 3;
        const float* W  = (m ? mw_e : mw_d) + (size_t)l * 3 * DD * DD;
        const float* ow = (m ? ow_e : ow_d) + (size_t)l * DD * DD;
        float* wv_s = sb;            // 4096
        float* ow_s = sb + 4096;     // 1024
        for (int i = t; i < 1024; i += 256)
            ((float4*)wv_s)[i] = ((const float4*)(W + (size_t)(2 * DD + h * 32) * DD))[i];
        for (int i = t; i < 1024; i += 256) {
            int tpl = i >> 5, j = i & 31;
            ow_s[tpl * 32 + j] = ow[(size_t)(ts * 32 + tpl) * 128 + h * 32 + j];
        }
        __syncthreads();
        int tpl = t >> 3, d0 = (t & 7) * 16;
        float acc[16];
        #pragma unroll
        for (int i = 0; i < 16; i++) acc[i] = 0.0f;
        for (int j = 0; j < 32; j++) {
            float o = ow_s[tpl * 32 + j];
            const float4* wr = (const float4*)(wv_s + j * 128 + d0);
            #pragma unroll
            for (int q = 0; q < 4; q++) {
                float4 w4 = wr[q];
                acc[q*4+0] = fmaf(o, w4.x, acc[q*4+0]);
                acc[q*4+1] = fmaf(o, w4.y, acc[q*4+1]);
                acc[q*4+2] = fmaf(o, w4.z, acc[q*4+2]);
                acc[q*4+3] = fmaf(o, w4.w, acc[q*4+3]);
            }
        }
        int n = ts * 32 + tpl;
        int kk0 = m * 512 + h * 128 + d0;
        int n_t = n >> 3, n_in = n & 7, ks = kk0 >> 4;
        frag_store8(g_BvoP + (size_t)l * 65536 + (size_t)(n_t * 64 + ks) * 64, n_in, acc, 1.0f);
        return;
    }
    {                                        // ---- P = U_h @ wq ----
        int r = bid - PCP0;
        int c = r >> 2, ds = r & 3;
        int h = c & 3, m = (c >> 2) & 1, l = c >> 3;
        const float* wq = (m ? wq_e : wq_d) + (size_t)l * DD * DD;
        const float* W  = (m ? mw_e : mw_d) + (size_t)l * 3 * DD * DD;
        float* U_s = sb;             // 4096
        float* wq_s = sb + 4096;     // 4096
        for (int i = t; i < 1024; i += 256)
            ((float4*)U_s)[i] = ((const float4*)(W + (size_t)h * 32 * DD))[i];
        for (int i = t; i < 1024; i += 256) {
            int dp = i >> 3, q = i & 7;
            *(float4*)(wq_s + dp * 32 + q * 4) = *(const float4*)(wq + (size_t)dp * 128 + ds * 32 + q * 4);
        }
        __syncthreads();
        int j = t >> 3, dl = (t & 7) * 4;
        float a0 = 0, a1 = 0, a2 = 0, a3 = 0;
        #pragma unroll 8
        for (int dp = 0; dp < 128; dp++) {
            float u = U_s[j * 128 + dp];
            float4 w4 = *(const float4*)(wq_s + dp * 32 + dl);
            a0 = fmaf(u, w4.x, a0); a1 = fmaf(u, w4.y, a1);
            a2 = fmaf(u, w4.z, a2); a3 = fmaf(u, w4.w, a3);
        }
        *(float4*)(g_P + (size_t)c * 4096 + j * 128 + ds * 32 + dl) = make_float4(a0, a1, a2, a3);
        if (ds == 0 && t < 32) {
            const float* bq = (m ? bq_e : bq_d) + l * DD;
            const float* mb = (m ? mb_e : mb_d) + l * 3 * DD;
            float s = 0.0f;
            #pragma unroll 8
            for (int dp = 0; dp < 128; dp++) s += U_s[t * 128 + dp] * bq[dp];
            g_cb[c * 32 + t] = s + mb[h * 32 + t];
        }
    }
}

// pc_Aq depends on g_P -> separate launch
__global__ void __launch_bounds__(256) pc_Aq_kernel(
    const float* __restrict__ mw_d, const float* __restrict__ mw_e) {
    __shared__ float P_s[32 * 128];
    __shared__ float V_s[32 * 32];
    __shared__ float cb_s[32];
    int c = blockIdx.x, ts = blockIdx.y, t = threadIdx.x;
    int h = c & 3, m = (c >> 2) & 1, l = c >> 3;
    const float* W = (m ? mw_e : mw_d) + (size_t)l * 3 * DD * DD;
    const float* wk = W + (size_t)(DD + h * 32) * DD;
    for (int i = t; i < 1024; i += 256)
        ((float4*)P_s)[i] = ((const float4*)(g_P + (size_t)c * 4096))[i];
    for (int i = t; i < 1024; i += 256) {
        int j = i >> 5, tpl = i & 31;
        V_s[j * 32 + tpl] = wk[(size_t)j * 128 + ts * 32 + tpl];
    }
    if (t < 32) cb_s[t] = g_cb[c * 32 + t];
    __syncthreads();
    const float scale = 0.17677669529663688f;
    int tpl = t >> 3, d0 = (t & 7) * 16;
    float acc[16];
    #pragma unroll
    for (int i = 0; i < 16; i++) acc[i] = 0.0f;
    float cq = 0.0f;
    for (int j = 0; j < 32; j++) {
        float v = V_s[j * 32 + tpl];
        const float4* pr = (const float4*)(P_s + j * 128 + d0);
        #pragma unroll
        for (int q = 0; q < 4; q++) {
            float4 p4 = pr[q];
            acc[q*4+0] = fmaf(v, p4.x, acc[q*4+0]);
            acc[q*4+1] = fmaf(v, p4.y, acc[q*4+1]);
            acc[q*4+2] = fmaf(v, p4.z, acc[q*4+2]);
            acc[q*4+3] = fmaf(v, p4.w, acc[q*4+3]);
        }
        cq += v * cb_s[j];
    }
    int n = ts * 32 + tpl;
    int n_t = n >> 3, n_in = n & 7, ks = t & 7;
    frag_store8(g_AqP + (size_t)(l * 2 + m) * 32768 + (size_t)(n_t * 8 + ks) * 64, n_in, acc, scale);
    if ((t & 7) == 0) g_cq[(l * 2 + m) * 512 + n] = cq * scale;
}

// ---------------- common helpers ----------------
__device__ __forceinline__ void layernorm_rows(const float* __restrict__ src,
                                               const float* __restrict__ g,
                                               const float* __restrict__ bta,
                                               float (*dst)[DD], int t, int nthr) {
    int warp = t >> 5, lane = t & 31, nw = nthr >> 5;
    for (int r = warp; r < NLAT; r += nw) {
        float4 v = ((const float4*)(src + r * DD))[lane];
        float s = v.x + v.y + v.z + v.w;
        #pragma unroll
        for (int o = 16; o; o >>= 1) s += __shfl_xor_sync(0xffffffffu, s, o);
        float mean = s * (1.0f / DD);
        float dx = v.x - mean, dy = v.y - mean, dz = v.z - mean, dw = v.w - mean;
        float q = dx * dx + dy * dy + dz * dz + dw * dw;
        #pragma unroll
        for (int o = 16; o; o >>= 1) q += __shfl_xor_sync(0xffffffffu, q, o);
        float rstd = rsqrtf(q * (1.0f / DD) + 1e-5f);
        int c = lane * 4;
        dst[r][c + 0] = dx * rstd * g[c + 0] + bta[c + 0];
        dst[r][c + 1] = dy * rstd * g[c + 1] + bta[c + 1];
        dst[r][c + 2] = dz * rstd * g[c + 2] + bta[c + 2];
        dst[r][c + 3] = dw * rstd * g[c + 3] + bta[c + 3];
    }
}

__device__ __forceinline__ uint32_t s2u(const void* p) {
    return (uint32_t)__cvta_generic_to_shared(p);
}

#define LDSM4(R, addr) asm volatile( \
    "ldmatrix.sync.aligned.m8n8.x4.shared.b16 {%0,%1,%2,%3},[%4];" \
    : "=r"((R)[0]), "=r"((R)[1]), "=r"((R)[2]), "=r"((R)[3]) : "r"(addr))
#define LDSM4T(R, addr) asm volatile( \
    "ldmatrix.sync.aligned.m8n8.x4.trans.shared.b16 {%0,%1,%2,%3},[%4];" \
    : "=r"((R)[0]), "=r"((R)[1]), "=r"((R)[2]), "=r"((R)[3]) : "r"(addr))
#define MMA16816(D, A, B0, B1) asm volatile( \
    "mma.sync.aligned.m16n8k16.row.col.f32.bf16.bf16.f32 " \
    "{%0,%1,%2,%3},{%4,%5,%6,%7},{%8,%9},{%0,%1,%2,%3};" \
    : "+f"((D)[0]), "+f"((D)[1]), "+f"((D)[2]), "+f"((D)[3]) \
    : "r"((A)[0]), "r"((A)[1]), "r"((A)[2]), "r"((A)[3]), "r"(B0), "r"(B1))
#define CP16(dst, src) asm volatile("cp.async.cg.shared.global [%0], [%1], 16;\n" :: "r"(dst), "l"(src))
#define CP_COMMIT() asm volatile("cp.async.commit_group;\n" ::: "memory")
#define CP_WAIT1() asm volatile("cp.async.wait_group 1;\n" ::: "memory")
#define CP_WAIT0() asm volatile("cp.async.wait_group 0;\n" ::: "memory")

// ---------------- fused attention: LN + Q-GEMM prologue + flash attention ----------------
#define KV_ELE (64 * 136)
#define ATT_BYTES (4 * KV_ELE * 2 + 64 * 72 * 2 + 64 * 68 * 4 + 3 * 64 * 4)

__device__ __forceinline__ void issue_chunk(const __nv_bfloat16* __restrict__ Kg,
                                            const __nv_bfloat16* __restrict__ Vg,
                                            __nv_bfloat16* Ksb, __nv_bfloat16* Vsb,
                                            int row0, int nk, int t) {
    #pragma unroll
    for (int i = t; i < 1024; i += 256) {
        int r = i >> 4, seg = (i & 15) * 8;
        if (r < nk) {
            CP16(s2u(Ksb + r * 136 + seg), Kg + (size_t)(row0 + r) * DD + seg);
            CP16(s2u(Vsb + r * 136 + seg), Vg + (size_t)(row0 + r) * DD + seg);
        }
    }
}

// grid 1024: bid<512 -> enzyme first, else drug. 256 threads.
__global__ void __launch_bounds__(256, 2) attn_kernel(int layer,
    const float* __restrict__ lng, const float* __restrict__ lnb) {
    extern __shared__ char smraw[];
    __nv_bfloat16* Ks0 = (__nv_bfloat16*)smraw;
    __nv_bfloat16* Vs0 = Ks0 + 2 * KV_ELE;
    __nv_bfloat16* Ps  = Vs0 + 2 * KV_ELE;
    float* ss  = (float*)(Ps + 64 * 72);
    float* m_s = ss + 64 * 68;
    float* l_s = m_s + 64;
    float* sc_s = l_s + 64;
    float* nlf = (float*)Ps;
    __nv_bfloat16* nlh = Vs0 + KV_ELE;
    __nv_bfloat16* qts = (__nv_bfloat16*)ss;

    int bid = blockIdx.x, t = threadIdx.x;
    int mod = (bid < 512) ? 1 : 0;
    int b = bid & 511;
    const __nv_bfloat16* Kg = mod ? g_ek : g_dk;
    const __nv_bfloat16* Vg = mod ? g_ev : g_dv;
    int w = t >> 5, lane = t & 31;
    int g = lane >> 2, tc = lane & 3;
    int s0 = g_starts[mod][b];
    int cnt = g_starts[mod][b + 1] - s0;

    int pb = (w & 3) * 16;
    int th = w >> 2;

    for (int i = t; i < (4 * KV_ELE * 2) / 16; i += 256)
        ((uint4*)smraw)[i] = make_uint4(0, 0, 0, 0);
    __syncthreads();

    int nchunks = (cnt + 63) >> 6;
    if (nchunks > 0) {
        issue_chunk(Kg, Vg, Ks0, Vs0, s0, min(64, cnt), t);
        CP_COMMIT();
    }

    layernorm_rows(g_lat + (size_t)b * NLAT * DD, lng, lnb, (float(*)[DD])nlf, t, 256);
    __syncthreads();
    for (int i = t; i < NLAT * DD / 2; i += 256) {
        int r = i >> 6, c = (i & 63) * 2;
        *(uint32_t*)(nlh + r * 136 + c) = f2bf2(nlf[r * DD + c], nlf[r * DD + c + 1]);
    }
    __syncthreads();
    {
        const uint32_t* AqP = g_AqP + (size_t)(layer * 2 + mod) * 32768;
        const float* cq = g_cq + (layer * 2 + mod) * 512;
        uint32_t aN = s2u(nlh + (lane & 15) * 136 + (lane >> 4) * 8);
        float acc[8][4];
        #pragma unroll
        for (int i = 0; i < 8; i++)
            #pragma unroll
            for (int j = 0; j < 4; j++) acc[i][j] = 0.0f;
        #pragma unroll
        for (int ks = 0; ks < 8; ks++) {
            uint32_t aA[4];
            LDSM4(aA, aN + ks * 32);
            #pragma unroll
            for (int nt = 0; nt < 8; nt++) {
                int n_t = w * 8 + nt;
                uint2 bb = *(const uint2*)(AqP + (size_t)(n_t * 8 + ks) * 64 + lane * 2);
                MMA16816(acc[nt], aA, bb.x, bb.y);
            }
        }
        #pragma unroll
        for (int nt = 0; nt < 8; nt++) {
            int n0 = w * 64 + nt * 8 + tc * 2;
            int h = n0 >> 7, col = n0 & 127;
            float c0v = cq[n0], c1v = cq[n0 + 1];
            *(uint32_t*)(qts + (g * 4 + h) * 136 + col)       = f2bf2(acc[nt][0] + c0v, acc[nt][1] + c1v);
            *(uint32_t*)(qts + ((g + 8) * 4 + h) * 136 + col) = f2bf2(acc[nt][2] + c0v, acc[nt][3] + c1v);
        }
    }
    __syncthreads();
    uint32_t qa[8][4];
    {
        uint32_t aQ = s2u(qts + (pb + (lane & 15)) * 136 + (lane >> 4) * 8);
        #pragma unroll
        for (int ks = 0; ks < 8; ks++) LDSM4(qa[ks], aQ + ks * 32);
    }
    if (t < 64) { m_s[t] = -1e30f; l_s[t] = 0.0f; }

    float cx[8][4];
    #pragma unroll
    for (int i = 0; i < 8; i++)
        #pragma unroll
        for (int j = 0; j < 4; j++) cx[i][j] = 0.0f;

    uint32_t aK1 = s2u(Ks0 + (th * 32 + ((lane >> 4) << 3) + (lane & 7)) * 136 + ((lane >> 3) & 1) * 8);
    uint32_t aK2 = aK1 + 16 * 136 * 2;
    uint32_t aP  = s2u(Ps + (pb + (lane & 15)) * 72 + (lane >> 4) * 8);
    uint32_t aV  = s2u(Vs0 + (lane & 15) * 136 + th * 64 + (lane >> 4) * 8);

    for (int k = 0; k < nchunks; k++) {
        int cur = k & 1;
        int nk = min(64, cnt - k * 64);
        if (k + 1 < nchunks) {
            int nk2 = min(64, cnt - (k + 1) * 64);
            issue_chunk(Kg, Vg, Ks0 + (cur ^ 1) * KV_ELE, Vs0 + (cur ^ 1) * KV_ELE,
                        s0 + (k + 1) * 64, nk2, t);
            CP_COMMIT();
            CP_WAIT1();
        } else {
            CP_WAIT0();
        }
        __syncthreads();
        {
            uint32_t kbase1 = aK1 + cur * (KV_ELE * 2);
            uint32_t kbase2 = aK2 + cur * (KV_ELE * 2);
            float sa[4][4];
            #pragma unroll
            for (int j = 0; j < 4; j++)
                #pragma unroll
                for (int q = 0; q < 4; q++) sa[j][q] = 0.0f;
            #pragma unroll
            for (int ks = 0; ks < 8; ks++) {
                uint32_t kb1[4], kb2[4];
                LDSM4(kb1, kbase1 + ks * 32);
                LDSM4(kb2, kbase2 + ks * 32);
                MMA16816(sa[0], qa[ks], kb1[0], kb1[1]);
                MMA16816(sa[1], qa[ks], kb1[2], kb1[3]);
                MMA16816(sa[2], qa[ks], kb2[0], kb2[1]);
                MMA16816(sa[3], qa[ks], kb2[2], kb2[3]);
            }
            int r0 = pb + g, r1 = pb + g + 8;
            #pragma unroll
            for (int j = 0; j < 4; j++) {
                int c0 = th * 32 + j * 8 + tc * 2;
                *(float2*)&ss[r0 * 68 + c0] = make_float2(sa[j][0], sa[j][1]);
                *(float2*)&ss[r1 * 68 + c0] = make_float2(sa[j][2], sa[j][3]);
            }
        }
        __syncthreads();
        {
            int p = t >> 2, sub = t & 3;
            int k0 = sub * 16;
            float mo = m_s[p];
            float cm = -1e30f;
            #pragma unroll 4
            for (int kk = k0; kk < k0 + 16; kk++) {
                float v = (kk < nk) ? ss[p * 68 + kk] : -1e30f;
                cm = fmaxf(cm, v);
            }
            cm = fmaxf(cm, __shfl_xor_sync(0xffffffffu, cm, 1));
            cm = fmaxf(cm, __shfl_xor_sync(0xffffffffu, cm, 2));
            cm = fmaxf(cm, mo);
            float sum = 0.0f;
            #pragma unroll 4
            for (int kk = k0; kk < k0 + 16; kk++) {
                float e = (kk < nk) ? __expf(ss[p * 68 + kk] - cm) : 0.0f;
                Ps[p * 72 + kk] = __float2bfloat16(e);
                sum += e;
            }
            sum += __shfl_xor_sync(0xffffffffu, sum, 1);
            sum += __shfl_xor_sync(0xffffffffu, sum, 2);
            if (sub == 0) {
                float scl = __expf(mo - cm);
                l_s[p] = l_s[p] * scl + sum;
                m_s[p] = cm;
                sc_s[p] = scl;
            }
        }
        __syncthreads();
        {
            uint32_t vbase = aV + cur * (KV_ELE * 2);
            float sc0 = sc_s[pb + g], sc1 = sc_s[pb + g + 8];
            #pragma unroll
            for (int nt = 0; nt < 8; nt++) {
                cx[nt][0] *= sc0; cx[nt][1] *= sc0;
                cx[nt][2] *= sc1; cx[nt][3] *= sc1;
            }
            #pragma unroll
            for (int ks = 0; ks < 4; ks++) {
                uint32_t pa[4];
                LDSM4(pa, aP + ks * 32);
                #pragma unroll
                for (int ntp = 0; ntp < 4; ntp++) {
                    uint32_t vb[4];
                    LDSM4T(vb, vbase + ks * 4352 + ntp * 32);
                    MMA16816(cx[ntp * 2 + 0], pa, vb[0], vb[1]);
                    MMA16816(cx[ntp * 2 + 1], pa, vb[2], vb[3]);
                }
            }
        }
        __syncthreads();
    }
    int r0 = pb + g, r1 = pb + g + 8;
    float l0 = l_s[r0], l1 = l_s[r1];
    float i0 = (l0 > 0.0f) ? 1.0f / l0 : 0.0f;
    float i1 = (l1 > 0.0f) ? 1.0f / l1 : 0.0f;
    __nv_bfloat16* cbp = g_ctxh + (size_t)b * 16384;
    int base0 = (r0 >> 2) * 1024 + mod * 512 + (r0 & 3) * 128;
    int base1 = (r1 >> 2) * 1024 + mod * 512 + (r1 & 3) * 128;
    #pragma unroll
    for (int nt = 0; nt < 8; nt++) {
        int d0 = th * 64 + nt * 8 + tc * 2;
        *(uint32_t*)(cbp + base0 + d0) = f2bf2(cx[nt][0] * i0, cx[nt][1] * i0);
        *(uint32_t*)(cbp + base1 + d0) = f2bf2(cx[nt][2] * i1, cx[nt][3] * i1);
    }
}

// ---------------- fused VO + LN2 + FFN, 2 batches/block (B-frag reuse) ----------------
// dsm: ctxs[2][16][1032] bf16 = 66048B; overlays: nlf[2] 16384B @0, nlh[2] @16384 (8704B),
// hidh[2] @25088 (16896B). latv[2] @66048 (16384B).
#define PF_BYTES (66048 + 16384)

__global__ void __launch_bounds__(256) projffn_kernel(int layer,
    const float* __restrict__ lng, const float* __restrict__ lnb,
    const float* __restrict__ b1, const float* __restrict__ b2) {
    extern __shared__ char dsm[];
    __nv_bfloat16* ctxs = (__nv_bfloat16*)dsm;                 // +bb*16512 halves
    float* nlf  = (float*)dsm;                                 // +bb*2048 floats
    __nv_bfloat16* nlh  = (__nv_bfloat16*)(dsm + 16384);       // +bb*(16*136)
    __nv_bfloat16* hidh = (__nv_bfloat16*)(dsm + 25088);       // +bb*(16*264)
    float* latv = (float*)(dsm + 66048);                       // +bb*2048 floats
    int blk = blockIdx.x, t = threadIdx.x;
    int b0 = blk * 2;
    int w = t >> 5, lane = t & 31, g = lane >> 2, tc = lane & 3;

    #pragma unroll
    for (int bb = 0; bb < 2; bb++) {
        const uint4* src = (const uint4*)(g_ctxh + (size_t)(b0 + bb) * 16384);
        for (int i = t; i < 2048; i += 256) {
            int r = i >> 7, c8 = i & 127;
            *(uint4*)(ctxs + bb * 16512 + r * 1032 + c8 * 8) = src[i];
        }
        const float4* lsrc = (const float4*)(g_lat + (size_t)(b0 + bb) * NLAT * DD);
        for (int i = t; i < 512; i += 256) ((float4*)(latv + bb * 2048))[i] = lsrc[i];
    }
    __syncthreads();
    // VO GEMM: B-frag loaded once per kstep, used for both batches
    {
        const uint32_t* BvP = g_BvoP + (size_t)layer * 65536;
        const float* cvo0 = g_cvo + (layer * 2 + 0) * 128;
        const float* cvo1 = g_cvo + (layer * 2 + 1) * 128;
        uint32_t aC = s2u(ctxs + (lane & 15) * 1032 + (lane >> 4) * 8);
        float acc[2][2][4];
        #pragma unroll
        for (int bb = 0; bb < 2; bb++)
            #pragma unroll
            for (int i = 0; i < 2; i++)
                #pragma unroll
                for (int j = 0; j < 4; j++) acc[bb][i][j] = 0.0f;
        #pragma unroll 2
        for (int ks = 0; ks < 64; ks++) {
            uint2 bf[2];
            #pragma unroll
            for (int nt = 0; nt < 2; nt++)
                bf[nt] = *(const uint2*)(BvP + (size_t)((w * 2 + nt) * 64 + ks) * 64 + lane * 2);
            #pragma unroll
            for (int bb = 0; bb < 2; bb++) {
                uint32_t aA[4];
                LDSM4(aA, aC + bb * 33024 + ks * 32);
                MMA16816(acc[bb][0], aA, bf[0].x, bf[0].y);
                MMA16816(acc[bb][1], aA, bf[1].x, bf[1].y);
            }
        }
        __syncthreads();   // ctxs reads done before nlf overlay
        #pragma unroll
        for (int bb = 0; bb < 2; bb++) {
            float* lv = latv + bb * 2048;
            #pragma unroll
            for (int nt = 0; nt < 2; nt++) {
                int n0 = w * 16 + nt * 8 + tc * 2;
                float c0v = cvo0[n0] + cvo1[n0];
                float c1v = cvo0[n0 + 1] + cvo1[n0 + 1];
                lv[g * 128 + n0]           += acc[bb][nt][0] + c0v;
                lv[g * 128 + n0 + 1]       += acc[bb][nt][1] + c1v;
                lv[(g + 8) * 128 + n0]     += acc[bb][nt][2] + c0v;
                lv[(g + 8) * 128 + n0 + 1] += acc[bb][nt][3] + c1v;
            }
        }
    }
    __syncthreads();
    layernorm_rows(latv, lng, lnb, (float(*)[DD])nlf, t, 256);
    layernorm_rows(latv + 2048, lng, lnb, (float(*)[DD])(nlf + 2048), t, 256);
    __syncthreads();
    for (int i = t; i < NLAT * DD; i += 256) {
        int r = i >> 6, c = (i & 63) * 2;   // r: 0..31 covers both batches
        int bb = r >> 4, rr = r & 15;
        *(uint32_t*)(nlh + bb * 2176 + rr * 136 + c) =
            f2bf2(nlf[bb * 2048 + rr * DD + c], nlf[bb * 2048 + rr * DD + c + 1]);
    }
    __syncthreads();
    // FFN1 (TC)
    {
        const uint32_t* W1P = g_w1P + (size_t)layer * 16384;
        uint32_t aN = s2u(nlh + (lane & 15) * 136 + (lane >> 4) * 8);
        float f1a[2][4][4];
        #pragma unroll
        for (int bb = 0; bb < 2; bb++)
            #pragma unroll
            for (int i = 0; i < 4; i++)
                #pragma unroll
                for (int j = 0; j < 4; j++) f1a[bb][i][j] = 0.0f;
        #pragma unroll
        for (int ks = 0; ks < 8; ks++) {
            uint2 bf[4];
            #pragma unroll
            for (int nt = 0; nt < 4; nt++)
                bf[nt] = *(const uint2*)(W1P + (size_t)((w * 4 + nt) * 8 + ks) * 64 + lane * 2);
            #pragma unroll
            for (int bb = 0; bb < 2; bb++) {
                uint32_t aA[4];
                LDSM4(aA, aN + bb * 4352 + ks * 32);
                #pragma unroll
                for (int nt = 0; nt < 4; nt++) MMA16816(f1a[bb][nt], aA, bf[nt].x, bf[nt].y);
            }
        }
        #pragma unroll
        for (int bb = 0; bb < 2; bb++) {
            __nv_bfloat16* hh = hidh + bb * 4224;
            #pragma unroll
            for (int nt = 0; nt < 4; nt++) {
                int n0 = (w * 4 + nt) * 8 + tc * 2;
                float b0v = b1[n0], b1v = b1[n0 + 1];
                *(uint32_t*)(hh + g * 264 + n0) =
                    f2bf2(fmaxf(f1a[bb][nt][0] + b0v, 0.0f), fmaxf(f1a[bb][nt][1] + b1v, 0.0f));
                *(uint32_t*)(hh + (g + 8) * 264 + n0) =
                    f2bf2(fmaxf(f1a[bb][nt][2] + b0v, 0.0f), fmaxf(f1a[bb][nt][3] + b1v, 0.0f));
            }
        }
    }
    __syncthreads();
    // FFN2 (TC) + residual -> g_lat
    {
        const uint32_t* W2P = g_w2P + (size_t)layer * 16384;
        uint32_t aH = s2u(hidh + (lane & 15) * 264 + (lane >> 4) * 8);
        float f2a[2][2][4];
        #pragma unroll
        for (int bb = 0; bb < 2; bb++)
            #pragma unroll
            for (int i = 0; i < 2; i++)
                #pragma unroll
                for (int j = 0; j < 4; j++) f2a[bb][i][j] = 0.0f;
        #pragma unroll 4
        for (int ks = 0; ks < 16; ks++) {
            uint2 bf[2];
            #pragma unroll
            for (int nt = 0; nt < 2; nt++)
                bf[nt] = *(const uint2*)(W2P + (size_t)((w * 2 + nt) * 16 + ks) * 64 + lane * 2);
            #pragma unroll
            for (int bb = 0; bb < 2; bb++) {
                uint32_t aA[4];
                LDSM4(aA, aH + bb * 8448 + ks * 32);
                MMA16816(f2a[bb][0], aA, bf[0].x, bf[0].y);
                MMA16816(f2a[bb][1], aA, bf[1].x, bf[1].y);
            }
        }
        #pragma unroll
        for (int bb = 0; bb < 2; bb++) {
            float* latb = g_lat + (size_t)(b0 + bb) * NLAT * DD;
            const float* lv = latv + bb * 2048;
            #pragma unroll
            for (int nt = 0; nt < 2; nt++) {
                int n0 = (w * 2 + nt) * 8 + tc * 2;
                float b0v = b2[n0], b1v = b2[n0 + 1];
                latb[g * 128 + n0]           = lv[g * 128 + n0] + f2a[bb][nt][0] + b0v;
                latb[g * 128 + n0 + 1]       = lv[g * 128 + n0 + 1] + f2a[bb][nt][1] + b1v;
                latb[(g + 8) * 128 + n0]     = lv[(g + 8) * 128 + n0] + f2a[bb][nt][2] + b0v;
                latb[(g + 8) * 128 + n0 + 1] = lv[(g + 8) * 128 + n0 + 1] + f2a[bb][nt][3] + b1v;
            }
        }
    }
}

// ---------------- head: grid 128, 4 batches/block ----------------
__global__ void __launch_bounds__(256) head_kernel(
    const float* __restrict__ w1, const float* __restrict__ b1,
    const float* __restrict__ w2, const float* __restrict__ b2,
    float* __restrict__ out) {
    __shared__ float flat_s[4][2048];
    __shared__ float hs[4][128];
    int blk = blockIdx.x, t = threadIdx.x;
    int b0 = blk * 4;
    const float4* src = (const float4*)(g_lat + (size_t)b0 * NLAT * DD);
    for (int i = t; i < 2048; i += 256) ((float4*)flat_s)[i] = src[i];
    __syncthreads();
    int tt = t & 127, bh = t >> 7;
    float acc0 = b1[tt], acc1 = acc0;
    const float4* w1r = (const float4*)(w1 + (size_t)tt * NLAT * DD);
    const float4* f0 = (const float4*)flat_s[bh * 2];
    const float4* f1 = (const float4*)flat_s[bh * 2 + 1];
    #pragma unroll 8
    for (int u4 = 0; u4 < 512; u4++) {
        float4 w4 = w1r[u4];
        float4 a4 = f0[u4];
        float4 c4 = f1[u4];
        acc0 = fmaf(w4.x, a4.x, fmaf(w4.y, a4.y, fmaf(w4.z, a4.z, fmaf(w4.w, a4.w, acc0))));
        acc1 = fmaf(w4.x, c4.x, fmaf(w4.y, c4.y, fmaf(w4.z, c4.z, fmaf(w4.w, c4.w, acc1))));
    }
    hs[bh * 2][tt] = fmaxf(acc0, 0.0f);
    hs[bh * 2 + 1][tt] = fmaxf(acc1, 0.0f);
    __syncthreads();
    int w = t >> 5, lane = t & 31;
    if (w < 4) {
        float s = 0.0f;
        #pragma unroll
        for (int q = 0; q < 4; q++) {
            int idx = q * 32 + lane;
            s += hs[w][idx] * w2[idx];
        }
        #pragma unroll
        for (int o = 16; o; o >>= 1) s += __shfl_xor_sync(0xffffffffu, s, o);
        if (lane == 0) {
            float x = s + b2[0];
            out[b0 + w] = (x > 20.0f) ? x : log1pf(__expf(x));
        }
    }
}

extern "C" void kernel_launch(void* const* d_in, const int* in_sizes, int n_in,
                              void* d_out, int out_size) {
    const float* drug_k   = (const float*)d_in[0];
    const float* drug_v   = (const float*)d_in[1];
    const float* enz_k    = (const float*)d_in[2];
    const float* enz_v    = (const float*)d_in[3];
    const int*   drug_b   = (const int*)d_in[4];
    const int*   enz_b    = (const int*)d_in[5];
    const float* latents  = (const float*)d_in[6];
    const float* wq_d     = (const float*)d_in[7];
    const float* bq_d     = (const float*)d_in[8];
    const float* wq_e     = (const float*)d_in[9];
    const float* bq_e     = (const float*)d_in[10];
    const float* mha_d_w  = (const float*)d_in[11];
    const float* mha_d_b  = (const float*)d_in[12];
    const float* mha_d_ow = (const float*)d_in[13];
    const float* mha_d_ob = (const float*)d_in[14];
    const float* mha_e_w  = (const float*)d_in[15];
    const float* mha_e_b  = (const float*)d_in[16];
    const float* mha_e_ow = (const float*)d_in[17];
    const float* mha_e_ob = (const float*)d_in[18];
    const float* ln1_g    = (const float*)d_in[19];
    const float* ln1_b    = (const float*)d_in[20];
    const float* ln2_g    = (const float*)d_in[21];
    const float* ln2_b    = (const float*)d_in[22];
    const float* ffn_w1   = (const float*)d_in[23];
    const float* ffn_b1   = (const float*)d_in[24];
    const float* ffn_w2   = (const float*)d_in[25];
    const float* ffn_b2   = (const float*)d_in[26];
    const float* head_w1  = (const float*)d_in[27];
    const float* head_b1  = (const float*)d_in[28];
    const float* head_w2  = (const float*)d_in[29];
    const float* head_b2  = (const float*)d_in[30];
    float* out = (float*)d_out;

    static int s_attr_set = 0;
    if (!s_attr_set) {
        cudaFuncSetAttribute(attn_kernel, cudaFuncAttributeMaxDynamicSharedMemorySize, ATT_BYTES);
        cudaFuncSetAttribute(projffn_kernel, cudaFuncAttributeMaxDynamicSharedMemorySize, PF_BYTES);
        s_attr_set = 1;
    }

    mega_setup_kernel<<<SETUP_GRID, 256>>>(
        drug_k, drug_v, enz_k, enz_v, drug_b, enz_b, latents,
        wq_d, bq_d, wq_e, bq_e,
        mha_d_w, mha_d_b, mha_d_ow, mha_d_ob,
        mha_e_w, mha_e_b, mha_e_ow, mha_e_ob,
        ffn_w1, ffn_w2);
    pc_Aq_kernel<<<dim3(32, 4), 256>>>(mha_d_w, mha_e_w);

    for (int l = 0; l < LAYERS; l++) {
        size_t oV = (size_t)l * DD;
        size_t oF1b = (size_t)l * 2 * DD;

        attn_kernel<<<1024, 256, ATT_BYTES>>>(l, ln1_g + oV, ln1_b + oV);
        projffn_kernel<<<BB / 2, 256, PF_BYTES>>>(l,
            ln2_g + oV, ln2_b + oV,
            ffn_b1 + oF1b, ffn_b2 + oV);
    }

    head_kernel<<<128, 256>>>(head_w1, head_b1, head_w2, head_b2, out);
}